// round 1
// baseline (speedup 1.0000x reference)
#include <cuda_runtime.h>
#include <math.h>

#define Bn  128
#define Tn  256
#define Cn  384
#define Hn  6
#define HDn 64
#define BT  (Bn * Tn)
#define FF  (4 * Cn)

// ---------------- scratch (device globals; allocation-free) ----------------
__device__ float g_x1  [(size_t)BT * Cn];        // LN1 / LN2 output
__device__ float g_q   [(size_t)Bn * Hn * Tn * HDn];
__device__ float g_k   [(size_t)Bn * Hn * Tn * HDn];
__device__ float g_v   [(size_t)Bn * Hn * Tn * HDn];
__device__ float g_attn[(size_t)BT * Cn];        // concat-head attention out
__device__ float g_hid [(size_t)BT * FF];        // FFN hidden

__device__ __forceinline__ float dot4(const float4 a, const float4 b) {
    return a.x * b.x + a.y * b.y + a.z * b.z + a.w * b.w;
}

// ---------------- LayerNorm: one warp per row (C = 384 = 96 float4) --------
__global__ __launch_bounds__(256)
void ln_kernel(const float* __restrict__ x, const float* __restrict__ g,
               const float* __restrict__ b, float* __restrict__ y)
{
    int row  = blockIdx.x * 8 + (threadIdx.x >> 5);
    int lane = threadIdx.x & 31;
    const float4* xr = (const float4*)(x + (size_t)row * Cn);
    float4 a0 = xr[lane], a1 = xr[lane + 32], a2 = xr[lane + 64];

    float s  = a0.x + a0.y + a0.z + a0.w
             + a1.x + a1.y + a1.z + a1.w
             + a2.x + a2.y + a2.z + a2.w;
    float sq = dot4(a0, a0) + dot4(a1, a1) + dot4(a2, a2);
    #pragma unroll
    for (int off = 16; off; off >>= 1) {
        s  += __shfl_xor_sync(0xffffffffu, s,  off);
        sq += __shfl_xor_sync(0xffffffffu, sq, off);
    }
    const float inv = 1.0f / (float)Cn;
    float mu  = s * inv;
    float var = sq * inv - mu * mu;
    float r   = rsqrtf(var + 1e-5f);

    const float4* g4 = (const float4*)g;
    const float4* b4 = (const float4*)b;
    float4* yr = (float4*)(y + (size_t)row * Cn);

    float4 gv, bv, o;
    gv = g4[lane];      bv = b4[lane];
    o.x = (a0.x - mu) * r * gv.x + bv.x;  o.y = (a0.y - mu) * r * gv.y + bv.y;
    o.z = (a0.z - mu) * r * gv.z + bv.z;  o.w = (a0.w - mu) * r * gv.w + bv.w;
    yr[lane] = o;
    gv = g4[lane + 32]; bv = b4[lane + 32];
    o.x = (a1.x - mu) * r * gv.x + bv.x;  o.y = (a1.y - mu) * r * gv.y + bv.y;
    o.z = (a1.z - mu) * r * gv.z + bv.z;  o.w = (a1.w - mu) * r * gv.w + bv.w;
    yr[lane + 32] = o;
    gv = g4[lane + 64]; bv = b4[lane + 64];
    o.x = (a2.x - mu) * r * gv.x + bv.x;  o.y = (a2.y - mu) * r * gv.y + bv.y;
    o.z = (a2.z - mu) * r * gv.z + bv.z;  o.w = (a2.w - mu) * r * gv.w + bv.w;
    yr[lane + 64] = o;
}

// ---------------- tiled SGEMM core: 64x64 block tile, BK=16, 256 thr -------
// A row-major [.,K] (lda=K), B row-major [K,N] (ldb=N), C row-major [.,N].
// Optional bias[N], residual (ld=N), relu.
__device__ __forceinline__
void sgemm_tile(const float* __restrict__ A, const float* __restrict__ B,
                float* __restrict__ Cp, const float* __restrict__ bias,
                const float* __restrict__ residual, int relu,
                int N, int K, int row0, int col0)
{
    __shared__ float As[16][64];   // stored transposed: As[k][m]
    __shared__ float Bs[16][64];   // Bs[k][n]

    const int tx = threadIdx.x & 15;        // 0..15  -> n direction
    const int ty = threadIdx.x >> 4;        // 0..15  -> m direction
    const int ar = threadIdx.x >> 2;        // 0..63  A tile row
    const int ac = (threadIdx.x & 3) * 4;   // A tile col (float4)
    const int br = threadIdx.x >> 4;        // 0..15  B tile row
    const int bc = (threadIdx.x & 15) * 4;  // B tile col (float4)

    float acc[4][4];
    #pragma unroll
    for (int i = 0; i < 4; i++)
        #pragma unroll
        for (int j = 0; j < 4; j++) acc[i][j] = 0.f;

    for (int k0 = 0; k0 < K; k0 += 16) {
        float4 a4 = *(const float4*)(A + (size_t)(row0 + ar) * K + k0 + ac);
        float4 b4 = *(const float4*)(B + (size_t)(k0 + br) * N + col0 + bc);
        As[ac + 0][ar] = a4.x;  As[ac + 1][ar] = a4.y;
        As[ac + 2][ar] = a4.z;  As[ac + 3][ar] = a4.w;
        *(float4*)&Bs[br][bc] = b4;
        __syncthreads();

        #pragma unroll
        for (int k = 0; k < 16; k++) {
            float4 av = *(const float4*)&As[k][ty * 4];
            float4 bv = *(const float4*)&Bs[k][tx * 4];
            acc[0][0] += av.x * bv.x; acc[0][1] += av.x * bv.y;
            acc[0][2] += av.x * bv.z; acc[0][3] += av.x * bv.w;
            acc[1][0] += av.y * bv.x; acc[1][1] += av.y * bv.y;
            acc[1][2] += av.y * bv.z; acc[1][3] += av.y * bv.w;
            acc[2][0] += av.z * bv.x; acc[2][1] += av.z * bv.y;
            acc[2][2] += av.z * bv.z; acc[2][3] += av.z * bv.w;
            acc[3][0] += av.w * bv.x; acc[3][1] += av.w * bv.y;
            acc[3][2] += av.w * bv.z; acc[3][3] += av.w * bv.w;
        }
        __syncthreads();
    }

    const int col = col0 + tx * 4;
    #pragma unroll
    for (int i = 0; i < 4; i++) {
        int row = row0 + ty * 4 + i;
        float4 r = make_float4(acc[i][0], acc[i][1], acc[i][2], acc[i][3]);
        if (bias) {
            float4 bb = *(const float4*)(bias + col);
            r.x += bb.x; r.y += bb.y; r.z += bb.z; r.w += bb.w;
        }
        if (residual) {
            float4 rr = *(const float4*)(residual + (size_t)row * N + col);
            r.x += rr.x; r.y += rr.y; r.z += rr.z; r.w += rr.w;
        }
        if (relu) {
            r.x = fmaxf(r.x, 0.f); r.y = fmaxf(r.y, 0.f);
            r.z = fmaxf(r.z, 0.f); r.w = fmaxf(r.w, 0.f);
        }
        *(float4*)(Cp + (size_t)row * N + col) = r;
    }
}

__global__ __launch_bounds__(256)
void gemm_kernel(const float* __restrict__ A, const float* __restrict__ B,
                 float* __restrict__ Cp, const float* __restrict__ bias,
                 const float* __restrict__ residual, int relu, int N, int K)
{
    sgemm_tile(A, B, Cp, bias, residual, relu, N, K,
               blockIdx.y * 64, blockIdx.x * 64);
}

// QKV: per-z (which in {q,k,v}, b, h) GEMM of x1[b] [T,C] @ W[h] [C,HD]
__global__ __launch_bounds__(256)
void qkv_kernel(const float* __restrict__ x1,
                const float* __restrict__ Wq, const float* __restrict__ Wk,
                const float* __restrict__ Wv,
                float* __restrict__ q, float* __restrict__ k, float* __restrict__ v)
{
    int z = blockIdx.z;
    int which = z / (Bn * Hn);
    int bh    = z % (Bn * Hn);
    int b = bh / Hn, h = bh % Hn;
    const float* W  = (which == 0 ? Wq : which == 1 ? Wk : Wv) + (size_t)h * Cn * HDn;
    float*       out = (which == 0 ? q  : which == 1 ? k  : v ) + (size_t)bh * Tn * HDn;
    sgemm_tile(x1 + (size_t)b * Tn * Cn, W, out, nullptr, nullptr, 0,
               HDn, Cn, blockIdx.y * 64, 0);
}

// ---------------- attention: one block per (b,h), one thread per query row -
// 2-pass causal softmax (pass A: row max, pass B: exp-sum + V accumulation).
__global__ __launch_bounds__(256)
void attn_kernel(const float* __restrict__ Q, const float* __restrict__ K,
                 const float* __restrict__ V, float* __restrict__ O)
{
    const int bh = blockIdx.x;
    const int b = bh / Hn, h = bh % Hn;
    const float* qb = Q + (size_t)bh * Tn * HDn;
    const float* kb = K + (size_t)bh * Tn * HDn;
    const float* vb = V + (size_t)bh * Tn * HDn;
    const int t = threadIdx.x;
    const float scale = 0.125f;  // 1/sqrt(64)

    float4 qr[16];
    {
        const float4* q4 = (const float4*)(qb + (size_t)t * HDn);
        #pragma unroll
        for (int i = 0; i < 16; i++) qr[i] = q4[i];
    }

    __shared__ float ks[64 * 64];
    __shared__ float vs[64 * 64];

    const int wmax = t | 31;  // max query index in this warp (uniform per warp)

    // ---- pass A: row max ----
    float m = -1e30f;
    for (int tile = 0; tile < 4; tile++) {
        const float4* src = (const float4*)(kb + (size_t)tile * 64 * HDn);
        #pragma unroll
        for (int j = 0; j < 4; j++)
            ((float4*)ks)[threadIdx.x + j * 256] = src[threadIdx.x + j * 256];
        __syncthreads();

        int lim = min(63, wmax - tile * 64);   // warp-uniform
        for (int s = 0; s <= lim; s++) {
            const float4* k4 = (const float4*)(ks + s * 64);
            float a0 = 0.f, a1 = 0.f;
            #pragma unroll
            for (int i = 0; i < 16; i += 2) {
                a0 += dot4(qr[i],     k4[i]);
                a1 += dot4(qr[i + 1], k4[i + 1]);
            }
            if (tile * 64 + s <= t) m = fmaxf(m, (a0 + a1) * scale);
        }
        __syncthreads();
    }

    // ---- pass B: exp-sum + weighted V ----
    float l = 0.f;
    float4 o[16];
    #pragma unroll
    for (int i = 0; i < 16; i++) o[i] = make_float4(0.f, 0.f, 0.f, 0.f);

    for (int tile = 0; tile < 4; tile++) {
        const float4* srck = (const float4*)(kb + (size_t)tile * 64 * HDn);
        const float4* srcv = (const float4*)(vb + (size_t)tile * 64 * HDn);
        #pragma unroll
        for (int j = 0; j < 4; j++) {
            ((float4*)ks)[threadIdx.x + j * 256] = srck[threadIdx.x + j * 256];
            ((float4*)vs)[threadIdx.x + j * 256] = srcv[threadIdx.x + j * 256];
        }
        __syncthreads();

        int lim = min(63, wmax - tile * 64);
        for (int s = 0; s <= lim; s++) {
            const float4* k4 = (const float4*)(ks + s * 64);
            float a0 = 0.f, a1 = 0.f;
            #pragma unroll
            for (int i = 0; i < 16; i += 2) {
                a0 += dot4(qr[i],     k4[i]);
                a1 += dot4(qr[i + 1], k4[i + 1]);
            }
            float p = 0.f;
            if (tile * 64 + s <= t) p = __expf((a0 + a1) * scale - m);
            l += p;
            const float4* v4 = (const float4*)(vs + s * 64);
            #pragma unroll
            for (int i = 0; i < 16; i++) {
                float4 vv = v4[i];
                o[i].x += p * vv.x; o[i].y += p * vv.y;
                o[i].z += p * vv.z; o[i].w += p * vv.w;
            }
        }
        __syncthreads();
    }

    float inv = 1.0f / l;
    float4* op = (float4*)(O + ((size_t)b * Tn + t) * Cn + h * HDn);
    #pragma unroll
    for (int i = 0; i < 16; i++) {
        float4 r = o[i];
        r.x *= inv; r.y *= inv; r.z *= inv; r.w *= inv;
        op[i] = r;
    }
}

// ---------------- launch ---------------------------------------------------
extern "C" void kernel_launch(void* const* d_in, const int* in_sizes, int n_in,
                              void* d_out, int out_size)
{
    const float* x     = (const float*)d_in[0];
    const float* ln1_g = (const float*)d_in[1];
    const float* ln1_b = (const float*)d_in[2];
    const float* Wq    = (const float*)d_in[3];
    const float* Wk    = (const float*)d_in[4];
    const float* Wv    = (const float*)d_in[5];
    const float* Wo    = (const float*)d_in[6];
    const float* bo    = (const float*)d_in[7];
    const float* ln2_g = (const float*)d_in[8];
    const float* ln2_b = (const float*)d_in[9];
    const float* W1    = (const float*)d_in[10];
    const float* b1    = (const float*)d_in[11];
    const float* W2    = (const float*)d_in[12];
    const float* b2    = (const float*)d_in[13];
    float* out = (float*)d_out;

    void *px1, *pq, *pk, *pv, *pattn, *phid;
    cudaGetSymbolAddress(&px1,  g_x1);
    cudaGetSymbolAddress(&pq,   g_q);
    cudaGetSymbolAddress(&pk,   g_k);
    cudaGetSymbolAddress(&pv,   g_v);
    cudaGetSymbolAddress(&pattn, g_attn);
    cudaGetSymbolAddress(&phid, g_hid);
    float* x1   = (float*)px1;
    float* q    = (float*)pq;
    float* k    = (float*)pk;
    float* v    = (float*)pv;
    float* attn = (float*)pattn;
    float* hid  = (float*)phid;

    // LN1
    ln_kernel<<<BT / 8, 256>>>(x, ln1_g, ln1_b, x1);
    // QKV projections
    qkv_kernel<<<dim3(1, Tn / 64, 3 * Bn * Hn), 256>>>(x1, Wq, Wk, Wv, q, k, v);
    // causal attention
    attn_kernel<<<Bn * Hn, 256>>>(q, k, v, attn);
    // output projection + bias + residual(x) -> d_out
    gemm_kernel<<<dim3(Cn / 64, BT / 64), 256>>>(attn, Wo, out, bo, x, 0, Cn, Cn);
    // LN2 (reads d_out)
    ln_kernel<<<BT / 8, 256>>>(out, ln2_g, ln2_b, x1);
    // FFN1: relu(x2 @ W1 + b1)
    gemm_kernel<<<dim3(FF / 64, BT / 64), 256>>>(x1, W1, hid, b1, nullptr, 1, FF, Cn);
    // FFN2: d_out += hid @ W2 + b2 (in-place residual, tile-local)
    gemm_kernel<<<dim3(Cn / 64, BT / 64), 256>>>(hid, W2, out, b2, out, 0, Cn, FF);
}

// round 2
// speedup vs baseline: 1.8902x; 1.8902x over previous
#include <cuda_runtime.h>
#include <cuda_bf16.h>
#include <math.h>
#include <stdint.h>

#define Bn  128
#define Tn  256
#define Cn  384
#define Hn  6
#define HDn 64
#define BT  (Bn * Tn)
#define FF  (4 * Cn)
#define QKVN (3 * Cn)   // 1152

// ---------------- scratch (device globals; allocation-free) ----------------
__device__ float g_x1  [(size_t)BT * Cn];          // LN1 / LN2 output
__device__ float g_qkv [(size_t)BT * QKVN];        // fused qkv output
__device__ float g_attn[(size_t)BT * Cn];          // concat-head attention out
__device__ float g_hid [(size_t)BT * FF];          // FFN hidden
__device__ float g_wqkv[(size_t)Cn * QKVN];        // packed QKV weights [C, 3*H*HD]

__device__ __forceinline__ float dot4(const float4 a, const float4 b) {
    return a.x * b.x + a.y * b.y + a.z * b.z + a.w * b.w;
}

// ---------------- LayerNorm: one warp per row (C = 384 = 96 float4) --------
__global__ __launch_bounds__(256)
void ln_kernel(const float* __restrict__ x, const float* __restrict__ g,
               const float* __restrict__ b, float* __restrict__ y)
{
    int row  = blockIdx.x * 8 + (threadIdx.x >> 5);
    int lane = threadIdx.x & 31;
    const float4* xr = (const float4*)(x + (size_t)row * Cn);
    float4 a0 = xr[lane], a1 = xr[lane + 32], a2 = xr[lane + 64];

    float s  = a0.x + a0.y + a0.z + a0.w
             + a1.x + a1.y + a1.z + a1.w
             + a2.x + a2.y + a2.z + a2.w;
    float sq = dot4(a0, a0) + dot4(a1, a1) + dot4(a2, a2);
    #pragma unroll
    for (int off = 16; off; off >>= 1) {
        s  += __shfl_xor_sync(0xffffffffu, s,  off);
        sq += __shfl_xor_sync(0xffffffffu, sq, off);
    }
    const float inv = 1.0f / (float)Cn;
    float mu  = s * inv;
    float var = sq * inv - mu * mu;
    float r   = rsqrtf(var + 1e-5f);

    const float4* g4 = (const float4*)g;
    const float4* b4 = (const float4*)b;
    float4* yr = (float4*)(y + (size_t)row * Cn);

    float4 gv, bv, o;
    gv = g4[lane];      bv = b4[lane];
    o.x = (a0.x - mu) * r * gv.x + bv.x;  o.y = (a0.y - mu) * r * gv.y + bv.y;
    o.z = (a0.z - mu) * r * gv.z + bv.z;  o.w = (a0.w - mu) * r * gv.w + bv.w;
    yr[lane] = o;
    gv = g4[lane + 32]; bv = b4[lane + 32];
    o.x = (a1.x - mu) * r * gv.x + bv.x;  o.y = (a1.y - mu) * r * gv.y + bv.y;
    o.z = (a1.z - mu) * r * gv.z + bv.z;  o.w = (a1.w - mu) * r * gv.w + bv.w;
    yr[lane + 32] = o;
    gv = g4[lane + 64]; bv = b4[lane + 64];
    o.x = (a2.x - mu) * r * gv.x + bv.x;  o.y = (a2.y - mu) * r * gv.y + bv.y;
    o.z = (a2.z - mu) * r * gv.z + bv.z;  o.w = (a2.w - mu) * r * gv.w + bv.w;
    yr[lane + 64] = o;
}

// ---------------- pack QKV weights: [3][H][C][HD] -> [C][3*H*HD] -----------
__global__ __launch_bounds__(256)
void pack_qkv(const float* __restrict__ Wq, const float* __restrict__ Wk,
              const float* __restrict__ Wv, float* __restrict__ Wc)
{
    int idx = blockIdx.x * 256 + threadIdx.x;
    if (idx >= Cn * QKVN) return;
    int c = idx / QKVN, j = idx % QKVN;
    int which = j / Cn;          // 0=q, 1=k, 2=v  (Cn == H*HD)
    int r = j % Cn;
    int h = r / HDn, d = r % HDn;
    const float* W = (which == 0) ? Wq : (which == 1) ? Wk : Wv;
    Wc[idx] = W[((size_t)h * Cn + c) * HDn + d];
}

// ---------------- bf16 split helpers ---------------------------------------
__device__ __forceinline__ void bf16_split(float x, __nv_bfloat16& h, __nv_bfloat16& l)
{
    h = __float2bfloat16(x);
    l = __float2bfloat16(x - __bfloat162float(h));
}

__device__ __forceinline__ void ldm_x4(uint32_t r[4], const __nv_bfloat16* p)
{
    uint32_t addr = (uint32_t)__cvta_generic_to_shared(p);
    asm volatile("ldmatrix.sync.aligned.m8n8.x4.shared.b16 {%0,%1,%2,%3}, [%4];\n"
                 : "=r"(r[0]), "=r"(r[1]), "=r"(r[2]), "=r"(r[3]) : "r"(addr));
}

__device__ __forceinline__ void ldm_x4_trans(uint32_t r[4], const __nv_bfloat16* p)
{
    uint32_t addr = (uint32_t)__cvta_generic_to_shared(p);
    asm volatile("ldmatrix.sync.aligned.m8n8.x4.trans.shared.b16 {%0,%1,%2,%3}, [%4];\n"
                 : "=r"(r[0]), "=r"(r[1]), "=r"(r[2]), "=r"(r[3]) : "r"(addr));
}

__device__ __forceinline__ void mma16816(float d[4], const uint32_t a[4], const uint32_t b[2])
{
    asm volatile(
        "mma.sync.aligned.m16n8k16.row.col.f32.bf16.bf16.f32 "
        "{%0,%1,%2,%3}, {%4,%5,%6,%7}, {%8,%9}, {%0,%1,%2,%3};\n"
        : "+f"(d[0]), "+f"(d[1]), "+f"(d[2]), "+f"(d[3])
        : "r"(a[0]), "r"(a[1]), "r"(a[2]), "r"(a[3]), "r"(b[0]), "r"(b[1]));
}

// ---------------- tensor-core GEMM: block 128x64, BK=32, 3xBF16 split ------
// A row-major [M,K], B row-major [K,N], C row-major [M,N].
// 8 warps: 4 (M) x 2 (N); warp tile 32x32 (2 m16-frags x 4 n8-frags).
#define PA 72    // A smem pitch (bf16 elems): hi cols [0,32), lo [32,64), pad
#define PB 136   // B smem pitch: hi cols [0,64), lo [64,128), pad

__global__ __launch_bounds__(256, 2)
void mma_gemm(const float* __restrict__ A, const float* __restrict__ B,
              float* __restrict__ Cp, const float* __restrict__ bias,
              const float* __restrict__ residual, int relu, int N, int K)
{
    __shared__ __nv_bfloat16 As[128 * PA];
    __shared__ __nv_bfloat16 Bs[32 * PB];

    const int tid  = threadIdx.x;
    const int lane = tid & 31;
    const int warp = tid >> 5;
    const int wm = warp & 3;      // 0..3  M
    const int wn = warp >> 2;     // 0..1  N
    const int row0 = blockIdx.y * 128;
    const int col0 = blockIdx.x * 64;

    float acc[2][4][4];
    #pragma unroll
    for (int i = 0; i < 2; i++)
        #pragma unroll
        for (int j = 0; j < 4; j++)
            #pragma unroll
            for (int q = 0; q < 4; q++) acc[i][j][q] = 0.f;

    // gmem prefetch registers
    const int arow = tid >> 3;            // 0..31, +p*32 (4 passes)
    const int acol = (tid & 7) * 4;       // 0..28
    const int brow = tid >> 4;            // 0..15, +p*16 (2 passes)
    const int bcol = (tid & 15) * 4;      // 0..60
    float4 pa[4], pb[2];

    const int nk = K / 32;

    // ---- load chunk 0 ----
    #pragma unroll
    for (int p = 0; p < 4; p++)
        pa[p] = *(const float4*)(A + (size_t)(row0 + arow + p * 32) * K + acol);
    #pragma unroll
    for (int p = 0; p < 2; p++)
        pb[p] = *(const float4*)(B + (size_t)(brow + p * 16) * N + col0 + bcol);

    // ---- store chunk 0 to smem ----
    #pragma unroll
    for (int p = 0; p < 4; p++) {
        int r = arow + p * 32;
        __nv_bfloat16 h0,l0,h1,l1,h2,l2,h3,l3;
        bf16_split(pa[p].x, h0, l0); bf16_split(pa[p].y, h1, l1);
        bf16_split(pa[p].z, h2, l2); bf16_split(pa[p].w, h3, l3);
        __nv_bfloat16* d = &As[r * PA + acol];
        d[0]=h0; d[1]=h1; d[2]=h2; d[3]=h3;
        d[32]=l0; d[33]=l1; d[34]=l2; d[35]=l3;
    }
    #pragma unroll
    for (int p = 0; p < 2; p++) {
        int r = brow + p * 16;
        __nv_bfloat16 h0,l0,h1,l1,h2,l2,h3,l3;
        bf16_split(pb[p].x, h0, l0); bf16_split(pb[p].y, h1, l1);
        bf16_split(pb[p].z, h2, l2); bf16_split(pb[p].w, h3, l3);
        __nv_bfloat16* d = &Bs[r * PB + bcol];
        d[0]=h0; d[1]=h1; d[2]=h2; d[3]=h3;
        d[64]=l0; d[65]=l1; d[66]=l2; d[67]=l3;
    }
    __syncthreads();

    for (int kc = 0; kc < nk; kc++) {
        // prefetch next chunk into regs
        if (kc + 1 < nk) {
            int k0 = (kc + 1) * 32;
            #pragma unroll
            for (int p = 0; p < 4; p++)
                pa[p] = *(const float4*)(A + (size_t)(row0 + arow + p * 32) * K + k0 + acol);
            #pragma unroll
            for (int p = 0; p < 2; p++)
                pb[p] = *(const float4*)(B + (size_t)(k0 + brow + p * 16) * N + col0 + bcol);
        }

        // ---- MMA over current smem chunk ----
        #pragma unroll
        for (int ks = 0; ks < 2; ks++) {
            const int k0 = ks * 16;
            uint32_t ah[2][4], al[2][4], bh[2][4], bl[2][4];
            #pragma unroll
            for (int i = 0; i < 2; i++) {
                const __nv_bfloat16* pbase =
                    &As[(wm * 32 + i * 16 + (lane & 15)) * PA + k0 + 8 * (lane >> 4)];
                ldm_x4(ah[i], pbase);
                ldm_x4(al[i], pbase + 32);
            }
            #pragma unroll
            for (int j2 = 0; j2 < 2; j2++) {
                const __nv_bfloat16* pbase =
                    &Bs[(k0 + (lane & 15)) * PB + wn * 32 + j2 * 16 + 8 * (lane >> 4)];
                ldm_x4_trans(bh[j2], pbase);
                ldm_x4_trans(bl[j2], pbase + 64);
            }
            #pragma unroll
            for (int i = 0; i < 2; i++)
                #pragma unroll
                for (int j = 0; j < 4; j++) {
                    const uint32_t* bhp = &bh[j >> 1][(j & 1) * 2];
                    const uint32_t* blp = &bl[j >> 1][(j & 1) * 2];
                    mma16816(acc[i][j], ah[i], bhp);
                    mma16816(acc[i][j], al[i], bhp);
                    mma16816(acc[i][j], ah[i], blp);
                }
        }
        __syncthreads();

        // store prefetched chunk to smem
        if (kc + 1 < nk) {
            #pragma unroll
            for (int p = 0; p < 4; p++) {
                int r = arow + p * 32;
                __nv_bfloat16 h0,l0,h1,l1,h2,l2,h3,l3;
                bf16_split(pa[p].x, h0, l0); bf16_split(pa[p].y, h1, l1);
                bf16_split(pa[p].z, h2, l2); bf16_split(pa[p].w, h3, l3);
                __nv_bfloat16* d = &As[r * PA + acol];
                d[0]=h0; d[1]=h1; d[2]=h2; d[3]=h3;
                d[32]=l0; d[33]=l1; d[34]=l2; d[35]=l3;
            }
            #pragma unroll
            for (int p = 0; p < 2; p++) {
                int r = brow + p * 16;
                __nv_bfloat16 h0,l0,h1,l1,h2,l2,h3,l3;
                bf16_split(pb[p].x, h0, l0); bf16_split(pb[p].y, h1, l1);
                bf16_split(pb[p].z, h2, l2); bf16_split(pb[p].w, h3, l3);
                __nv_bfloat16* d = &Bs[r * PB + bcol];
                d[0]=h0; d[1]=h1; d[2]=h2; d[3]=h3;
                d[64]=l0; d[65]=l1; d[66]=l2; d[67]=l3;
            }
            __syncthreads();
        }
    }

    // ---- epilogue ----
    #pragma unroll
    for (int i = 0; i < 2; i++) {
        #pragma unroll
        for (int j = 0; j < 4; j++) {
            int rb = row0 + wm * 32 + i * 16 + (lane >> 2);
            int c  = col0 + wn * 32 + j * 8 + (lane & 3) * 2;
            #pragma unroll
            for (int hh = 0; hh < 2; hh++) {
                int r = rb + 8 * hh;
                float2 v = make_float2(acc[i][j][2 * hh], acc[i][j][2 * hh + 1]);
                if (bias) {
                    float2 bb = *(const float2*)(bias + c);
                    v.x += bb.x; v.y += bb.y;
                }
                if (residual) {
                    float2 rr = *(const float2*)(residual + (size_t)r * N + c);
                    v.x += rr.x; v.y += rr.y;
                }
                if (relu) { v.x = fmaxf(v.x, 0.f); v.y = fmaxf(v.y, 0.f); }
                *(float2*)(Cp + (size_t)r * N + c) = v;
            }
        }
    }
}

// ---------------- attention: one block per (b,h), one thread per query row -
// reads fused qkv buffer [BT, 1152]: q at col h*64, k at 384+h*64, v at 768+h*64
__global__ __launch_bounds__(256)
void attn_kernel(const float* __restrict__ QKV, float* __restrict__ O)
{
    const int bh = blockIdx.x;
    const int b = bh / Hn, h = bh % Hn;
    const float* base = QKV + (size_t)b * Tn * QKVN;
    const int t = threadIdx.x;
    const float scale = 0.125f;  // 1/sqrt(64)

    float4 qr[16];
    {
        const float4* q4 = (const float4*)(base + (size_t)t * QKVN + h * HDn);
        #pragma unroll
        for (int i = 0; i < 16; i++) qr[i] = q4[i];
    }

    __shared__ float ks[64 * 64];
    __shared__ float vs[64 * 64];

    const int wmax = t | 31;  // max query index in this warp (uniform per warp)

    // ---- pass A: row max ----
    float m = -1e30f;
    for (int tile = 0; tile < 4; tile++) {
        #pragma unroll
        for (int j = 0; j < 4; j++) {
            int f = threadIdx.x + j * 256;   // 0..1023
            int row = f >> 4, cf = f & 15;
            ((float4*)ks)[f] = ((const float4*)(base +
                (size_t)(tile * 64 + row) * QKVN + Cn + h * HDn))[cf];
        }
        __syncthreads();

        int lim = min(63, wmax - tile * 64);   // warp-uniform
        for (int s = 0; s <= lim; s++) {
            const float4* k4 = (const float4*)(ks + s * 64);
            float a0 = 0.f, a1 = 0.f;
            #pragma unroll
            for (int i = 0; i < 16; i += 2) {
                a0 += dot4(qr[i],     k4[i]);
                a1 += dot4(qr[i + 1], k4[i + 1]);
            }
            if (tile * 64 + s <= t) m = fmaxf(m, (a0 + a1) * scale);
        }
        __syncthreads();
    }

    // ---- pass B: exp-sum + weighted V ----
    float l = 0.f;
    float4 o[16];
    #pragma unroll
    for (int i = 0; i < 16; i++) o[i] = make_float4(0.f, 0.f, 0.f, 0.f);

    for (int tile = 0; tile < 4; tile++) {
        #pragma unroll
        for (int j = 0; j < 4; j++) {
            int f = threadIdx.x + j * 256;
            int row = f >> 4, cf = f & 15;
            ((float4*)ks)[f] = ((const float4*)(base +
                (size_t)(tile * 64 + row) * QKVN + Cn + h * HDn))[cf];
            ((float4*)vs)[f] = ((const float4*)(base +
                (size_t)(tile * 64 + row) * QKVN + 2 * Cn + h * HDn))[cf];
        }
        __syncthreads();

        int lim = min(63, wmax - tile * 64);
        for (int s = 0; s <= lim; s++) {
            const float4* k4 = (const float4*)(ks + s * 64);
            float a0 = 0.f, a1 = 0.f;
            #pragma unroll
            for (int i = 0; i < 16; i += 2) {
                a0 += dot4(qr[i],     k4[i]);
                a1 += dot4(qr[i + 1], k4[i + 1]);
            }
            float p = 0.f;
            if (tile * 64 + s <= t) p = __expf((a0 + a1) * scale - m);
            l += p;
            const float4* v4 = (const float4*)(vs + s * 64);
            #pragma unroll
            for (int i = 0; i < 16; i++) {
                float4 vv = v4[i];
                o[i].x += p * vv.x; o[i].y += p * vv.y;
                o[i].z += p * vv.z; o[i].w += p * vv.w;
            }
        }
        __syncthreads();
    }

    float inv = 1.0f / l;
    float4* op = (float4*)(O + ((size_t)b * Tn + t) * Cn + h * HDn);
    #pragma unroll
    for (int i = 0; i < 16; i++) {
        float4 r = o[i];
        r.x *= inv; r.y *= inv; r.z *= inv; r.w *= inv;
        op[i] = r;
    }
}

// ---------------- launch ---------------------------------------------------
extern "C" void kernel_launch(void* const* d_in, const int* in_sizes, int n_in,
                              void* d_out, int out_size)
{
    const float* x     = (const float*)d_in[0];
    const float* ln1_g = (const float*)d_in[1];
    const float* ln1_b = (const float*)d_in[2];
    const float* Wq    = (const float*)d_in[3];
    const float* Wk    = (const float*)d_in[4];
    const float* Wv    = (const float*)d_in[5];
    const float* Wo    = (const float*)d_in[6];
    const float* bo    = (const float*)d_in[7];
    const float* ln2_g = (const float*)d_in[8];
    const float* ln2_b = (const float*)d_in[9];
    const float* W1    = (const float*)d_in[10];
    const float* b1    = (const float*)d_in[11];
    const float* W2    = (const float*)d_in[12];
    const float* b2    = (const float*)d_in[13];
    float* out = (float*)d_out;

    void *px1, *pqkv, *pattn, *phid, *pwqkv;
    cudaGetSymbolAddress(&px1,   g_x1);
    cudaGetSymbolAddress(&pqkv,  g_qkv);
    cudaGetSymbolAddress(&pattn, g_attn);
    cudaGetSymbolAddress(&phid,  g_hid);
    cudaGetSymbolAddress(&pwqkv, g_wqkv);
    float* x1   = (float*)px1;
    float* qkv  = (float*)pqkv;
    float* attn = (float*)pattn;
    float* hid  = (float*)phid;
    float* wqkv = (float*)pwqkv;

    // LN1
    ln_kernel<<<BT / 8, 256>>>(x, ln1_g, ln1_b, x1);
    // pack QKV weights into [C, 1152]
    pack_qkv<<<(Cn * QKVN + 255) / 256, 256>>>(Wq, Wk, Wv, wqkv);
    // fused QKV projection: [BT,384] x [384,1152]
    mma_gemm<<<dim3(QKVN / 64, BT / 128), 256>>>(x1, wqkv, qkv, nullptr, nullptr, 0, QKVN, Cn);
    // causal attention
    attn_kernel<<<Bn * Hn, 256>>>(qkv, attn);
    // output projection + bias + residual(x) -> d_out
    mma_gemm<<<dim3(Cn / 64, BT / 128), 256>>>(attn, Wo, out, bo, x, 0, Cn, Cn);
    // LN2 (reads d_out)
    ln_kernel<<<BT / 8, 256>>>(out, ln2_g, ln2_b, x1);
    // FFN1: relu(x2 @ W1 + b1)
    mma_gemm<<<dim3(FF / 64, BT / 128), 256>>>(x1, W1, hid, b1, nullptr, 1, FF, Cn);
    // FFN2: d_out += hid @ W2 + b2 (in-place residual, tile-local)
    mma_gemm<<<dim3(Cn / 64, BT / 128), 256>>>(hid, W2, out, b2, out, 0, Cn, FF);
}

// round 3
// speedup vs baseline: 2.5609x; 1.3548x over previous
#include <cuda_runtime.h>
#include <cuda_bf16.h>
#include <math.h>
#include <stdint.h>

#define Bn  128
#define Tn  256
#define Cn  384
#define Hn  6
#define HDn 64
#define BT  (Bn * Tn)
#define FF  (4 * Cn)
#define QKVN (3 * Cn)   // 1152

// ---------------- scratch (device globals; allocation-free) ----------------
__device__ float g_x1  [(size_t)BT * Cn];          // LN1 / LN2 output
__device__ float g_qkv [(size_t)BT * QKVN];        // fused qkv output
__device__ float g_attn[(size_t)BT * Cn];          // concat-head attention out
__device__ float g_hid [(size_t)BT * FF];          // FFN hidden
__device__ float g_wqkv[(size_t)Cn * QKVN];        // packed QKV weights [C, 3*H*HD]

__device__ __forceinline__ float dot4(const float4 a, const float4 b) {
    return a.x * b.x + a.y * b.y + a.z * b.z + a.w * b.w;
}

// ---------------- LayerNorm: one warp per row (C = 384 = 96 float4) --------
__global__ __launch_bounds__(256)
void ln_kernel(const float* __restrict__ x, const float* __restrict__ g,
               const float* __restrict__ b, float* __restrict__ y)
{
    int row  = blockIdx.x * 8 + (threadIdx.x >> 5);
    int lane = threadIdx.x & 31;
    const float4* xr = (const float4*)(x + (size_t)row * Cn);
    float4 a0 = xr[lane], a1 = xr[lane + 32], a2 = xr[lane + 64];

    float s  = a0.x + a0.y + a0.z + a0.w
             + a1.x + a1.y + a1.z + a1.w
             + a2.x + a2.y + a2.z + a2.w;
    float sq = dot4(a0, a0) + dot4(a1, a1) + dot4(a2, a2);
    #pragma unroll
    for (int off = 16; off; off >>= 1) {
        s  += __shfl_xor_sync(0xffffffffu, s,  off);
        sq += __shfl_xor_sync(0xffffffffu, sq, off);
    }
    const float inv = 1.0f / (float)Cn;
    float mu  = s * inv;
    float var = sq * inv - mu * mu;
    float r   = rsqrtf(var + 1e-5f);

    const float4* g4 = (const float4*)g;
    const float4* b4 = (const float4*)b;
    float4* yr = (float4*)(y + (size_t)row * Cn);

    float4 gv, bv, o;
    gv = g4[lane];      bv = b4[lane];
    o.x = (a0.x - mu) * r * gv.x + bv.x;  o.y = (a0.y - mu) * r * gv.y + bv.y;
    o.z = (a0.z - mu) * r * gv.z + bv.z;  o.w = (a0.w - mu) * r * gv.w + bv.w;
    yr[lane] = o;
    gv = g4[lane + 32]; bv = b4[lane + 32];
    o.x = (a1.x - mu) * r * gv.x + bv.x;  o.y = (a1.y - mu) * r * gv.y + bv.y;
    o.z = (a1.z - mu) * r * gv.z + bv.z;  o.w = (a1.w - mu) * r * gv.w + bv.w;
    yr[lane + 32] = o;
    gv = g4[lane + 64]; bv = b4[lane + 64];
    o.x = (a2.x - mu) * r * gv.x + bv.x;  o.y = (a2.y - mu) * r * gv.y + bv.y;
    o.z = (a2.z - mu) * r * gv.z + bv.z;  o.w = (a2.w - mu) * r * gv.w + bv.w;
    yr[lane + 64] = o;
}

// ---------------- pack QKV weights: [3][H][C][HD] -> [C][3*H*HD] -----------
__global__ __launch_bounds__(256)
void pack_qkv(const float* __restrict__ Wq, const float* __restrict__ Wk,
              const float* __restrict__ Wv, float* __restrict__ Wc)
{
    int idx = blockIdx.x * 256 + threadIdx.x;
    if (idx >= Cn * QKVN) return;
    int c = idx / QKVN, j = idx % QKVN;
    int which = j / Cn;          // 0=q, 1=k, 2=v  (Cn == H*HD)
    int r = j % Cn;
    int h = r / HDn, d = r % HDn;
    const float* W = (which == 0) ? Wq : (which == 1) ? Wk : Wv;
    Wc[idx] = W[((size_t)h * Cn + c) * HDn + d];
}

// ---------------- bf16 helpers ---------------------------------------------
__device__ __forceinline__ void bf16_split(float x, __nv_bfloat16& h, __nv_bfloat16& l)
{
    h = __float2bfloat16(x);
    l = __float2bfloat16(x - __bfloat162float(h));
}

__device__ __forceinline__ uint32_t pack_bf16x2(float lo, float hi)
{
    uint32_t d;
    asm("cvt.rn.bf16x2.f32 %0, %1, %2;" : "=r"(d) : "f"(hi), "f"(lo));
    return d;
}

__device__ __forceinline__ void ldm_x4(uint32_t r[4], const __nv_bfloat16* p)
{
    uint32_t addr = (uint32_t)__cvta_generic_to_shared(p);
    asm volatile("ldmatrix.sync.aligned.m8n8.x4.shared.b16 {%0,%1,%2,%3}, [%4];\n"
                 : "=r"(r[0]), "=r"(r[1]), "=r"(r[2]), "=r"(r[3]) : "r"(addr));
}

__device__ __forceinline__ void ldm_x4_trans(uint32_t r[4], const __nv_bfloat16* p)
{
    uint32_t addr = (uint32_t)__cvta_generic_to_shared(p);
    asm volatile("ldmatrix.sync.aligned.m8n8.x4.trans.shared.b16 {%0,%1,%2,%3}, [%4];\n"
                 : "=r"(r[0]), "=r"(r[1]), "=r"(r[2]), "=r"(r[3]) : "r"(addr));
}

__device__ __forceinline__ void mma16816(float d[4], const uint32_t a[4],
                                         uint32_t b0, uint32_t b1)
{
    asm volatile(
        "mma.sync.aligned.m16n8k16.row.col.f32.bf16.bf16.f32 "
        "{%0,%1,%2,%3}, {%4,%5,%6,%7}, {%8,%9}, {%0,%1,%2,%3};\n"
        : "+f"(d[0]), "+f"(d[1]), "+f"(d[2]), "+f"(d[3])
        : "r"(a[0]), "r"(a[1]), "r"(a[2]), "r"(a[3]), "r"(b0), "r"(b1));
}

// ---------------- tensor-core GEMM: block 128x64, BK=32, 3xBF16 split ------
#define PA 72    // A smem pitch (bf16 elems): hi cols [0,32), lo [32,64), pad
#define PB 136   // B smem pitch: hi cols [0,64), lo [64,128), pad

__global__ __launch_bounds__(256, 2)
void mma_gemm(const float* __restrict__ A, const float* __restrict__ B,
              float* __restrict__ Cp, const float* __restrict__ bias,
              const float* __restrict__ residual, int relu, int N, int K)
{
    __shared__ __nv_bfloat16 As[128 * PA];
    __shared__ __nv_bfloat16 Bs[32 * PB];

    const int tid  = threadIdx.x;
    const int lane = tid & 31;
    const int warp = tid >> 5;
    const int wm = warp & 3;      // 0..3  M
    const int wn = warp >> 2;     // 0..1  N
    const int row0 = blockIdx.y * 128;
    const int col0 = blockIdx.x * 64;

    float acc[2][4][4];
    #pragma unroll
    for (int i = 0; i < 2; i++)
        #pragma unroll
        for (int j = 0; j < 4; j++)
            #pragma unroll
            for (int q = 0; q < 4; q++) acc[i][j][q] = 0.f;

    const int arow = tid >> 3;            // 0..31, +p*32 (4 passes)
    const int acol = (tid & 7) * 4;       // 0..28
    const int brow = tid >> 4;            // 0..15, +p*16 (2 passes)
    const int bcol = (tid & 15) * 4;      // 0..60
    float4 pa[4], pb[2];

    const int nk = K / 32;

    #pragma unroll
    for (int p = 0; p < 4; p++)
        pa[p] = *(const float4*)(A + (size_t)(row0 + arow + p * 32) * K + acol);
    #pragma unroll
    for (int p = 0; p < 2; p++)
        pb[p] = *(const float4*)(B + (size_t)(brow + p * 16) * N + col0 + bcol);

    #pragma unroll
    for (int p = 0; p < 4; p++) {
        int r = arow + p * 32;
        __nv_bfloat16 h0,l0,h1,l1,h2,l2,h3,l3;
        bf16_split(pa[p].x, h0, l0); bf16_split(pa[p].y, h1, l1);
        bf16_split(pa[p].z, h2, l2); bf16_split(pa[p].w, h3, l3);
        __nv_bfloat16* d = &As[r * PA + acol];
        d[0]=h0; d[1]=h1; d[2]=h2; d[3]=h3;
        d[32]=l0; d[33]=l1; d[34]=l2; d[35]=l3;
    }
    #pragma unroll
    for (int p = 0; p < 2; p++) {
        int r = brow + p * 16;
        __nv_bfloat16 h0,l0,h1,l1,h2,l2,h3,l3;
        bf16_split(pb[p].x, h0, l0); bf16_split(pb[p].y, h1, l1);
        bf16_split(pb[p].z, h2, l2); bf16_split(pb[p].w, h3, l3);
        __nv_bfloat16* d = &Bs[r * PB + bcol];
        d[0]=h0; d[1]=h1; d[2]=h2; d[3]=h3;
        d[64]=l0; d[65]=l1; d[66]=l2; d[67]=l3;
    }
    __syncthreads();

    for (int kc = 0; kc < nk; kc++) {
        if (kc + 1 < nk) {
            int k0 = (kc + 1) * 32;
            #pragma unroll
            for (int p = 0; p < 4; p++)
                pa[p] = *(const float4*)(A + (size_t)(row0 + arow + p * 32) * K + k0 + acol);
            #pragma unroll
            for (int p = 0; p < 2; p++)
                pb[p] = *(const float4*)(B + (size_t)(k0 + brow + p * 16) * N + col0 + bcol);
        }

        #pragma unroll
        for (int ks = 0; ks < 2; ks++) {
            const int k0 = ks * 16;
            uint32_t ah[2][4], al[2][4], bh[2][4], bl[2][4];
            #pragma unroll
            for (int i = 0; i < 2; i++) {
                const __nv_bfloat16* pbase =
                    &As[(wm * 32 + i * 16 + (lane & 15)) * PA + k0 + 8 * (lane >> 4)];
                ldm_x4(ah[i], pbase);
                ldm_x4(al[i], pbase + 32);
            }
            #pragma unroll
            for (int j2 = 0; j2 < 2; j2++) {
                const __nv_bfloat16* pbase =
                    &Bs[(k0 + (lane & 15)) * PB + wn * 32 + j2 * 16 + 8 * (lane >> 4)];
                ldm_x4_trans(bh[j2], pbase);
                ldm_x4_trans(bl[j2], pbase + 64);
            }
            #pragma unroll
            for (int i = 0; i < 2; i++)
                #pragma unroll
                for (int j = 0; j < 4; j++) {
                    uint32_t bh0 = bh[j >> 1][(j & 1) * 2], bh1 = bh[j >> 1][(j & 1) * 2 + 1];
                    uint32_t bl0 = bl[j >> 1][(j & 1) * 2], bl1 = bl[j >> 1][(j & 1) * 2 + 1];
                    mma16816(acc[i][j], ah[i], bh0, bh1);
                    mma16816(acc[i][j], al[i], bh0, bh1);
                    mma16816(acc[i][j], ah[i], bl0, bl1);
                }
        }
        __syncthreads();

        if (kc + 1 < nk) {
            #pragma unroll
            for (int p = 0; p < 4; p++) {
                int r = arow + p * 32;
                __nv_bfloat16 h0,l0,h1,l1,h2,l2,h3,l3;
                bf16_split(pa[p].x, h0, l0); bf16_split(pa[p].y, h1, l1);
                bf16_split(pa[p].z, h2, l2); bf16_split(pa[p].w, h3, l3);
                __nv_bfloat16* d = &As[r * PA + acol];
                d[0]=h0; d[1]=h1; d[2]=h2; d[3]=h3;
                d[32]=l0; d[33]=l1; d[34]=l2; d[35]=l3;
            }
            #pragma unroll
            for (int p = 0; p < 2; p++) {
                int r = brow + p * 16;
                __nv_bfloat16 h0,l0,h1,l1,h2,l2,h3,l3;
                bf16_split(pb[p].x, h0, l0); bf16_split(pb[p].y, h1, l1);
                bf16_split(pb[p].z, h2, l2); bf16_split(pb[p].w, h3, l3);
                __nv_bfloat16* d = &Bs[r * PB + bcol];
                d[0]=h0; d[1]=h1; d[2]=h2; d[3]=h3;
                d[64]=l0; d[65]=l1; d[66]=l2; d[67]=l3;
            }
            __syncthreads();
        }
    }

    #pragma unroll
    for (int i = 0; i < 2; i++) {
        #pragma unroll
        for (int j = 0; j < 4; j++) {
            int rb = row0 + wm * 32 + i * 16 + (lane >> 2);
            int c  = col0 + wn * 32 + j * 8 + (lane & 3) * 2;
            #pragma unroll
            for (int hh = 0; hh < 2; hh++) {
                int r = rb + 8 * hh;
                float2 v = make_float2(acc[i][j][2 * hh], acc[i][j][2 * hh + 1]);
                if (bias) {
                    float2 bb = *(const float2*)(bias + c);
                    v.x += bb.x; v.y += bb.y;
                }
                if (residual) {
                    float2 rr = *(const float2*)(residual + (size_t)r * N + c);
                    v.x += rr.x; v.y += rr.y;
                }
                if (relu) { v.x = fmaxf(v.x, 0.f); v.y = fmaxf(v.y, 0.f); }
                *(float2*)(Cp + (size_t)r * N + c) = v;
            }
        }
    }
}

// ---------------- flash attention (tensor cores, bf16 3-term split) --------
// grid (qt=2, H, B), 256 threads = 8 warps; warp w owns q rows [w*16, w*16+16)
// of the 128-row q-tile. smem: one 128x136 bf16 buffer (Q stage, then K|V).
#define PF 136   // smem pitch: hi cols [0,64), lo [64,128), +8 pad

__global__ __launch_bounds__(256)
void attn_flash(const float* __restrict__ QKV, float* __restrict__ O)
{
    __shared__ __nv_bfloat16 sm[128 * PF];

    const int tid  = threadIdx.x;
    const int lane = tid & 31;
    const int w    = tid >> 5;
    const int qt = blockIdx.x;           // 0,1
    const int h  = blockIdx.y;
    const int b  = blockIdx.z;
    const float* base = QKV + (size_t)b * Tn * QKVN;

    // ---- stage Q (scaled by 0.125, exact) into smem hi/lo ----
    #pragma unroll
    for (int it = 0; it < 8; it++) {
        int f = tid + it * 256;          // 0..2047
        int row = f >> 4, c4 = (f & 15) * 4;
        float4 v = *(const float4*)(base + (size_t)(qt * 128 + row) * QKVN + h * HDn + c4);
        v.x *= 0.125f; v.y *= 0.125f; v.z *= 0.125f; v.w *= 0.125f;
        __nv_bfloat16 h0,l0,h1,l1,h2,l2,h3,l3;
        bf16_split(v.x, h0, l0); bf16_split(v.y, h1, l1);
        bf16_split(v.z, h2, l2); bf16_split(v.w, h3, l3);
        __nv_bfloat16* d = &sm[row * PF + c4];
        d[0]=h0; d[1]=h1; d[2]=h2; d[3]=h3;
        d[64]=l0; d[65]=l1; d[66]=l2; d[67]=l3;
    }
    __syncthreads();

    // ---- Q fragments to registers: 4 k-steps, hi+lo ----
    uint32_t qh[4][4], ql[4][4];
    #pragma unroll
    for (int ks = 0; ks < 4; ks++) {
        const __nv_bfloat16* p = &sm[(w * 16 + (lane & 15)) * PF + ks * 16 + 8 * (lane >> 4)];
        ldm_x4(qh[ks], p);
        ldm_x4(ql[ks], p + 64);
    }
    __syncthreads();

    // ---- online softmax state + O accumulators ----
    float o[8][4];
    #pragma unroll
    for (int j = 0; j < 8; j++)
        #pragma unroll
        for (int q = 0; q < 4; q++) o[j][q] = 0.f;
    float m_old[2] = {-1e30f, -1e30f};
    float l_sum[2] = {0.f, 0.f};

    const int qrow0 = qt * 128 + w * 16 + (lane >> 2);  // row for q=0,1 (+8 for q=2,3)
    const int n_st = 2 * qt + 2;

    for (int st = 0; st < n_st; st++) {
        // ---- load K (rows 0..63) and V (rows 64..127) hi/lo ----
        #pragma unroll
        for (int it = 0; it < 4; it++) {
            int f = tid + it * 256;      // 0..1023
            int row = f >> 4, c4 = (f & 15) * 4;
            float4 kv = *(const float4*)(base + (size_t)(st * 64 + row) * QKVN + Cn + h * HDn + c4);
            float4 vv = *(const float4*)(base + (size_t)(st * 64 + row) * QKVN + 2 * Cn + h * HDn + c4);
            __nv_bfloat16 h0,l0,h1,l1,h2,l2,h3,l3;
            bf16_split(kv.x, h0, l0); bf16_split(kv.y, h1, l1);
            bf16_split(kv.z, h2, l2); bf16_split(kv.w, h3, l3);
            __nv_bfloat16* d = &sm[row * PF + c4];
            d[0]=h0; d[1]=h1; d[2]=h2; d[3]=h3;
            d[64]=l0; d[65]=l1; d[66]=l2; d[67]=l3;
            bf16_split(vv.x, h0, l0); bf16_split(vv.y, h1, l1);
            bf16_split(vv.z, h2, l2); bf16_split(vv.w, h3, l3);
            d = &sm[(64 + row) * PF + c4];
            d[0]=h0; d[1]=h1; d[2]=h2; d[3]=h3;
            d[64]=l0; d[65]=l1; d[66]=l2; d[67]=l3;
        }
        __syncthreads();

        // ---- S = Q K^T (3-term split), 128x64 tile, warp does 16x64 ----
        float s[8][4];
        #pragma unroll
        for (int j = 0; j < 8; j++)
            #pragma unroll
            for (int q = 0; q < 4; q++) s[j][q] = 0.f;

        #pragma unroll
        for (int ks = 0; ks < 4; ks++) {
            #pragma unroll
            for (int g = 0; g < 4; g++) {
                uint32_t kh4[4], kl4[4];
                const __nv_bfloat16* p =
                    &sm[(g * 16 + (lane & 15)) * PF + ks * 16 + 8 * (lane >> 4)];
                ldm_x4(kh4, p);
                ldm_x4(kl4, p + 64);
                #pragma unroll
                for (int j = 0; j < 2; j++) {
                    int jj = g * 2 + j;
                    mma16816(s[jj], qh[ks], kh4[j], kh4[j + 2]);
                    mma16816(s[jj], ql[ks], kh4[j], kh4[j + 2]);
                    mma16816(s[jj], qh[ks], kl4[j], kl4[j + 2]);
                }
            }
        }

        // ---- causal mask + online softmax ----
        float m_tile[2] = {-1e30f, -1e30f};
        #pragma unroll
        for (int j = 0; j < 8; j++) {
            #pragma unroll
            for (int q = 0; q < 4; q++) {
                int scol = st * 64 + j * 8 + 2 * (lane & 3) + (q & 1);
                int qrow = qrow0 + 8 * (q >> 1);
                if (scol > qrow) s[j][q] = -1e30f;
                m_tile[q >> 1] = fmaxf(m_tile[q >> 1], s[j][q]);
            }
        }
        #pragma unroll
        for (int r = 0; r < 2; r++) {
            m_tile[r] = fmaxf(m_tile[r], __shfl_xor_sync(0xffffffffu, m_tile[r], 1));
            m_tile[r] = fmaxf(m_tile[r], __shfl_xor_sync(0xffffffffu, m_tile[r], 2));
        }
        float m_new[2], fscale[2], rsum[2] = {0.f, 0.f};
        #pragma unroll
        for (int r = 0; r < 2; r++) {
            m_new[r] = fmaxf(m_old[r], m_tile[r]);
            fscale[r] = __expf(m_old[r] - m_new[r]);
        }
        #pragma unroll
        for (int j = 0; j < 8; j++) {
            #pragma unroll
            for (int q = 0; q < 4; q++) {
                float p = __expf(s[j][q] - m_new[q >> 1]);
                s[j][q] = p;
                rsum[q >> 1] += p;
            }
        }
        #pragma unroll
        for (int r = 0; r < 2; r++) {
            rsum[r] += __shfl_xor_sync(0xffffffffu, rsum[r], 1);
            rsum[r] += __shfl_xor_sync(0xffffffffu, rsum[r], 2);
            l_sum[r] = l_sum[r] * fscale[r] + rsum[r];
            m_old[r] = m_new[r];
        }
        #pragma unroll
        for (int j = 0; j < 8; j++) {
            o[j][0] *= fscale[0]; o[j][1] *= fscale[0];
            o[j][2] *= fscale[1]; o[j][3] *= fscale[1];
        }

        // ---- O += P V (3-term split: Ph*Vh + Pl*Vh + Ph*Vl) ----
        #pragma unroll
        for (int ks = 0; ks < 4; ks++) {
            // P fragments from s[2ks], s[2ks+1]
            float p00 = s[2*ks][0],   p01 = s[2*ks][1],   p02 = s[2*ks][2],   p03 = s[2*ks][3];
            float p10 = s[2*ks+1][0], p11 = s[2*ks+1][1], p12 = s[2*ks+1][2], p13 = s[2*ks+1][3];
            uint32_t pah[4], pal[4];
            pah[0] = pack_bf16x2(p00, p01);
            pah[1] = pack_bf16x2(p02, p03);
            pah[2] = pack_bf16x2(p10, p11);
            pah[3] = pack_bf16x2(p12, p13);
            // residuals
            float r00 = p00 - __bfloat162float(__float2bfloat16(p00));
            float r01 = p01 - __bfloat162float(__float2bfloat16(p01));
            float r02 = p02 - __bfloat162float(__float2bfloat16(p02));
            float r03 = p03 - __bfloat162float(__float2bfloat16(p03));
            float r10 = p10 - __bfloat162float(__float2bfloat16(p10));
            float r11 = p11 - __bfloat162float(__float2bfloat16(p11));
            float r12 = p12 - __bfloat162float(__float2bfloat16(p12));
            float r13 = p13 - __bfloat162float(__float2bfloat16(p13));
            pal[0] = pack_bf16x2(r00, r01);
            pal[1] = pack_bf16x2(r02, r03);
            pal[2] = pack_bf16x2(r10, r11);
            pal[3] = pack_bf16x2(r12, r13);

            #pragma unroll
            for (int g = 0; g < 4; g++) {
                uint32_t vh4[4], vl4[4];
                const __nv_bfloat16* p =
                    &sm[(64 + ks * 16 + (lane & 15)) * PF + g * 16 + 8 * (lane >> 4)];
                ldm_x4_trans(vh4, p);
                ldm_x4_trans(vl4, p + 64);
                #pragma unroll
                for (int j = 0; j < 2; j++) {
                    int dd = g * 2 + j;
                    mma16816(o[dd], pah, vh4[j * 2], vh4[j * 2 + 1]);
                    mma16816(o[dd], pal, vh4[j * 2], vh4[j * 2 + 1]);
                    mma16816(o[dd], pah, vl4[j * 2], vl4[j * 2 + 1]);
                }
            }
        }
        __syncthreads();
    }

    // ---- epilogue: normalize and store ----
    float inv0 = 1.0f / l_sum[0];
    float inv1 = 1.0f / l_sum[1];
    #pragma unroll
    for (int j = 0; j < 8; j++) {
        int col = h * HDn + j * 8 + 2 * (lane & 3);
        #pragma unroll
        for (int r = 0; r < 2; r++) {
            int row = b * Tn + qrow0 + 8 * r;
            float inv = r ? inv1 : inv0;
            float2 v = make_float2(o[j][2 * r] * inv, o[j][2 * r + 1] * inv);
            *(float2*)(O + (size_t)row * Cn + col) = v;
        }
    }
}

// ---------------- launch ---------------------------------------------------
extern "C" void kernel_launch(void* const* d_in, const int* in_sizes, int n_in,
                              void* d_out, int out_size)
{
    const float* x     = (const float*)d_in[0];
    const float* ln1_g = (const float*)d_in[1];
    const float* ln1_b = (const float*)d_in[2];
    const float* Wq    = (const float*)d_in[3];
    const float* Wk    = (const float*)d_in[4];
    const float* Wv    = (const float*)d_in[5];
    const float* Wo    = (const float*)d_in[6];
    const float* bo    = (const float*)d_in[7];
    const float* ln2_g = (const float*)d_in[8];
    const float* ln2_b = (const float*)d_in[9];
    const float* W1    = (const float*)d_in[10];
    const float* b1    = (const float*)d_in[11];
    const float* W2    = (const float*)d_in[12];
    const float* b2    = (const float*)d_in[13];
    float* out = (float*)d_out;

    void *px1, *pqkv, *pattn, *phid, *pwqkv;
    cudaGetSymbolAddress(&px1,   g_x1);
    cudaGetSymbolAddress(&pqkv,  g_qkv);
    cudaGetSymbolAddress(&pattn, g_attn);
    cudaGetSymbolAddress(&phid,  g_hid);
    cudaGetSymbolAddress(&pwqkv, g_wqkv);
    float* x1   = (float*)px1;
    float* qkv  = (float*)pqkv;
    float* attn = (float*)pattn;
    float* hid  = (float*)phid;
    float* wqkv = (float*)pwqkv;

    // LN1
    ln_kernel<<<BT / 8, 256>>>(x, ln1_g, ln1_b, x1);
    // pack QKV weights into [C, 1152]
    pack_qkv<<<(Cn * QKVN + 255) / 256, 256>>>(Wq, Wk, Wv, wqkv);
    // fused QKV projection: [BT,384] x [384,1152]
    mma_gemm<<<dim3(QKVN / 64, BT / 128), 256>>>(x1, wqkv, qkv, nullptr, nullptr, 0, QKVN, Cn);
    // causal flash attention
    attn_flash<<<dim3(2, Hn, Bn), 256>>>(qkv, attn);
    // output projection + bias + residual(x) -> d_out
    mma_gemm<<<dim3(Cn / 64, BT / 128), 256>>>(attn, Wo, out, bo, x, 0, Cn, Cn);
    // LN2 (reads d_out)
    ln_kernel<<<BT / 8, 256>>>(out, ln2_g, ln2_b, x1);
    // FFN1: relu(x2 @ W1 + b1)
    mma_gemm<<<dim3(FF / 64, BT / 128), 256>>>(x1, W1, hid, b1, nullptr, 1, FF, Cn);
    // FFN2: d_out += hid @ W2 + b2 (in-place residual, tile-local)
    mma_gemm<<<dim3(Cn / 64, BT / 128), 256>>>(hid, W2, out, b2, out, 0, Cn, FF);
}

// round 4
// speedup vs baseline: 2.5642x; 1.0013x over previous
#include <cuda_runtime.h>
#include <cuda_bf16.h>
#include <math.h>
#include <stdint.h>

#define Bn  128
#define Tn  256
#define Cn  384
#define Hn  6
#define HDn 64
#define BT  (Bn * Tn)
#define FF  (4 * Cn)
#define QKVN (3 * Cn)   // 1152

// ---------------- scratch (device globals; allocation-free) ----------------
__device__ float g_x1  [(size_t)BT * Cn];          // LN1 / LN2 output
__device__ float g_qkv [(size_t)BT * QKVN];        // fused qkv output
__device__ float g_attn[(size_t)BT * Cn];          // concat-head attention out
__device__ float g_hid [(size_t)BT * FF];          // FFN hidden
__device__ float g_wqkv[(size_t)Cn * QKVN];        // packed QKV weights [C, 3*H*HD]

__device__ __forceinline__ float dot4(const float4 a, const float4 b) {
    return a.x * b.x + a.y * b.y + a.z * b.z + a.w * b.w;
}

// ---------------- LayerNorm: one warp per row (C = 384 = 96 float4) --------
__global__ __launch_bounds__(256)
void ln_kernel(const float* __restrict__ x, const float* __restrict__ g,
               const float* __restrict__ b, float* __restrict__ y)
{
    int row  = blockIdx.x * 8 + (threadIdx.x >> 5);
    int lane = threadIdx.x & 31;
    const float4* xr = (const float4*)(x + (size_t)row * Cn);
    float4 a0 = xr[lane], a1 = xr[lane + 32], a2 = xr[lane + 64];

    float s  = a0.x + a0.y + a0.z + a0.w
             + a1.x + a1.y + a1.z + a1.w
             + a2.x + a2.y + a2.z + a2.w;
    float sq = dot4(a0, a0) + dot4(a1, a1) + dot4(a2, a2);
    #pragma unroll
    for (int off = 16; off; off >>= 1) {
        s  += __shfl_xor_sync(0xffffffffu, s,  off);
        sq += __shfl_xor_sync(0xffffffffu, sq, off);
    }
    const float inv = 1.0f / (float)Cn;
    float mu  = s * inv;
    float var = sq * inv - mu * mu;
    float r   = rsqrtf(var + 1e-5f);

    const float4* g4 = (const float4*)g;
    const float4* b4 = (const float4*)b;
    float4* yr = (float4*)(y + (size_t)row * Cn);

    float4 gv, bv, o;
    gv = g4[lane];      bv = b4[lane];
    o.x = (a0.x - mu) * r * gv.x + bv.x;  o.y = (a0.y - mu) * r * gv.y + bv.y;
    o.z = (a0.z - mu) * r * gv.z + bv.z;  o.w = (a0.w - mu) * r * gv.w + bv.w;
    yr[lane] = o;
    gv = g4[lane + 32]; bv = b4[lane + 32];
    o.x = (a1.x - mu) * r * gv.x + bv.x;  o.y = (a1.y - mu) * r * gv.y + bv.y;
    o.z = (a1.z - mu) * r * gv.z + bv.z;  o.w = (a1.w - mu) * r * gv.w + bv.w;
    yr[lane + 32] = o;
    gv = g4[lane + 64]; bv = b4[lane + 64];
    o.x = (a2.x - mu) * r * gv.x + bv.x;  o.y = (a2.y - mu) * r * gv.y + bv.y;
    o.z = (a2.z - mu) * r * gv.z + bv.z;  o.w = (a2.w - mu) * r * gv.w + bv.w;
    yr[lane + 64] = o;
}

// ---------------- pack QKV weights: [3][H][C][HD] -> [C][3*H*HD] -----------
__global__ __launch_bounds__(256)
void pack_qkv(const float* __restrict__ Wq, const float* __restrict__ Wk,
              const float* __restrict__ Wv, float* __restrict__ Wc)
{
    int idx = blockIdx.x * 256 + threadIdx.x;
    if (idx >= Cn * QKVN) return;
    int c = idx / QKVN, j = idx % QKVN;
    int which = j / Cn;          // 0=q, 1=k, 2=v  (Cn == H*HD)
    int r = j % Cn;
    int h = r / HDn, d = r % HDn;
    const float* W = (which == 0) ? Wq : (which == 1) ? Wk : Wv;
    Wc[idx] = W[((size_t)h * Cn + c) * HDn + d];
}

// ---------------- bf16 helpers ---------------------------------------------
__device__ __forceinline__ void bf16_split(float x, __nv_bfloat16& h, __nv_bfloat16& l)
{
    h = __float2bfloat16(x);
    l = __float2bfloat16(x - __bfloat162float(h));
}

__device__ __forceinline__ uint32_t pack_bf16x2(float lo, float hi)
{
    uint32_t d;
    asm("cvt.rn.bf16x2.f32 %0, %1, %2;" : "=r"(d) : "f"(hi), "f"(lo));
    return d;
}

__device__ __forceinline__ void ldm_x4(uint32_t r[4], const __nv_bfloat16* p)
{
    uint32_t addr = (uint32_t)__cvta_generic_to_shared(p);
    asm volatile("ldmatrix.sync.aligned.m8n8.x4.shared.b16 {%0,%1,%2,%3}, [%4];\n"
                 : "=r"(r[0]), "=r"(r[1]), "=r"(r[2]), "=r"(r[3]) : "r"(addr));
}

__device__ __forceinline__ void ldm_x4_trans(uint32_t r[4], const __nv_bfloat16* p)
{
    uint32_t addr = (uint32_t)__cvta_generic_to_shared(p);
    asm volatile("ldmatrix.sync.aligned.m8n8.x4.trans.shared.b16 {%0,%1,%2,%3}, [%4];\n"
                 : "=r"(r[0]), "=r"(r[1]), "=r"(r[2]), "=r"(r[3]) : "r"(addr));
}

__device__ __forceinline__ void mma16816(float d[4], const uint32_t a[4],
                                         uint32_t b0, uint32_t b1)
{
    asm volatile(
        "mma.sync.aligned.m16n8k16.row.col.f32.bf16.bf16.f32 "
        "{%0,%1,%2,%3}, {%4,%5,%6,%7}, {%8,%9}, {%0,%1,%2,%3};\n"
        : "+f"(d[0]), "+f"(d[1]), "+f"(d[2]), "+f"(d[3])
        : "r"(a[0]), "r"(a[1]), "r"(a[2]), "r"(a[3]), "r"(b0), "r"(b1));
}

// ---------------- tensor-core GEMM: block 128x64, BK=32, 3xBF16 split ------
#define PA 72    // A smem pitch (bf16 elems): hi cols [0,32), lo [32,64), pad
#define PB 136   // B smem pitch: hi cols [0,64), lo [64,128), pad

__global__ __launch_bounds__(256, 2)
void mma_gemm(const float* __restrict__ A, const float* __restrict__ B,
              float* __restrict__ Cp, const float* __restrict__ bias,
              const float* __restrict__ residual, int relu, int N, int K)
{
    __shared__ __nv_bfloat16 As[128 * PA];
    __shared__ __nv_bfloat16 Bs[32 * PB];

    const int tid  = threadIdx.x;
    const int lane = tid & 31;
    const int warp = tid >> 5;
    const int wm = warp & 3;      // 0..3  M
    const int wn = warp >> 2;     // 0..1  N
    const int row0 = blockIdx.y * 128;
    const int col0 = blockIdx.x * 64;

    float acc[2][4][4];
    #pragma unroll
    for (int i = 0; i < 2; i++)
        #pragma unroll
        for (int j = 0; j < 4; j++)
            #pragma unroll
            for (int q = 0; q < 4; q++) acc[i][j][q] = 0.f;

    const int arow = tid >> 3;            // 0..31, +p*32 (4 passes)
    const int acol = (tid & 7) * 4;       // 0..28
    const int brow = tid >> 4;            // 0..15, +p*16 (2 passes)
    const int bcol = (tid & 15) * 4;      // 0..60
    float4 pa[4], pb[2];

    const int nk = K / 32;

    #pragma unroll
    for (int p = 0; p < 4; p++)
        pa[p] = *(const float4*)(A + (size_t)(row0 + arow + p * 32) * K + acol);
    #pragma unroll
    for (int p = 0; p < 2; p++)
        pb[p] = *(const float4*)(B + (size_t)(brow + p * 16) * N + col0 + bcol);

    #pragma unroll
    for (int p = 0; p < 4; p++) {
        int r = arow + p * 32;
        __nv_bfloat16 h0,l0,h1,l1,h2,l2,h3,l3;
        bf16_split(pa[p].x, h0, l0); bf16_split(pa[p].y, h1, l1);
        bf16_split(pa[p].z, h2, l2); bf16_split(pa[p].w, h3, l3);
        __nv_bfloat16* d = &As[r * PA + acol];
        d[0]=h0; d[1]=h1; d[2]=h2; d[3]=h3;
        d[32]=l0; d[33]=l1; d[34]=l2; d[35]=l3;
    }
    #pragma unroll
    for (int p = 0; p < 2; p++) {
        int r = brow + p * 16;
        __nv_bfloat16 h0,l0,h1,l1,h2,l2,h3,l3;
        bf16_split(pb[p].x, h0, l0); bf16_split(pb[p].y, h1, l1);
        bf16_split(pb[p].z, h2, l2); bf16_split(pb[p].w, h3, l3);
        __nv_bfloat16* d = &Bs[r * PB + bcol];
        d[0]=h0; d[1]=h1; d[2]=h2; d[3]=h3;
        d[64]=l0; d[65]=l1; d[66]=l2; d[67]=l3;
    }
    __syncthreads();

    for (int kc = 0; kc < nk; kc++) {
        if (kc + 1 < nk) {
            int k0 = (kc + 1) * 32;
            #pragma unroll
            for (int p = 0; p < 4; p++)
                pa[p] = *(const float4*)(A + (size_t)(row0 + arow + p * 32) * K + k0 + acol);
            #pragma unroll
            for (int p = 0; p < 2; p++)
                pb[p] = *(const float4*)(B + (size_t)(k0 + brow + p * 16) * N + col0 + bcol);
        }

        #pragma unroll
        for (int ks = 0; ks < 2; ks++) {
            const int k0 = ks * 16;
            uint32_t ah[2][4], al[2][4], bh[2][4], bl[2][4];
            #pragma unroll
            for (int i = 0; i < 2; i++) {
                const __nv_bfloat16* pbase =
                    &As[(wm * 32 + i * 16 + (lane & 15)) * PA + k0 + 8 * (lane >> 4)];
                ldm_x4(ah[i], pbase);
                ldm_x4(al[i], pbase + 32);
            }
            #pragma unroll
            for (int j2 = 0; j2 < 2; j2++) {
                const __nv_bfloat16* pbase =
                    &Bs[(k0 + (lane & 15)) * PB + wn * 32 + j2 * 16 + 8 * (lane >> 4)];
                ldm_x4_trans(bh[j2], pbase);
                ldm_x4_trans(bl[j2], pbase + 64);
            }
            #pragma unroll
            for (int i = 0; i < 2; i++)
                #pragma unroll
                for (int j = 0; j < 4; j++) {
                    uint32_t bh0 = bh[j >> 1][(j & 1) * 2], bh1 = bh[j >> 1][(j & 1) * 2 + 1];
                    uint32_t bl0 = bl[j >> 1][(j & 1) * 2], bl1 = bl[j >> 1][(j & 1) * 2 + 1];
                    mma16816(acc[i][j], ah[i], bh0, bh1);
                    mma16816(acc[i][j], al[i], bh0, bh1);
                    mma16816(acc[i][j], ah[i], bl0, bl1);
                }
        }
        __syncthreads();

        if (kc + 1 < nk) {
            #pragma unroll
            for (int p = 0; p < 4; p++) {
                int r = arow + p * 32;
                __nv_bfloat16 h0,l0,h1,l1,h2,l2,h3,l3;
                bf16_split(pa[p].x, h0, l0); bf16_split(pa[p].y, h1, l1);
                bf16_split(pa[p].z, h2, l2); bf16_split(pa[p].w, h3, l3);
                __nv_bfloat16* d = &As[r * PA + acol];
                d[0]=h0; d[1]=h1; d[2]=h2; d[3]=h3;
                d[32]=l0; d[33]=l1; d[34]=l2; d[35]=l3;
            }
            #pragma unroll
            for (int p = 0; p < 2; p++) {
                int r = brow + p * 16;
                __nv_bfloat16 h0,l0,h1,l1,h2,l2,h3,l3;
                bf16_split(pb[p].x, h0, l0); bf16_split(pb[p].y, h1, l1);
                bf16_split(pb[p].z, h2, l2); bf16_split(pb[p].w, h3, l3);
                __nv_bfloat16* d = &Bs[r * PB + bcol];
                d[0]=h0; d[1]=h1; d[2]=h2; d[3]=h3;
                d[64]=l0; d[65]=l1; d[66]=l2; d[67]=l3;
            }
            __syncthreads();
        }
    }

    #pragma unroll
    for (int i = 0; i < 2; i++) {
        #pragma unroll
        for (int j = 0; j < 4; j++) {
            int rb = row0 + wm * 32 + i * 16 + (lane >> 2);
            int c  = col0 + wn * 32 + j * 8 + (lane & 3) * 2;
            #pragma unroll
            for (int hh = 0; hh < 2; hh++) {
                int r = rb + 8 * hh;
                float2 v = make_float2(acc[i][j][2 * hh], acc[i][j][2 * hh + 1]);
                if (bias) {
                    float2 bb = *(const float2*)(bias + c);
                    v.x += bb.x; v.y += bb.y;
                }
                if (residual) {
                    float2 rr = *(const float2*)(residual + (size_t)r * N + c);
                    v.x += rr.x; v.y += rr.y;
                }
                if (relu) { v.x = fmaxf(v.x, 0.f); v.y = fmaxf(v.y, 0.f); }
                *(float2*)(Cp + (size_t)r * N + c) = v;
            }
        }
    }
}

// ---------------- flash attention (tensor cores, bf16 3-term split) --------
// grid (qt=2, H, B), 256 threads = 8 warps; warp w owns q rows [w*16, w*16+16)
// of the 128-row q-tile. smem: one 128x136 bf16 buffer (Q stage, then K|V).
#define PF 136   // smem pitch: hi cols [0,64), lo [64,128), +8 pad

__global__ __launch_bounds__(256)
void attn_flash(const float* __restrict__ QKV, float* __restrict__ O)
{
    __shared__ __nv_bfloat16 sm[128 * PF];

    const int tid  = threadIdx.x;
    const int lane = tid & 31;
    const int w    = tid >> 5;
    const int qt = blockIdx.x;           // 0,1
    const int h  = blockIdx.y;
    const int b  = blockIdx.z;
    const float* base = QKV + (size_t)b * Tn * QKVN;

    // ---- stage Q (scaled by 0.125, exact) into smem hi/lo ----
    #pragma unroll
    for (int it = 0; it < 8; it++) {
        int f = tid + it * 256;          // 0..2047
        int row = f >> 4, c4 = (f & 15) * 4;
        float4 v = *(const float4*)(base + (size_t)(qt * 128 + row) * QKVN + h * HDn + c4);
        v.x *= 0.125f; v.y *= 0.125f; v.z *= 0.125f; v.w *= 0.125f;
        __nv_bfloat16 h0,l0,h1,l1,h2,l2,h3,l3;
        bf16_split(v.x, h0, l0); bf16_split(v.y, h1, l1);
        bf16_split(v.z, h2, l2); bf16_split(v.w, h3, l3);
        __nv_bfloat16* d = &sm[row * PF + c4];
        d[0]=h0; d[1]=h1; d[2]=h2; d[3]=h3;
        d[64]=l0; d[65]=l1; d[66]=l2; d[67]=l3;
    }
    __syncthreads();

    // ---- Q fragments to registers: 4 k-steps, hi+lo ----
    uint32_t qh[4][4], ql[4][4];
    #pragma unroll
    for (int ks = 0; ks < 4; ks++) {
        const __nv_bfloat16* p = &sm[(w * 16 + (lane & 15)) * PF + ks * 16 + 8 * (lane >> 4)];
        ldm_x4(qh[ks], p);
        ldm_x4(ql[ks], p + 64);
    }
    __syncthreads();

    // ---- online softmax state + O accumulators ----
    float o[8][4];
    #pragma unroll
    for (int j = 0; j < 8; j++)
        #pragma unroll
        for (int q = 0; q < 4; q++) o[j][q] = 0.f;
    float m_old[2] = {-1e30f, -1e30f};
    float l_sum[2] = {0.f, 0.f};

    const int qrow0 = qt * 128 + w * 16 + (lane >> 2);  // row for q=0,1 (+8 for q=2,3)
    const int n_st = 2 * qt + 2;

    for (int st = 0; st < n_st; st++) {
        // ---- load K (rows 0..63) and V (rows 64..127) hi/lo ----
        #pragma unroll
        for (int it = 0; it < 4; it++) {
            int f = tid + it * 256;      // 0..1023
            int row = f >> 4, c4 = (f & 15) * 4;
            float4 kv = *(const float4*)(base + (size_t)(st * 64 + row) * QKVN + Cn + h * HDn + c4);
            float4 vv = *(const float4*)(base + (size_t)(st * 64 + row) * QKVN + 2 * Cn + h * HDn + c4);
            __nv_bfloat16 h0,l0,h1,l1,h2,l2,h3,l3;
            bf16_split(kv.x, h0, l0); bf16_split(kv.y, h1, l1);
            bf16_split(kv.z, h2, l2); bf16_split(kv.w, h3, l3);
            __nv_bfloat16* d = &sm[row * PF + c4];
            d[0]=h0; d[1]=h1; d[2]=h2; d[3]=h3;
            d[64]=l0; d[65]=l1; d[66]=l2; d[67]=l3;
            bf16_split(vv.x, h0, l0); bf16_split(vv.y, h1, l1);
            bf16_split(vv.z, h2, l2); bf16_split(vv.w, h3, l3);
            d = &sm[(64 + row) * PF + c4];
            d[0]=h0; d[1]=h1; d[2]=h2; d[3]=h3;
            d[64]=l0; d[65]=l1; d[66]=l2; d[67]=l3;
        }
        __syncthreads();

        // ---- S = Q K^T (3-term split), 128x64 tile, warp does 16x64 ----
        float s[8][4];
        #pragma unroll
        for (int j = 0; j < 8; j++)
            #pragma unroll
            for (int q = 0; q < 4; q++) s[j][q] = 0.f;

        #pragma unroll
        for (int ks = 0; ks < 4; ks++) {
            #pragma unroll
            for (int g = 0; g < 4; g++) {
                uint32_t kh4[4], kl4[4];
                const __nv_bfloat16* p =
                    &sm[(g * 16 + (lane & 15)) * PF + ks * 16 + 8 * (lane >> 4)];
                ldm_x4(kh4, p);
                ldm_x4(kl4, p + 64);
                #pragma unroll
                for (int j = 0; j < 2; j++) {
                    int jj = g * 2 + j;
                    mma16816(s[jj], qh[ks], kh4[j], kh4[j + 2]);
                    mma16816(s[jj], ql[ks], kh4[j], kh4[j + 2]);
                    mma16816(s[jj], qh[ks], kl4[j], kl4[j + 2]);
                }
            }
        }

        // ---- causal mask + online softmax ----
        float m_tile[2] = {-1e30f, -1e30f};
        #pragma unroll
        for (int j = 0; j < 8; j++) {
            #pragma unroll
            for (int q = 0; q < 4; q++) {
                int scol = st * 64 + j * 8 + 2 * (lane & 3) + (q & 1);
                int qrow = qrow0 + 8 * (q >> 1);
                if (scol > qrow) s[j][q] = -1e30f;
                m_tile[q >> 1] = fmaxf(m_tile[q >> 1], s[j][q]);
            }
        }
        #pragma unroll
        for (int r = 0; r < 2; r++) {
            m_tile[r] = fmaxf(m_tile[r], __shfl_xor_sync(0xffffffffu, m_tile[r], 1));
            m_tile[r] = fmaxf(m_tile[r], __shfl_xor_sync(0xffffffffu, m_tile[r], 2));
        }
        float m_new[2], fscale[2], rsum[2] = {0.f, 0.f};
        #pragma unroll
        for (int r = 0; r < 2; r++) {
            m_new[r] = fmaxf(m_old[r], m_tile[r]);
            fscale[r] = __expf(m_old[r] - m_new[r]);
        }
        #pragma unroll
        for (int j = 0; j < 8; j++) {
            #pragma unroll
            for (int q = 0; q < 4; q++) {
                float p = __expf(s[j][q] - m_new[q >> 1]);
                s[j][q] = p;
                rsum[q >> 1] += p;
            }
        }
        #pragma unroll
        for (int r = 0; r < 2; r++) {
            rsum[r] += __shfl_xor_sync(0xffffffffu, rsum[r], 1);
            rsum[r] += __shfl_xor_sync(0xffffffffu, rsum[r], 2);
            l_sum[r] = l_sum[r] * fscale[r] + rsum[r];
            m_old[r] = m_new[r];
        }
        #pragma unroll
        for (int j = 0; j < 8; j++) {
            o[j][0] *= fscale[0]; o[j][1] *= fscale[0];
            o[j][2] *= fscale[1]; o[j][3] *= fscale[1];
        }

        // ---- O += P V (3-term split: Ph*Vh + Pl*Vh + Ph*Vl) ----
        #pragma unroll
        for (int ks = 0; ks < 4; ks++) {
            // P fragments from s[2ks], s[2ks+1]
            float p00 = s[2*ks][0],   p01 = s[2*ks][1],   p02 = s[2*ks][2],   p03 = s[2*ks][3];
            float p10 = s[2*ks+1][0], p11 = s[2*ks+1][1], p12 = s[2*ks+1][2], p13 = s[2*ks+1][3];
            uint32_t pah[4], pal[4];
            pah[0] = pack_bf16x2(p00, p01);
            pah[1] = pack_bf16x2(p02, p03);
            pah[2] = pack_bf16x2(p10, p11);
            pah[3] = pack_bf16x2(p12, p13);
            // residuals
            float r00 = p00 - __bfloat162float(__float2bfloat16(p00));
            float r01 = p01 - __bfloat162float(__float2bfloat16(p01));
            float r02 = p02 - __bfloat162float(__float2bfloat16(p02));
            float r03 = p03 - __bfloat162float(__float2bfloat16(p03));
            float r10 = p10 - __bfloat162float(__float2bfloat16(p10));
            float r11 = p11 - __bfloat162float(__float2bfloat16(p11));
            float r12 = p12 - __bfloat162float(__float2bfloat16(p12));
            float r13 = p13 - __bfloat162float(__float2bfloat16(p13));
            pal[0] = pack_bf16x2(r00, r01);
            pal[1] = pack_bf16x2(r02, r03);
            pal[2] = pack_bf16x2(r10, r11);
            pal[3] = pack_bf16x2(r12, r13);

            #pragma unroll
            for (int g = 0; g < 4; g++) {
                uint32_t vh4[4], vl4[4];
                const __nv_bfloat16* p =
                    &sm[(64 + ks * 16 + (lane & 15)) * PF + g * 16 + 8 * (lane >> 4)];
                ldm_x4_trans(vh4, p);
                ldm_x4_trans(vl4, p + 64);
                #pragma unroll
                for (int j = 0; j < 2; j++) {
                    int dd = g * 2 + j;
                    mma16816(o[dd], pah, vh4[j * 2], vh4[j * 2 + 1]);
                    mma16816(o[dd], pal, vh4[j * 2], vh4[j * 2 + 1]);
                    mma16816(o[dd], pah, vl4[j * 2], vl4[j * 2 + 1]);
                }
            }
        }
        __syncthreads();
    }

    // ---- epilogue: normalize and store ----
    float inv0 = 1.0f / l_sum[0];
    float inv1 = 1.0f / l_sum[1];
    #pragma unroll
    for (int j = 0; j < 8; j++) {
        int col = h * HDn + j * 8 + 2 * (lane & 3);
        #pragma unroll
        for (int r = 0; r < 2; r++) {
            int row = b * Tn + qrow0 + 8 * r;
            float inv = r ? inv1 : inv0;
            float2 v = make_float2(o[j][2 * r] * inv, o[j][2 * r + 1] * inv);
            *(float2*)(O + (size_t)row * Cn + col) = v;
        }
    }
}

// ---------------- launch ---------------------------------------------------
extern "C" void kernel_launch(void* const* d_in, const int* in_sizes, int n_in,
                              void* d_out, int out_size)
{
    const float* x     = (const float*)d_in[0];
    const float* ln1_g = (const float*)d_in[1];
    const float* ln1_b = (const float*)d_in[2];
    const float* Wq    = (const float*)d_in[3];
    const float* Wk    = (const float*)d_in[4];
    const float* Wv    = (const float*)d_in[5];
    const float* Wo    = (const float*)d_in[6];
    const float* bo    = (const float*)d_in[7];
    const float* ln2_g = (const float*)d_in[8];
    const float* ln2_b = (const float*)d_in[9];
    const float* W1    = (const float*)d_in[10];
    const float* b1    = (const float*)d_in[11];
    const float* W2    = (const float*)d_in[12];
    const float* b2    = (const float*)d_in[13];
    float* out = (float*)d_out;

    void *px1, *pqkv, *pattn, *phid, *pwqkv;
    cudaGetSymbolAddress(&px1,   g_x1);
    cudaGetSymbolAddress(&pqkv,  g_qkv);
    cudaGetSymbolAddress(&pattn, g_attn);
    cudaGetSymbolAddress(&phid,  g_hid);
    cudaGetSymbolAddress(&pwqkv, g_wqkv);
    float* x1   = (float*)px1;
    float* qkv  = (float*)pqkv;
    float* attn = (float*)pattn;
    float* hid  = (float*)phid;
    float* wqkv = (float*)pwqkv;

    // LN1
    ln_kernel<<<BT / 8, 256>>>(x, ln1_g, ln1_b, x1);
    // pack QKV weights into [C, 1152]
    pack_qkv<<<(Cn * QKVN + 255) / 256, 256>>>(Wq, Wk, Wv, wqkv);
    // fused QKV projection: [BT,384] x [384,1152]
    mma_gemm<<<dim3(QKVN / 64, BT / 128), 256>>>(x1, wqkv, qkv, nullptr, nullptr, 0, QKVN, Cn);
    // causal flash attention
    attn_flash<<<dim3(2, Hn, Bn), 256>>>(qkv, attn);
    // output projection + bias + residual(x) -> d_out
    mma_gemm<<<dim3(Cn / 64, BT / 128), 256>>>(attn, Wo, out, bo, x, 0, Cn, Cn);
    // LN2 (reads d_out)
    ln_kernel<<<BT / 8, 256>>>(out, ln2_g, ln2_b, x1);
    // FFN1: relu(x2 @ W1 + b1)
    mma_gemm<<<dim3(FF / 64, BT / 128), 256>>>(x1, W1, hid, b1, nullptr, 1, FF, Cn);
    // FFN2: d_out += hid @ W2 + b2 (in-place residual, tile-local)
    mma_gemm<<<dim3(Cn / 64, BT / 128), 256>>>(hid, W2, out, b2, out, 0, Cn, FF);
}

// round 6
// speedup vs baseline: 3.2361x; 1.2620x over previous
#include <cuda_runtime.h>
#include <cuda_bf16.h>
#include <math.h>
#include <stdint.h>

#define Bn  128
#define Tn  256
#define Cn  384
#define Hn  6
#define HDn 64
#define BT  (Bn * Tn)
#define FF  (4 * Cn)
#define QKVN (3 * Cn)   // 1152

// ---------------- scratch (device globals; allocation-free) ----------------
__device__ __align__(16) float g_qkv[(size_t)BT * QKVN];
__device__ __align__(16) __nv_bfloat16 g_x1h [(size_t)BT * Cn];
__device__ __align__(16) __nv_bfloat16 g_x1l [(size_t)BT * Cn];
__device__ __align__(16) __nv_bfloat16 g_ath [(size_t)BT * Cn];
__device__ __align__(16) __nv_bfloat16 g_atl [(size_t)BT * Cn];
__device__ __align__(16) __nv_bfloat16 g_hidh[(size_t)BT * FF];
__device__ __align__(16) __nv_bfloat16 g_hidl[(size_t)BT * FF];
__device__ __align__(16) __nv_bfloat16 g_wqkvh[(size_t)QKVN * Cn];
__device__ __align__(16) __nv_bfloat16 g_wqkvl[(size_t)QKVN * Cn];
__device__ __align__(16) __nv_bfloat16 g_woth[(size_t)Cn * Cn];
__device__ __align__(16) __nv_bfloat16 g_wotl[(size_t)Cn * Cn];
__device__ __align__(16) __nv_bfloat16 g_w1th[(size_t)FF * Cn];
__device__ __align__(16) __nv_bfloat16 g_w1tl[(size_t)FF * Cn];
__device__ __align__(16) __nv_bfloat16 g_w2th[(size_t)Cn * FF];
__device__ __align__(16) __nv_bfloat16 g_w2tl[(size_t)Cn * FF];

// ---------------- helpers ---------------------------------------------------
__device__ __forceinline__ float dot4(const float4 a, const float4 b) {
    return a.x * b.x + a.y * b.y + a.z * b.z + a.w * b.w;
}
__device__ __forceinline__ uint32_t pack_bf16x2(float lo, float hi) {
    uint32_t d;
    asm("cvt.rn.bf16x2.f32 %0, %1, %2;" : "=r"(d) : "f"(hi), "f"(lo));
    return d;
}
__device__ __forceinline__ void bf16_split(float x, __nv_bfloat16& h, __nv_bfloat16& l) {
    h = __float2bfloat16(x);
    l = __float2bfloat16(x - __bfloat162float(h));
}
__device__ __forceinline__ void split_store2(__nv_bfloat16* ph, __nv_bfloat16* pl,
                                             size_t off, float x, float y) {
    float hx = __bfloat162float(__float2bfloat16(x));
    float hy = __bfloat162float(__float2bfloat16(y));
    *(uint32_t*)(ph + off) = pack_bf16x2(x, y);
    *(uint32_t*)(pl + off) = pack_bf16x2(x - hx, y - hy);
}
__device__ __forceinline__ void split_store4(__nv_bfloat16* ph, __nv_bfloat16* pl,
                                             size_t off, float4 v) {
    split_store2(ph, pl, off, v.x, v.y);
    split_store2(ph, pl, off + 2, v.z, v.w);
}
__device__ __forceinline__ uint32_t smem_u32(const void* p) {
    uint32_t a;
    asm("{ .reg .u64 t; cvta.to.shared.u64 t, %1; cvt.u32.u64 %0, t; }" : "=r"(a) : "l"(p));
    return a;
}
__device__ __forceinline__ void cp16(uint32_t dst, const void* src) {
    asm volatile("cp.async.cg.shared.global [%0], [%1], 16;" :: "r"(dst), "l"(src));
}
#define CP_COMMIT() asm volatile("cp.async.commit_group;" ::: "memory")
#define CP_WAIT(n)  asm volatile("cp.async.wait_group %0;" :: "n"(n) : "memory")

__device__ __forceinline__ void ldm4u(uint32_t r[4], uint32_t saddr) {
    asm volatile("ldmatrix.sync.aligned.m8n8.x4.shared.b16 {%0,%1,%2,%3}, [%4];\n"
                 : "=r"(r[0]), "=r"(r[1]), "=r"(r[2]), "=r"(r[3]) : "r"(saddr));
}
__device__ __forceinline__ void ldm_x4(uint32_t r[4], const __nv_bfloat16* p) {
    ldm4u(r, smem_u32(p));
}
__device__ __forceinline__ void ldm_x4_trans(uint32_t r[4], const __nv_bfloat16* p) {
    uint32_t a = smem_u32(p);
    asm volatile("ldmatrix.sync.aligned.m8n8.x4.trans.shared.b16 {%0,%1,%2,%3}, [%4];\n"
                 : "=r"(r[0]), "=r"(r[1]), "=r"(r[2]), "=r"(r[3]) : "r"(a));
}
__device__ __forceinline__ void mma16816(float d[4], const uint32_t a[4],
                                         uint32_t b0, uint32_t b1) {
    asm volatile("mma.sync.aligned.m16n8k16.row.col.f32.bf16.bf16.f32 "
        "{%0,%1,%2,%3}, {%4,%5,%6,%7}, {%8,%9}, {%0,%1,%2,%3};\n"
        : "+f"(d[0]), "+f"(d[1]), "+f"(d[2]), "+f"(d[3])
        : "r"(a[0]), "r"(a[1]), "r"(a[2]), "r"(a[3]), "r"(b0), "r"(b1));
}
#define SW128S(o) ((o) ^ (((o) >> 3) & 0x70))

// ---------------- LayerNorm -> bf16 hi/lo planes ----------------------------
__global__ __launch_bounds__(256)
void ln_kernel(const float* __restrict__ x, const float* __restrict__ g,
               const float* __restrict__ b,
               __nv_bfloat16* __restrict__ yh, __nv_bfloat16* __restrict__ yl)
{
    int row  = blockIdx.x * 8 + (threadIdx.x >> 5);
    int lane = threadIdx.x & 31;
    const float4* xr = (const float4*)(x + (size_t)row * Cn);
    float4 a0 = xr[lane], a1 = xr[lane + 32], a2 = xr[lane + 64];

    float s  = a0.x + a0.y + a0.z + a0.w + a1.x + a1.y + a1.z + a1.w
             + a2.x + a2.y + a2.z + a2.w;
    float sq = dot4(a0, a0) + dot4(a1, a1) + dot4(a2, a2);
    #pragma unroll
    for (int off = 16; off; off >>= 1) {
        s  += __shfl_xor_sync(0xffffffffu, s,  off);
        sq += __shfl_xor_sync(0xffffffffu, sq, off);
    }
    const float inv = 1.0f / (float)Cn;
    float mu  = s * inv;
    float var = sq * inv - mu * mu;
    float r   = rsqrtf(var + 1e-5f);

    const float4* g4 = (const float4*)g;
    const float4* b4 = (const float4*)b;
    size_t rb = (size_t)row * Cn;
    #pragma unroll
    for (int seg = 0; seg < 3; seg++) {
        int li = lane + seg * 32;
        float4 a = seg == 0 ? a0 : (seg == 1 ? a1 : a2);
        float4 gv = g4[li], bv = b4[li];
        float4 o;
        o.x = (a.x - mu) * r * gv.x + bv.x;  o.y = (a.y - mu) * r * gv.y + bv.y;
        o.z = (a.z - mu) * r * gv.z + bv.z;  o.w = (a.w - mu) * r * gv.w + bv.w;
        split_store4(yh, yl, rb + li * 4, o);
    }
}

// ---------------- weight prep: transpose to [N][K] + split -----------------
__global__ __launch_bounds__(256)
void pack_t(const float* __restrict__ in, __nv_bfloat16* __restrict__ oh,
            __nv_bfloat16* __restrict__ ol, int K, int N)
{
    int idx = blockIdx.x * 256 + threadIdx.x;
    if (idx >= N * K) return;
    int n = idx / K, k = idx % K;
    float v = in[(size_t)k * N + n];
    __nv_bfloat16 h = __float2bfloat16(v);
    oh[idx] = h;
    ol[idx] = __float2bfloat16(v - __bfloat162float(h));
}

__global__ __launch_bounds__(256)
void pack_qkv_t(const float* __restrict__ Wq, const float* __restrict__ Wk,
                const float* __restrict__ Wv,
                __nv_bfloat16* __restrict__ oh, __nv_bfloat16* __restrict__ ol)
{
    int idx = blockIdx.x * 256 + threadIdx.x;
    if (idx >= QKVN * Cn) return;
    int n = idx / Cn, c = idx % Cn;
    int which = n / Cn;
    int rr = n % Cn;
    int h = rr / HDn, d = rr % HDn;
    const float* W = (which == 0) ? Wq : (which == 1) ? Wk : Wv;
    float v = W[((size_t)h * Cn + c) * HDn + d];
    __nv_bfloat16 hh = __float2bfloat16(v);
    oh[idx] = hh;
    ol[idx] = __float2bfloat16(v - __bfloat162float(hh));
}

// ---------------- mma.sync GEMM v2: 128x64 tile, KC=64, cp.async 2-stage ----
// A planes [M][K] bf16, B planes [N][K] bf16. C row-major [M,N]:
// fp32 (Cf, +bias/+residual) or bf16 planes (Ch/Cl, +bias/+relu).
// Stage layout (48KB): Ah@0 (16K), Al@16384, Bh@32768 (8K), Bl@40960.
#define KC   64
#define STG  49152

__global__ __launch_bounds__(256)
void mma_gemm2(const __nv_bfloat16* __restrict__ Ah, const __nv_bfloat16* __restrict__ Al,
               const __nv_bfloat16* __restrict__ Bh, const __nv_bfloat16* __restrict__ Bl,
               float* __restrict__ Cf,
               __nv_bfloat16* __restrict__ Ch, __nv_bfloat16* __restrict__ Cl,
               const float* __restrict__ bias, const float* __restrict__ residual,
               int relu, int N, int K)
{
    extern __shared__ __align__(1024) char sm[];   // 2 * STG
    const uint32_t sb0 = smem_u32(sm);

    const int tid  = threadIdx.x;
    const int lane = tid & 31;
    const int w    = tid >> 5;
    const int wm   = w & 3;
    const int wn   = w >> 2;
    const int row0 = blockIdx.y * 128;
    const int col0 = blockIdx.x * 64;

    const int r8 = tid >> 3;             // 0..31
    const int u8 = (tid & 7) * 16;       // byte offset within 128B row

    float acc[2][4][4];
    #pragma unroll
    for (int i = 0; i < 2; i++)
        #pragma unroll
        for (int j = 0; j < 4; j++)
            #pragma unroll
            for (int q = 0; q < 4; q++) acc[i][j][q] = 0.f;

    const int nc = K / KC;

    // ---- issue loads for stage c into buffer buf ----
    auto load_stage = [&](int c, int buf) {
        const uint32_t sb = sb0 + buf * STG;
        const int k0 = c * KC;
        #pragma unroll
        for (int i = 0; i < 4; i++) {
            int r = r8 + i * 32;
            size_t go = ((size_t)(row0 + r) * K + k0) * 2 + u8;
            uint32_t so = SW128S((uint32_t)(r * 128 + u8));
            cp16(sb + so,         (const char*)Ah + go);
            cp16(sb + 16384 + so, (const char*)Al + go);
        }
        #pragma unroll
        for (int i = 0; i < 2; i++) {
            int r = r8 + i * 32;
            size_t go = ((size_t)(col0 + r) * K + k0) * 2 + u8;
            uint32_t so = SW128S((uint32_t)(r * 128 + u8));
            cp16(sb + 32768 + so, (const char*)Bh + go);
            cp16(sb + 40960 + so, (const char*)Bl + go);
        }
        CP_COMMIT();
    };

    load_stage(0, 0);

    for (int c = 0; c < nc; c++) {
        const int buf = c & 1;
        if (c + 1 < nc) {
            load_stage(c + 1, buf ^ 1);
            CP_WAIT(1);
        } else {
            CP_WAIT(0);
        }
        __syncthreads();

        const uint32_t sb = sb0 + buf * STG;
        #pragma unroll
        for (int ks = 0; ks < 4; ks++) {
            const uint32_t kb = ks * 32 + 16 * (lane >> 4);
            uint32_t ah[2][4], al[2][4], bh[2][4], bl[2][4];
            #pragma unroll
            for (int i = 0; i < 2; i++) {
                uint32_t off = SW128S((uint32_t)((wm * 32 + i * 16 + (lane & 15)) * 128 + kb));
                ldm4u(ah[i], sb + off);
                ldm4u(al[i], sb + 16384 + off);
            }
            #pragma unroll
            for (int j2 = 0; j2 < 2; j2++) {
                uint32_t off = SW128S((uint32_t)((wn * 32 + j2 * 16 + (lane & 15)) * 128 + kb));
                ldm4u(bh[j2], sb + 32768 + off);
                ldm4u(bl[j2], sb + 40960 + off);
            }
            #pragma unroll
            for (int i = 0; i < 2; i++)
                #pragma unroll
                for (int j = 0; j < 4; j++) {
                    uint32_t b0h = bh[j >> 1][j & 1], b1h = bh[j >> 1][(j & 1) + 2];
                    uint32_t b0l = bl[j >> 1][j & 1], b1l = bl[j >> 1][(j & 1) + 2];
                    mma16816(acc[i][j], ah[i], b0h, b1h);
                    mma16816(acc[i][j], al[i], b0h, b1h);
                    mma16816(acc[i][j], ah[i], b0l, b1l);
                }
        }
        __syncthreads();
    }

    // ---- epilogue ----
    #pragma unroll
    for (int i = 0; i < 2; i++) {
        #pragma unroll
        for (int j = 0; j < 4; j++) {
            int rb = row0 + wm * 32 + i * 16 + (lane >> 2);
            int cc = col0 + wn * 32 + j * 8 + (lane & 3) * 2;
            #pragma unroll
            for (int hh = 0; hh < 2; hh++) {
                int r = rb + 8 * hh;
                float vx = acc[i][j][2 * hh], vy = acc[i][j][2 * hh + 1];
                if (bias) { vx += bias[cc]; vy += bias[cc + 1]; }
                if (Cf) {
                    if (residual) {
                        float2 rr = *(const float2*)(residual + (size_t)r * N + cc);
                        vx += rr.x; vy += rr.y;
                    }
                    *(float2*)(Cf + (size_t)r * N + cc) = make_float2(vx, vy);
                } else {
                    if (relu) { vx = fmaxf(vx, 0.f); vy = fmaxf(vy, 0.f); }
                    split_store2(Ch, Cl, (size_t)r * N + cc, vx, vy);
                }
            }
        }
    }
}

// ---------------- flash attention (mma.sync, bf16 3-term split) ------------
#define PF 136

__global__ __launch_bounds__(256)
void attn_flash(const float* __restrict__ QKV,
                __nv_bfloat16* __restrict__ Oh, __nv_bfloat16* __restrict__ Ol)
{
    __shared__ __nv_bfloat16 smf[128 * PF];

    const int tid  = threadIdx.x;
    const int lane = tid & 31;
    const int w    = tid >> 5;
    const int qt = blockIdx.x;
    const int h  = blockIdx.y;
    const int b  = blockIdx.z;
    const float* base = QKV + (size_t)b * Tn * QKVN;

    #pragma unroll
    for (int it = 0; it < 8; it++) {
        int f = tid + it * 256;
        int row = f >> 4, c4 = (f & 15) * 4;
        float4 v = *(const float4*)(base + (size_t)(qt * 128 + row) * QKVN + h * HDn + c4);
        v.x *= 0.125f; v.y *= 0.125f; v.z *= 0.125f; v.w *= 0.125f;
        __nv_bfloat16 h0,l0,h1,l1,h2,l2,h3,l3;
        bf16_split(v.x, h0, l0); bf16_split(v.y, h1, l1);
        bf16_split(v.z, h2, l2); bf16_split(v.w, h3, l3);
        __nv_bfloat16* d = &smf[row * PF + c4];
        d[0]=h0; d[1]=h1; d[2]=h2; d[3]=h3;
        d[64]=l0; d[65]=l1; d[66]=l2; d[67]=l3;
    }
    __syncthreads();

    uint32_t qh[4][4], ql[4][4];
    #pragma unroll
    for (int ks = 0; ks < 4; ks++) {
        const __nv_bfloat16* p = &smf[(w * 16 + (lane & 15)) * PF + ks * 16 + 8 * (lane >> 4)];
        ldm_x4(qh[ks], p);
        ldm_x4(ql[ks], p + 64);
    }
    __syncthreads();

    float o[8][4];
    #pragma unroll
    for (int j = 0; j < 8; j++)
        #pragma unroll
        for (int q = 0; q < 4; q++) o[j][q] = 0.f;
    float m_old[2] = {-1e30f, -1e30f};
    float l_sum[2] = {0.f, 0.f};

    const int qrow0 = qt * 128 + w * 16 + (lane >> 2);
    const int n_st = 2 * qt + 2;

    for (int st = 0; st < n_st; st++) {
        #pragma unroll
        for (int it = 0; it < 4; it++) {
            int f = tid + it * 256;
            int row = f >> 4, c4 = (f & 15) * 4;
            float4 kv = *(const float4*)(base + (size_t)(st * 64 + row) * QKVN + Cn + h * HDn + c4);
            float4 vv = *(const float4*)(base + (size_t)(st * 64 + row) * QKVN + 2 * Cn + h * HDn + c4);
            __nv_bfloat16 h0,l0,h1,l1,h2,l2,h3,l3;
            bf16_split(kv.x, h0, l0); bf16_split(kv.y, h1, l1);
            bf16_split(kv.z, h2, l2); bf16_split(kv.w, h3, l3);
            __nv_bfloat16* d = &smf[row * PF + c4];
            d[0]=h0; d[1]=h1; d[2]=h2; d[3]=h3;
            d[64]=l0; d[65]=l1; d[66]=l2; d[67]=l3;
            bf16_split(vv.x, h0, l0); bf16_split(vv.y, h1, l1);
            bf16_split(vv.z, h2, l2); bf16_split(vv.w, h3, l3);
            d = &smf[(64 + row) * PF + c4];
            d[0]=h0; d[1]=h1; d[2]=h2; d[3]=h3;
            d[64]=l0; d[65]=l1; d[66]=l2; d[67]=l3;
        }
        __syncthreads();

        float s[8][4];
        #pragma unroll
        for (int j = 0; j < 8; j++)
            #pragma unroll
            for (int q = 0; q < 4; q++) s[j][q] = 0.f;

        #pragma unroll
        for (int ks = 0; ks < 4; ks++) {
            #pragma unroll
            for (int g = 0; g < 4; g++) {
                uint32_t kh4[4], kl4[4];
                const __nv_bfloat16* p =
                    &smf[(g * 16 + (lane & 15)) * PF + ks * 16 + 8 * (lane >> 4)];
                ldm_x4(kh4, p);
                ldm_x4(kl4, p + 64);
                #pragma unroll
                for (int j = 0; j < 2; j++) {
                    int jj = g * 2 + j;
                    mma16816(s[jj], qh[ks], kh4[j], kh4[j + 2]);
                    mma16816(s[jj], ql[ks], kh4[j], kh4[j + 2]);
                    mma16816(s[jj], qh[ks], kl4[j], kl4[j + 2]);
                }
            }
        }

        float m_tile[2] = {-1e30f, -1e30f};
        #pragma unroll
        for (int j = 0; j < 8; j++) {
            #pragma unroll
            for (int q = 0; q < 4; q++) {
                int scol = st * 64 + j * 8 + 2 * (lane & 3) + (q & 1);
                int qrow = qrow0 + 8 * (q >> 1);
                if (scol > qrow) s[j][q] = -1e30f;
                m_tile[q >> 1] = fmaxf(m_tile[q >> 1], s[j][q]);
            }
        }
        #pragma unroll
        for (int r = 0; r < 2; r++) {
            m_tile[r] = fmaxf(m_tile[r], __shfl_xor_sync(0xffffffffu, m_tile[r], 1));
            m_tile[r] = fmaxf(m_tile[r], __shfl_xor_sync(0xffffffffu, m_tile[r], 2));
        }
        float m_new[2], fscale[2], rsum[2] = {0.f, 0.f};
        #pragma unroll
        for (int r = 0; r < 2; r++) {
            m_new[r] = fmaxf(m_old[r], m_tile[r]);
            fscale[r] = __expf(m_old[r] - m_new[r]);
        }
        #pragma unroll
        for (int j = 0; j < 8; j++) {
            #pragma unroll
            for (int q = 0; q < 4; q++) {
                float p = __expf(s[j][q] - m_new[q >> 1]);
                s[j][q] = p;
                rsum[q >> 1] += p;
            }
        }
        #pragma unroll
        for (int r = 0; r < 2; r++) {
            rsum[r] += __shfl_xor_sync(0xffffffffu, rsum[r], 1);
            rsum[r] += __shfl_xor_sync(0xffffffffu, rsum[r], 2);
            l_sum[r] = l_sum[r] * fscale[r] + rsum[r];
            m_old[r] = m_new[r];
        }
        #pragma unroll
        for (int j = 0; j < 8; j++) {
            o[j][0] *= fscale[0]; o[j][1] *= fscale[0];
            o[j][2] *= fscale[1]; o[j][3] *= fscale[1];
        }

        #pragma unroll
        for (int ks = 0; ks < 4; ks++) {
            float p00 = s[2*ks][0],   p01 = s[2*ks][1],   p02 = s[2*ks][2],   p03 = s[2*ks][3];
            float p10 = s[2*ks+1][0], p11 = s[2*ks+1][1], p12 = s[2*ks+1][2], p13 = s[2*ks+1][3];
            uint32_t pah[4], pal[4];
            pah[0] = pack_bf16x2(p00, p01);
            pah[1] = pack_bf16x2(p02, p03);
            pah[2] = pack_bf16x2(p10, p11);
            pah[3] = pack_bf16x2(p12, p13);
            float r00 = p00 - __bfloat162float(__float2bfloat16(p00));
            float r01 = p01 - __bfloat162float(__float2bfloat16(p01));
            float r02 = p02 - __bfloat162float(__float2bfloat16(p02));
            float r03 = p03 - __bfloat162float(__float2bfloat16(p03));
            float r10 = p10 - __bfloat162float(__float2bfloat16(p10));
            float r11 = p11 - __bfloat162float(__float2bfloat16(p11));
            float r12 = p12 - __bfloat162float(__float2bfloat16(p12));
            float r13 = p13 - __bfloat162float(__float2bfloat16(p13));
            pal[0] = pack_bf16x2(r00, r01);
            pal[1] = pack_bf16x2(r02, r03);
            pal[2] = pack_bf16x2(r10, r11);
            pal[3] = pack_bf16x2(r12, r13);

            #pragma unroll
            for (int g = 0; g < 4; g++) {
                uint32_t vh4[4], vl4[4];
                const __nv_bfloat16* p =
                    &smf[(64 + ks * 16 + (lane & 15)) * PF + g * 16 + 8 * (lane >> 4)];
                ldm_x4_trans(vh4, p);
                ldm_x4_trans(vl4, p + 64);
                #pragma unroll
                for (int j = 0; j < 2; j++) {
                    int dd = g * 2 + j;
                    mma16816(o[dd], pah, vh4[j * 2], vh4[j * 2 + 1]);
                    mma16816(o[dd], pal, vh4[j * 2], vh4[j * 2 + 1]);
                    mma16816(o[dd], pah, vl4[j * 2], vl4[j * 2 + 1]);
                }
            }
        }
        __syncthreads();
    }

    float inv0 = 1.0f / l_sum[0];
    float inv1 = 1.0f / l_sum[1];
    #pragma unroll
    for (int j = 0; j < 8; j++) {
        int col = h * HDn + j * 8 + 2 * (lane & 3);
        #pragma unroll
        for (int r = 0; r < 2; r++) {
            int row = b * Tn + qrow0 + 8 * r;
            float inv = r ? inv1 : inv0;
            split_store2(Oh, Ol, (size_t)row * Cn + col,
                         o[j][2 * r] * inv, o[j][2 * r + 1] * inv);
        }
    }
}

// ---------------- launch ---------------------------------------------------
extern "C" void kernel_launch(void* const* d_in, const int* in_sizes, int n_in,
                              void* d_out, int out_size)
{
    const float* x     = (const float*)d_in[0];
    const float* ln1_g = (const float*)d_in[1];
    const float* ln1_b = (const float*)d_in[2];
    const float* Wq    = (const float*)d_in[3];
    const float* Wk    = (const float*)d_in[4];
    const float* Wv    = (const float*)d_in[5];
    const float* Wo    = (const float*)d_in[6];
    const float* bo    = (const float*)d_in[7];
    const float* ln2_g = (const float*)d_in[8];
    const float* ln2_b = (const float*)d_in[9];
    const float* W1    = (const float*)d_in[10];
    const float* b1    = (const float*)d_in[11];
    const float* W2    = (const float*)d_in[12];
    const float* b2    = (const float*)d_in[13];
    float* out = (float*)d_out;

    cudaFuncSetAttribute(mma_gemm2, cudaFuncAttributeMaxDynamicSharedMemorySize, 2 * STG);

    void *p;
    cudaGetSymbolAddress(&p, g_qkv);   float* qkv = (float*)p;
    cudaGetSymbolAddress(&p, g_x1h);   __nv_bfloat16* x1h = (__nv_bfloat16*)p;
    cudaGetSymbolAddress(&p, g_x1l);   __nv_bfloat16* x1l = (__nv_bfloat16*)p;
    cudaGetSymbolAddress(&p, g_ath);   __nv_bfloat16* ath = (__nv_bfloat16*)p;
    cudaGetSymbolAddress(&p, g_atl);   __nv_bfloat16* atl = (__nv_bfloat16*)p;
    cudaGetSymbolAddress(&p, g_hidh);  __nv_bfloat16* hidh = (__nv_bfloat16*)p;
    cudaGetSymbolAddress(&p, g_hidl);  __nv_bfloat16* hidl = (__nv_bfloat16*)p;
    cudaGetSymbolAddress(&p, g_wqkvh); __nv_bfloat16* wqkvh = (__nv_bfloat16*)p;
    cudaGetSymbolAddress(&p, g_wqkvl); __nv_bfloat16* wqkvl = (__nv_bfloat16*)p;
    cudaGetSymbolAddress(&p, g_woth);  __nv_bfloat16* woth = (__nv_bfloat16*)p;
    cudaGetSymbolAddress(&p, g_wotl);  __nv_bfloat16* wotl = (__nv_bfloat16*)p;
    cudaGetSymbolAddress(&p, g_w1th);  __nv_bfloat16* w1th = (__nv_bfloat16*)p;
    cudaGetSymbolAddress(&p, g_w1tl);  __nv_bfloat16* w1tl = (__nv_bfloat16*)p;
    cudaGetSymbolAddress(&p, g_w2th);  __nv_bfloat16* w2th = (__nv_bfloat16*)p;
    cudaGetSymbolAddress(&p, g_w2tl);  __nv_bfloat16* w2tl = (__nv_bfloat16*)p;

    // weight prep (transpose + split)
    pack_qkv_t<<<(QKVN * Cn + 255) / 256, 256>>>(Wq, Wk, Wv, wqkvh, wqkvl);
    pack_t<<<(Cn * Cn + 255) / 256, 256>>>(Wo, woth, wotl, Cn, Cn);
    pack_t<<<(Cn * FF + 255) / 256, 256>>>(W1, w1th, w1tl, Cn, FF);
    pack_t<<<(FF * Cn + 255) / 256, 256>>>(W2, w2th, w2tl, FF, Cn);

    // LN1 -> planes
    ln_kernel<<<BT / 8, 256>>>(x, ln1_g, ln1_b, x1h, x1l);
    // QKV: [BT,384] x [1152,384]^T -> fp32 qkv
    mma_gemm2<<<dim3(QKVN / 64, BT / 128), 256, 2 * STG>>>(
        x1h, x1l, wqkvh, wqkvl, qkv, nullptr, nullptr, nullptr, nullptr, 0, QKVN, Cn);
    // causal flash attention -> planes
    attn_flash<<<dim3(2, Hn, Bn), 256>>>(qkv, ath, atl);
    // Wo + bias + residual(x) -> d_out (fp32)
    mma_gemm2<<<dim3(Cn / 64, BT / 128), 256, 2 * STG>>>(
        ath, atl, woth, wotl, out, nullptr, nullptr, bo, x, 0, Cn, Cn);
    // LN2 -> planes
    ln_kernel<<<BT / 8, 256>>>(out, ln2_g, ln2_b, x1h, x1l);
    // FFN1: relu(x2 @ W1 + b1) -> planes
    mma_gemm2<<<dim3(FF / 64, BT / 128), 256, 2 * STG>>>(
        x1h, x1l, w1th, w1tl, nullptr, hidh, hidl, b1, nullptr, 1, FF, Cn);
    // FFN2: d_out += hid @ W2 + b2
    mma_gemm2<<<dim3(Cn / 64, BT / 128), 256, 2 * STG>>>(
        hidh, hidl, w2th, w2tl, out, nullptr, nullptr, b2, out, 0, Cn, FF);
}

// round 7
// speedup vs baseline: 4.1570x; 1.2846x over previous
#include <cuda_runtime.h>
#include <cuda_fp16.h>
#include <math.h>
#include <stdint.h>

#define Bn  128
#define Tn  256
#define Cn  384
#define Hn  6
#define HDn 64
#define BT  (Bn * Tn)
#define FF  (4 * Cn)
#define QKVN (3 * Cn)   // 1152

// ---------------- scratch (device globals; allocation-free) ----------------
__device__ __align__(16) float g_qkv[(size_t)BT * QKVN];
__device__ __align__(16) __half g_x1h [(size_t)BT * Cn];
__device__ __align__(16) __half g_x1l [(size_t)BT * Cn];
__device__ __align__(16) __half g_ath [(size_t)BT * Cn];
__device__ __align__(16) __half g_atl [(size_t)BT * Cn];
__device__ __align__(16) __half g_hidh[(size_t)BT * FF];
__device__ __align__(16) __half g_hidl[(size_t)BT * FF];
__device__ __align__(16) __half g_wqkvh[(size_t)QKVN * Cn];  // [1152][384] hi only
__device__ __align__(16) __half g_woth [(size_t)Cn * Cn];
__device__ __align__(16) __half g_w1th [(size_t)FF * Cn];
__device__ __align__(16) __half g_w2th [(size_t)Cn * FF];

// ---------------- helpers ---------------------------------------------------
__device__ __forceinline__ float dot4(const float4 a, const float4 b) {
    return a.x * b.x + a.y * b.y + a.z * b.z + a.w * b.w;
}
__device__ __forceinline__ uint32_t pack_f16x2(float lo, float hi) {
    uint32_t d;
    asm("cvt.rn.f16x2.f32 %0, %1, %2;" : "=r"(d) : "f"(hi), "f"(lo));
    return d;
}
__device__ __forceinline__ void split_store2(__half* ph, __half* pl,
                                             size_t off, float x, float y) {
    float hx = __half2float(__float2half_rn(x));
    float hy = __half2float(__float2half_rn(y));
    *(uint32_t*)(ph + off) = pack_f16x2(x, y);
    *(uint32_t*)(pl + off) = pack_f16x2(x - hx, y - hy);
}
__device__ __forceinline__ void split_store4(__half* ph, __half* pl,
                                             size_t off, float4 v) {
    split_store2(ph, pl, off, v.x, v.y);
    split_store2(ph, pl, off + 2, v.z, v.w);
}
__device__ __forceinline__ uint32_t smem_u32(const void* p) {
    uint32_t a;
    asm("{ .reg .u64 t; cvta.to.shared.u64 t, %1; cvt.u32.u64 %0, t; }" : "=r"(a) : "l"(p));
    return a;
}
__device__ __forceinline__ void cp16(uint32_t dst, const void* src) {
    asm volatile("cp.async.cg.shared.global [%0], [%1], 16;" :: "r"(dst), "l"(src));
}
#define CP_COMMIT() asm volatile("cp.async.commit_group;" ::: "memory")
#define CP_WAIT(n)  asm volatile("cp.async.wait_group %0;" :: "n"(n) : "memory")

__device__ __forceinline__ void ldm4u(uint32_t r[4], uint32_t saddr) {
    asm volatile("ldmatrix.sync.aligned.m8n8.x4.shared.b16 {%0,%1,%2,%3}, [%4];\n"
                 : "=r"(r[0]), "=r"(r[1]), "=r"(r[2]), "=r"(r[3]) : "r"(saddr));
}
__device__ __forceinline__ void ldm_x4(uint32_t r[4], const __half* p) {
    ldm4u(r, smem_u32(p));
}
__device__ __forceinline__ void ldm_x4_trans(uint32_t r[4], const __half* p) {
    uint32_t a = smem_u32(p);
    asm volatile("ldmatrix.sync.aligned.m8n8.x4.trans.shared.b16 {%0,%1,%2,%3}, [%4];\n"
                 : "=r"(r[0]), "=r"(r[1]), "=r"(r[2]), "=r"(r[3]) : "r"(a));
}
__device__ __forceinline__ void mma16816(float d[4], const uint32_t a[4],
                                         uint32_t b0, uint32_t b1) {
    asm volatile("mma.sync.aligned.m16n8k16.row.col.f32.f16.f16.f32 "
        "{%0,%1,%2,%3}, {%4,%5,%6,%7}, {%8,%9}, {%0,%1,%2,%3};\n"
        : "+f"(d[0]), "+f"(d[1]), "+f"(d[2]), "+f"(d[3])
        : "r"(a[0]), "r"(a[1]), "r"(a[2]), "r"(a[3]), "r"(b0), "r"(b1));
}
#define SW128S(o) ((o) ^ (((o) >> 3) & 0x70))

// ---------------- LayerNorm -> fp16 hi/lo planes ----------------------------
__global__ __launch_bounds__(256)
void ln_kernel(const float* __restrict__ x, const float* __restrict__ g,
               const float* __restrict__ b,
               __half* __restrict__ yh, __half* __restrict__ yl)
{
    int row  = blockIdx.x * 8 + (threadIdx.x >> 5);
    int lane = threadIdx.x & 31;
    const float4* xr = (const float4*)(x + (size_t)row * Cn);
    float4 a0 = xr[lane], a1 = xr[lane + 32], a2 = xr[lane + 64];

    float s  = a0.x + a0.y + a0.z + a0.w + a1.x + a1.y + a1.z + a1.w
             + a2.x + a2.y + a2.z + a2.w;
    float sq = dot4(a0, a0) + dot4(a1, a1) + dot4(a2, a2);
    #pragma unroll
    for (int off = 16; off; off >>= 1) {
        s  += __shfl_xor_sync(0xffffffffu, s,  off);
        sq += __shfl_xor_sync(0xffffffffu, sq, off);
    }
    const float inv = 1.0f / (float)Cn;
    float mu  = s * inv;
    float var = sq * inv - mu * mu;
    float r   = rsqrtf(var + 1e-5f);

    const float4* g4 = (const float4*)g;
    const float4* b4 = (const float4*)b;
    size_t rb = (size_t)row * Cn;
    #pragma unroll
    for (int seg = 0; seg < 3; seg++) {
        int li = lane + seg * 32;
        float4 a = seg == 0 ? a0 : (seg == 1 ? a1 : a2);
        float4 gv = g4[li], bv = b4[li];
        float4 o;
        o.x = (a.x - mu) * r * gv.x + bv.x;  o.y = (a.y - mu) * r * gv.y + bv.y;
        o.z = (a.z - mu) * r * gv.z + bv.z;  o.w = (a.w - mu) * r * gv.w + bv.w;
        split_store4(yh, yl, rb + li * 4, o);
    }
}

// ---------------- weight prep: transpose to [N][K], hi plane only ----------
__global__ __launch_bounds__(256)
void pack_t(const float* __restrict__ in, __half* __restrict__ oh, int K, int N)
{
    int idx = blockIdx.x * 256 + threadIdx.x;
    if (idx >= N * K) return;
    int n = idx / K, k = idx % K;
    oh[idx] = __float2half_rn(in[(size_t)k * N + n]);
}

__global__ __launch_bounds__(256)
void pack_qkv_t(const float* __restrict__ Wq, const float* __restrict__ Wk,
                const float* __restrict__ Wv, __half* __restrict__ oh)
{
    int idx = blockIdx.x * 256 + threadIdx.x;
    if (idx >= QKVN * Cn) return;
    int n = idx / Cn, c = idx % Cn;
    int which = n / Cn;
    int rr = n % Cn;
    int h = rr / HDn, d = rr % HDn;
    const float* W = (which == 0) ? Wq : (which == 1) ? Wk : Wv;
    oh[idx] = __float2half_rn(W[((size_t)h * Cn + c) * HDn + d]);
}

// ---------------- mma.sync GEMM: 128x64 tile, KC=64, fp16 2-term split -----
// A planes [M][K] fp16 hi+lo, B plane [N][K] fp16 hi.
// Stage layout (40KB): Ah@0 (16K), Al@16384, Bh@32768 (8K).
#define KC   64
#define STG  40960

__global__ __launch_bounds__(256)
void mma_gemm2(const __half* __restrict__ Ah, const __half* __restrict__ Al,
               const __half* __restrict__ Bh,
               float* __restrict__ Cf,
               __half* __restrict__ Ch, __half* __restrict__ Cl,
               const float* __restrict__ bias, const float* __restrict__ residual,
               int relu, int N, int K)
{
    extern __shared__ __align__(1024) char sm[];   // 2 * STG
    const uint32_t sb0 = smem_u32(sm);

    const int tid  = threadIdx.x;
    const int lane = tid & 31;
    const int w    = tid >> 5;
    const int wm   = w & 3;
    const int wn   = w >> 2;
    const int row0 = blockIdx.y * 128;
    const int col0 = blockIdx.x * 64;

    const int r8 = tid >> 3;             // 0..31
    const int u8 = (tid & 7) * 16;       // byte offset within 128B row

    float acc[2][4][4];
    #pragma unroll
    for (int i = 0; i < 2; i++)
        #pragma unroll
        for (int j = 0; j < 4; j++)
            #pragma unroll
            for (int q = 0; q < 4; q++) acc[i][j][q] = 0.f;

    const int nc = K / KC;

    auto load_stage = [&](int c, int buf) {
        const uint32_t sb = sb0 + buf * STG;
        const int k0 = c * KC;
        #pragma unroll
        for (int i = 0; i < 4; i++) {
            int r = r8 + i * 32;
            size_t go = ((size_t)(row0 + r) * K + k0) * 2 + u8;
            uint32_t so = SW128S((uint32_t)(r * 128 + u8));
            cp16(sb + so,         (const char*)Ah + go);
            cp16(sb + 16384 + so, (const char*)Al + go);
        }
        #pragma unroll
        for (int i = 0; i < 2; i++) {
            int r = r8 + i * 32;
            size_t go = ((size_t)(col0 + r) * K + k0) * 2 + u8;
            uint32_t so = SW128S((uint32_t)(r * 128 + u8));
            cp16(sb + 32768 + so, (const char*)Bh + go);
        }
        CP_COMMIT();
    };

    load_stage(0, 0);

    for (int c = 0; c < nc; c++) {
        const int buf = c & 1;
        if (c + 1 < nc) {
            load_stage(c + 1, buf ^ 1);
            CP_WAIT(1);
        } else {
            CP_WAIT(0);
        }
        __syncthreads();

        const uint32_t sb = sb0 + buf * STG;
        #pragma unroll
        for (int ks = 0; ks < 4; ks++) {
            const uint32_t kb = ks * 32 + 16 * (lane >> 4);
            uint32_t ah[2][4], al[2][4], bh[2][4];
            #pragma unroll
            for (int i = 0; i < 2; i++) {
                uint32_t off = SW128S((uint32_t)((wm * 32 + i * 16 + (lane & 15)) * 128 + kb));
                ldm4u(ah[i], sb + off);
                ldm4u(al[i], sb + 16384 + off);
            }
            #pragma unroll
            for (int j2 = 0; j2 < 2; j2++) {
                uint32_t off = SW128S((uint32_t)((wn * 32 + j2 * 16 + (lane & 15)) * 128 + kb));
                ldm4u(bh[j2], sb + 32768 + off);
            }
            #pragma unroll
            for (int i = 0; i < 2; i++)
                #pragma unroll
                for (int j = 0; j < 4; j++) {
                    uint32_t b0h = bh[j >> 1][j & 1], b1h = bh[j >> 1][(j & 1) + 2];
                    mma16816(acc[i][j], ah[i], b0h, b1h);
                    mma16816(acc[i][j], al[i], b0h, b1h);
                }
        }
        __syncthreads();
    }

    // ---- epilogue ----
    #pragma unroll
    for (int i = 0; i < 2; i++) {
        #pragma unroll
        for (int j = 0; j < 4; j++) {
            int rb = row0 + wm * 32 + i * 16 + (lane >> 2);
            int cc = col0 + wn * 32 + j * 8 + (lane & 3) * 2;
            #pragma unroll
            for (int hh = 0; hh < 2; hh++) {
                int r = rb + 8 * hh;
                float vx = acc[i][j][2 * hh], vy = acc[i][j][2 * hh + 1];
                if (bias) { vx += bias[cc]; vy += bias[cc + 1]; }
                if (Cf) {
                    if (residual) {
                        float2 rr = *(const float2*)(residual + (size_t)r * N + cc);
                        vx += rr.x; vy += rr.y;
                    }
                    *(float2*)(Cf + (size_t)r * N + cc) = make_float2(vx, vy);
                } else {
                    if (relu) { vx = fmaxf(vx, 0.f); vy = fmaxf(vy, 0.f); }
                    split_store2(Ch, Cl, (size_t)r * N + cc, vx, vy);
                }
            }
        }
    }
}

// ---------------- flash attention (mma.sync, fp16 2-term split) ------------
// smem: Q staged hi[0,64)/lo[64,128) pitch 136; then K hi rows 0-63,
// V hi rows 64-127 (cols [0,64) of same buffer).
#define PF 136

__global__ __launch_bounds__(256)
void attn_flash(const float* __restrict__ QKV,
                __half* __restrict__ Oh, __half* __restrict__ Ol)
{
    __shared__ __half smf[128 * PF];

    const int tid  = threadIdx.x;
    const int lane = tid & 31;
    const int w    = tid >> 5;
    const int qt = blockIdx.x;
    const int h  = blockIdx.y;
    const int b  = blockIdx.z;
    const float* base = QKV + (size_t)b * Tn * QKVN;

    // ---- stage Q (x0.125, exact) hi/lo ----
    #pragma unroll
    for (int it = 0; it < 8; it++) {
        int f = tid + it * 256;
        int row = f >> 4, c4 = (f & 15) * 4;
        float4 v = *(const float4*)(base + (size_t)(qt * 128 + row) * QKVN + h * HDn + c4);
        v.x *= 0.125f; v.y *= 0.125f; v.z *= 0.125f; v.w *= 0.125f;
        float hx = __half2float(__float2half_rn(v.x));
        float hy = __half2float(__float2half_rn(v.y));
        float hz = __half2float(__float2half_rn(v.z));
        float hw = __half2float(__float2half_rn(v.w));
        __half* d = &smf[row * PF + c4];
        *(uint32_t*)(d)      = pack_f16x2(v.x, v.y);
        *(uint32_t*)(d + 2)  = pack_f16x2(v.z, v.w);
        *(uint32_t*)(d + 64) = pack_f16x2(v.x - hx, v.y - hy);
        *(uint32_t*)(d + 66) = pack_f16x2(v.z - hz, v.w - hw);
    }
    __syncthreads();

    uint32_t qh[4][4], ql[4][4];
    #pragma unroll
    for (int ks = 0; ks < 4; ks++) {
        const __half* p = &smf[(w * 16 + (lane & 15)) * PF + ks * 16 + 8 * (lane >> 4)];
        ldm_x4(qh[ks], p);
        ldm_x4(ql[ks], p + 64);
    }
    __syncthreads();

    float o[8][4];
    #pragma unroll
    for (int j = 0; j < 8; j++)
        #pragma unroll
        for (int q = 0; q < 4; q++) o[j][q] = 0.f;
    float m_old[2] = {-1e30f, -1e30f};
    float l_sum[2] = {0.f, 0.f};

    const int qrow0 = qt * 128 + w * 16 + (lane >> 2);
    const int n_st = 2 * qt + 2;

    for (int st = 0; st < n_st; st++) {
        // ---- load K hi (rows 0-63) and V hi (rows 64-127) ----
        #pragma unroll
        for (int it = 0; it < 4; it++) {
            int f = tid + it * 256;
            int row = f >> 4, c4 = (f & 15) * 4;
            float4 kv = *(const float4*)(base + (size_t)(st * 64 + row) * QKVN + Cn + h * HDn + c4);
            float4 vv = *(const float4*)(base + (size_t)(st * 64 + row) * QKVN + 2 * Cn + h * HDn + c4);
            __half* d = &smf[row * PF + c4];
            *(uint32_t*)(d)     = pack_f16x2(kv.x, kv.y);
            *(uint32_t*)(d + 2) = pack_f16x2(kv.z, kv.w);
            d = &smf[(64 + row) * PF + c4];
            *(uint32_t*)(d)     = pack_f16x2(vv.x, vv.y);
            *(uint32_t*)(d + 2) = pack_f16x2(vv.z, vv.w);
        }
        __syncthreads();

        // ---- S = Qh K^T + Ql K^T ----
        float s[8][4];
        #pragma unroll
        for (int j = 0; j < 8; j++)
            #pragma unroll
            for (int q = 0; q < 4; q++) s[j][q] = 0.f;

        #pragma unroll
        for (int ks = 0; ks < 4; ks++) {
            #pragma unroll
            for (int g = 0; g < 4; g++) {
                uint32_t kh4[4];
                const __half* p =
                    &smf[(g * 16 + (lane & 15)) * PF + ks * 16 + 8 * (lane >> 4)];
                ldm_x4(kh4, p);
                #pragma unroll
                for (int j = 0; j < 2; j++) {
                    int jj = g * 2 + j;
                    mma16816(s[jj], qh[ks], kh4[j], kh4[j + 2]);
                    mma16816(s[jj], ql[ks], kh4[j], kh4[j + 2]);
                }
            }
        }

        // ---- causal mask + online softmax ----
        float m_tile[2] = {-1e30f, -1e30f};
        #pragma unroll
        for (int j = 0; j < 8; j++) {
            #pragma unroll
            for (int q = 0; q < 4; q++) {
                int scol = st * 64 + j * 8 + 2 * (lane & 3) + (q & 1);
                int qrow = qrow0 + 8 * (q >> 1);
                if (scol > qrow) s[j][q] = -1e30f;
                m_tile[q >> 1] = fmaxf(m_tile[q >> 1], s[j][q]);
            }
        }
        #pragma unroll
        for (int r = 0; r < 2; r++) {
            m_tile[r] = fmaxf(m_tile[r], __shfl_xor_sync(0xffffffffu, m_tile[r], 1));
            m_tile[r] = fmaxf(m_tile[r], __shfl_xor_sync(0xffffffffu, m_tile[r], 2));
        }
        float m_new[2], fscale[2], rsum[2] = {0.f, 0.f};
        #pragma unroll
        for (int r = 0; r < 2; r++) {
            m_new[r] = fmaxf(m_old[r], m_tile[r]);
            fscale[r] = __expf(m_old[r] - m_new[r]);
        }
        #pragma unroll
        for (int j = 0; j < 8; j++) {
            #pragma unroll
            for (int q = 0; q < 4; q++) {
                float p = __expf(s[j][q] - m_new[q >> 1]);
                s[j][q] = p;
                rsum[q >> 1] += p;
            }
        }
        #pragma unroll
        for (int r = 0; r < 2; r++) {
            rsum[r] += __shfl_xor_sync(0xffffffffu, rsum[r], 1);
            rsum[r] += __shfl_xor_sync(0xffffffffu, rsum[r], 2);
            l_sum[r] = l_sum[r] * fscale[r] + rsum[r];
            m_old[r] = m_new[r];
        }
        #pragma unroll
        for (int j = 0; j < 8; j++) {
            o[j][0] *= fscale[0]; o[j][1] *= fscale[0];
            o[j][2] *= fscale[1]; o[j][3] *= fscale[1];
        }

        // ---- O += Ph V + Pl V ----
        #pragma unroll
        for (int ks = 0; ks < 4; ks++) {
            float p00 = s[2*ks][0],   p01 = s[2*ks][1],   p02 = s[2*ks][2],   p03 = s[2*ks][3];
            float p10 = s[2*ks+1][0], p11 = s[2*ks+1][1], p12 = s[2*ks+1][2], p13 = s[2*ks+1][3];
            uint32_t pah[4], pal[4];
            pah[0] = pack_f16x2(p00, p01);
            pah[1] = pack_f16x2(p02, p03);
            pah[2] = pack_f16x2(p10, p11);
            pah[3] = pack_f16x2(p12, p13);
            float r00 = p00 - __half2float(__float2half_rn(p00));
            float r01 = p01 - __half2float(__float2half_rn(p01));
            float r02 = p02 - __half2float(__float2half_rn(p02));
            float r03 = p03 - __half2float(__float2half_rn(p03));
            float r10 = p10 - __half2float(__float2half_rn(p10));
            float r11 = p11 - __half2float(__float2half_rn(p11));
            float r12 = p12 - __half2float(__float2half_rn(p12));
            float r13 = p13 - __half2float(__float2half_rn(p13));
            pal[0] = pack_f16x2(r00, r01);
            pal[1] = pack_f16x2(r02, r03);
            pal[2] = pack_f16x2(r10, r11);
            pal[3] = pack_f16x2(r12, r13);

            #pragma unroll
            for (int g = 0; g < 4; g++) {
                uint32_t vh4[4];
                const __half* p =
                    &smf[(64 + ks * 16 + (lane & 15)) * PF + g * 16 + 8 * (lane >> 4)];
                ldm_x4_trans(vh4, p);
                #pragma unroll
                for (int j = 0; j < 2; j++) {
                    int dd = g * 2 + j;
                    mma16816(o[dd], pah, vh4[j * 2], vh4[j * 2 + 1]);
                    mma16816(o[dd], pal, vh4[j * 2], vh4[j * 2 + 1]);
                }
            }
        }
        __syncthreads();
    }

    float inv0 = 1.0f / l_sum[0];
    float inv1 = 1.0f / l_sum[1];
    #pragma unroll
    for (int j = 0; j < 8; j++) {
        int col = h * HDn + j * 8 + 2 * (lane & 3);
        #pragma unroll
        for (int r = 0; r < 2; r++) {
            int row = b * Tn + qrow0 + 8 * r;
            float inv = r ? inv1 : inv0;
            split_store2(Oh, Ol, (size_t)row * Cn + col,
                         o[j][2 * r] * inv, o[j][2 * r + 1] * inv);
        }
    }
}

// ---------------- launch ---------------------------------------------------
extern "C" void kernel_launch(void* const* d_in, const int* in_sizes, int n_in,
                              void* d_out, int out_size)
{
    const float* x     = (const float*)d_in[0];
    const float* ln1_g = (const float*)d_in[1];
    const float* ln1_b = (const float*)d_in[2];
    const float* Wq    = (const float*)d_in[3];
    const float* Wk    = (const float*)d_in[4];
    const float* Wv    = (const float*)d_in[5];
    const float* Wo    = (const float*)d_in[6];
    const float* bo    = (const float*)d_in[7];
    const float* ln2_g = (const float*)d_in[8];
    const float* ln2_b = (const float*)d_in[9];
    const float* W1    = (const float*)d_in[10];
    const float* b1    = (const float*)d_in[11];
    const float* W2    = (const float*)d_in[12];
    const float* b2    = (const float*)d_in[13];
    float* out = (float*)d_out;

    cudaFuncSetAttribute(mma_gemm2, cudaFuncAttributeMaxDynamicSharedMemorySize, 2 * STG);

    void *p;
    cudaGetSymbolAddress(&p, g_qkv);   float* qkv = (float*)p;
    cudaGetSymbolAddress(&p, g_x1h);   __half* x1h = (__half*)p;
    cudaGetSymbolAddress(&p, g_x1l);   __half* x1l = (__half*)p;
    cudaGetSymbolAddress(&p, g_ath);   __half* ath = (__half*)p;
    cudaGetSymbolAddress(&p, g_atl);   __half* atl = (__half*)p;
    cudaGetSymbolAddress(&p, g_hidh);  __half* hidh = (__half*)p;
    cudaGetSymbolAddress(&p, g_hidl);  __half* hidl = (__half*)p;
    cudaGetSymbolAddress(&p, g_wqkvh); __half* wqkvh = (__half*)p;
    cudaGetSymbolAddress(&p, g_woth);  __half* woth = (__half*)p;
    cudaGetSymbolAddress(&p, g_w1th);  __half* w1th = (__half*)p;
    cudaGetSymbolAddress(&p, g_w2th);  __half* w2th = (__half*)p;

    // weight prep (transpose + fp16 hi)
    pack_qkv_t<<<(QKVN * Cn + 255) / 256, 256>>>(Wq, Wk, Wv, wqkvh);
    pack_t<<<(Cn * Cn + 255) / 256, 256>>>(Wo, woth, Cn, Cn);
    pack_t<<<(Cn * FF + 255) / 256, 256>>>(W1, w1th, Cn, FF);
    pack_t<<<(FF * Cn + 255) / 256, 256>>>(W2, w2th, FF, Cn);

    // LN1 -> planes
    ln_kernel<<<BT / 8, 256>>>(x, ln1_g, ln1_b, x1h, x1l);
    // QKV: [BT,384] x [1152,384]^T -> fp32 qkv
    mma_gemm2<<<dim3(QKVN / 64, BT / 128), 256, 2 * STG>>>(
        x1h, x1l, wqkvh, qkv, nullptr, nullptr, nullptr, nullptr, 0, QKVN, Cn);
    // causal flash attention -> planes
    attn_flash<<<dim3(2, Hn, Bn), 256>>>(qkv, ath, atl);
    // Wo + bias + residual(x) -> d_out (fp32)
    mma_gemm2<<<dim3(Cn / 64, BT / 128), 256, 2 * STG>>>(
        ath, atl, woth, out, nullptr, nullptr, bo, x, 0, Cn, Cn);
    // LN2 -> planes
    ln_kernel<<<BT / 8, 256>>>(out, ln2_g, ln2_b, x1h, x1l);
    // FFN1: relu(x2 @ W1 + b1) -> planes
    mma_gemm2<<<dim3(FF / 64, BT / 128), 256, 2 * STG>>>(
        x1h, x1l, w1th, nullptr, hidh, hidl, b1, nullptr, 1, FF, Cn);
    // FFN2: d_out += hid @ W2 + b2
    mma_gemm2<<<dim3(Cn / 64, BT / 128), 256, 2 * STG>>>(
        hidh, hidl, w2th, out, nullptr, nullptr, b2, out, 0, Cn, FF);
}

// round 8
// speedup vs baseline: 4.3269x; 1.0409x over previous
#include <cuda_runtime.h>
#include <cuda_fp16.h>
#include <math.h>
#include <stdint.h>

#define Bn  128
#define Tn  256
#define Cn  384
#define Hn  6
#define HDn 64
#define BT  (Bn * Tn)
#define FF  (4 * Cn)
#define QKVN (3 * Cn)   // 1152

// ---------------- scratch (device globals; allocation-free) ----------------
__device__ __align__(16) __half g_x1h [(size_t)BT * Cn];
__device__ __align__(16) __half g_x1l [(size_t)BT * Cn];
__device__ __align__(16) __half g_qh  [(size_t)BT * Cn];
__device__ __align__(16) __half g_ql  [(size_t)BT * Cn];
__device__ __align__(16) __half g_kh  [(size_t)BT * Cn];
__device__ __align__(16) __half g_vh  [(size_t)BT * Cn];
__device__ __align__(16) __half g_ath [(size_t)BT * Cn];
__device__ __align__(16) __half g_atl [(size_t)BT * Cn];
__device__ __align__(16) __half g_hidh[(size_t)BT * FF];
__device__ __align__(16) __half g_hidl[(size_t)BT * FF];
__device__ __align__(16) __half g_wqkvh[(size_t)QKVN * Cn];
__device__ __align__(16) __half g_woth [(size_t)Cn * Cn];
__device__ __align__(16) __half g_w1th [(size_t)FF * Cn];
__device__ __align__(16) __half g_w2th [(size_t)Cn * FF];

// ---------------- helpers ---------------------------------------------------
__device__ __forceinline__ float dot4(const float4 a, const float4 b) {
    return a.x * b.x + a.y * b.y + a.z * b.z + a.w * b.w;
}
__device__ __forceinline__ uint32_t pack_f16x2(float lo, float hi) {
    uint32_t d;
    asm("cvt.rn.f16x2.f32 %0, %1, %2;" : "=r"(d) : "f"(hi), "f"(lo));
    return d;
}
__device__ __forceinline__ void split_store2(__half* ph, __half* pl,
                                             size_t off, float x, float y) {
    float hx = __half2float(__float2half_rn(x));
    float hy = __half2float(__float2half_rn(y));
    *(uint32_t*)(ph + off) = pack_f16x2(x, y);
    *(uint32_t*)(pl + off) = pack_f16x2(x - hx, y - hy);
}
__device__ __forceinline__ void split_store4(__half* ph, __half* pl,
                                             size_t off, float4 v) {
    split_store2(ph, pl, off, v.x, v.y);
    split_store2(ph, pl, off + 2, v.z, v.w);
}
__device__ __forceinline__ uint32_t smem_u32(const void* p) {
    uint32_t a;
    asm("{ .reg .u64 t; cvta.to.shared.u64 t, %1; cvt.u32.u64 %0, t; }" : "=r"(a) : "l"(p));
    return a;
}
__device__ __forceinline__ void cp16(uint32_t dst, const void* src) {
    asm volatile("cp.async.cg.shared.global [%0], [%1], 16;" :: "r"(dst), "l"(src));
}
#define CP_COMMIT() asm volatile("cp.async.commit_group;" ::: "memory")
#define CP_WAIT(n)  asm volatile("cp.async.wait_group %0;" :: "n"(n) : "memory")

__device__ __forceinline__ void ldm4u(uint32_t r[4], uint32_t saddr) {
    asm volatile("ldmatrix.sync.aligned.m8n8.x4.shared.b16 {%0,%1,%2,%3}, [%4];\n"
                 : "=r"(r[0]), "=r"(r[1]), "=r"(r[2]), "=r"(r[3]) : "r"(saddr));
}
__device__ __forceinline__ void ldm_x4(uint32_t r[4], const __half* p) {
    ldm4u(r, smem_u32(p));
}
__device__ __forceinline__ void ldm_x4_trans(uint32_t r[4], const __half* p) {
    uint32_t a = smem_u32(p);
    asm volatile("ldmatrix.sync.aligned.m8n8.x4.trans.shared.b16 {%0,%1,%2,%3}, [%4];\n"
                 : "=r"(r[0]), "=r"(r[1]), "=r"(r[2]), "=r"(r[3]) : "r"(a));
}
__device__ __forceinline__ void mma16816(float d[4], const uint32_t a[4],
                                         uint32_t b0, uint32_t b1) {
    asm volatile("mma.sync.aligned.m16n8k16.row.col.f32.f16.f16.f32 "
        "{%0,%1,%2,%3}, {%4,%5,%6,%7}, {%8,%9}, {%0,%1,%2,%3};\n"
        : "+f"(d[0]), "+f"(d[1]), "+f"(d[2]), "+f"(d[3])
        : "r"(a[0]), "r"(a[1]), "r"(a[2]), "r"(a[3]), "r"(b0), "r"(b1));
}
#define SW128S(o) ((o) ^ (((o) >> 3) & 0x70))

// ---------------- LayerNorm -> fp16 hi/lo planes ----------------------------
__global__ __launch_bounds__(256)
void ln_kernel(const float* __restrict__ x, const float* __restrict__ g,
               const float* __restrict__ b,
               __half* __restrict__ yh, __half* __restrict__ yl)
{
    int row  = blockIdx.x * 8 + (threadIdx.x >> 5);
    int lane = threadIdx.x & 31;
    const float4* xr = (const float4*)(x + (size_t)row * Cn);
    float4 a0 = xr[lane], a1 = xr[lane + 32], a2 = xr[lane + 64];

    float s  = a0.x + a0.y + a0.z + a0.w + a1.x + a1.y + a1.z + a1.w
             + a2.x + a2.y + a2.z + a2.w;
    float sq = dot4(a0, a0) + dot4(a1, a1) + dot4(a2, a2);
    #pragma unroll
    for (int off = 16; off; off >>= 1) {
        s  += __shfl_xor_sync(0xffffffffu, s,  off);
        sq += __shfl_xor_sync(0xffffffffu, sq, off);
    }
    const float inv = 1.0f / (float)Cn;
    float mu  = s * inv;
    float var = sq * inv - mu * mu;
    float r   = rsqrtf(var + 1e-5f);

    const float4* g4 = (const float4*)g;
    const float4* b4 = (const float4*)b;
    size_t rb = (size_t)row * Cn;
    #pragma unroll
    for (int seg = 0; seg < 3; seg++) {
        int li = lane + seg * 32;
        float4 a = seg == 0 ? a0 : (seg == 1 ? a1 : a2);
        float4 gv = g4[li], bv = b4[li];
        float4 o;
        o.x = (a.x - mu) * r * gv.x + bv.x;  o.y = (a.y - mu) * r * gv.y + bv.y;
        o.z = (a.z - mu) * r * gv.z + bv.z;  o.w = (a.w - mu) * r * gv.w + bv.w;
        split_store4(yh, yl, rb + li * 4, o);
    }
}

// ---------------- weight prep: transpose to [N][K], fp16 hi -----------------
__global__ __launch_bounds__(256)
void pack_t(const float* __restrict__ in, __half* __restrict__ oh, int K, int N)
{
    int idx = blockIdx.x * 256 + threadIdx.x;
    if (idx >= N * K) return;
    int n = idx / K, k = idx % K;
    oh[idx] = __float2half_rn(in[(size_t)k * N + n]);
}

__global__ __launch_bounds__(256)
void pack_qkv_t(const float* __restrict__ Wq, const float* __restrict__ Wk,
                const float* __restrict__ Wv, __half* __restrict__ oh)
{
    int idx = blockIdx.x * 256 + threadIdx.x;
    if (idx >= QKVN * Cn) return;
    int n = idx / Cn, c = idx % Cn;
    int which = n / Cn;
    int rr = n % Cn;
    int h = rr / HDn, d = rr % HDn;
    const float* W = (which == 0) ? Wq : (which == 1) ? Wk : Wv;
    oh[idx] = __float2half_rn(W[((size_t)h * Cn + c) * HDn + d]);
}

// ---------------- mma.sync GEMM: 128x128 tile, KC=64, fp16 2-term split ----
// A planes [M][K] fp16 hi+lo, B plane [N][K] fp16 hi.
// Stage (48KB): Ah@0 (16K), Al@16384, Bh@32768 (16K). 2 stages = 96KB.
// Output modes: fp32 (Cf, +bias/+residual), fp16 planes (Ch/Cl, +bias/+relu),
// or QKV mode (Q scaled+split->Ch/Cl, K hi->Kh, V hi->Vh; col0 selects).
#define KC   64
#define STG  49152

__global__ __launch_bounds__(256, 2)
void mma_gemm3(const __half* __restrict__ Ah, const __half* __restrict__ Al,
               const __half* __restrict__ Bh,
               float* __restrict__ Cf,
               __half* __restrict__ Ch, __half* __restrict__ Cl,
               __half* __restrict__ Kh, __half* __restrict__ Vh,
               const float* __restrict__ bias, const float* __restrict__ residual,
               int relu, int qkv, int N, int K)
{
    extern __shared__ __align__(1024) char sm[];   // 2 * STG
    const uint32_t sb0 = smem_u32(sm);

    const int tid  = threadIdx.x;
    const int lane = tid & 31;
    const int w    = tid >> 5;
    const int wm   = w & 3;       // 4 M groups of 32 rows
    const int wn   = w >> 2;      // 2 N groups of 64 cols
    const int row0 = blockIdx.y * 128;
    const int col0 = blockIdx.x * 128;

    const int r8 = tid >> 3;             // 0..31
    const int u8 = (tid & 7) * 16;       // byte offset within 128B row

    float acc[2][8][4];
    #pragma unroll
    for (int i = 0; i < 2; i++)
        #pragma unroll
        for (int j = 0; j < 8; j++)
            #pragma unroll
            for (int q = 0; q < 4; q++) acc[i][j][q] = 0.f;

    const int nc = K / KC;

    auto load_stage = [&](int c, int buf) {
        const uint32_t sb = sb0 + buf * STG;
        const int k0 = c * KC;
        #pragma unroll
        for (int i = 0; i < 4; i++) {
            int r = r8 + i * 32;
            size_t go = ((size_t)(row0 + r) * K + k0) * 2 + u8;
            uint32_t so = SW128S((uint32_t)(r * 128 + u8));
            cp16(sb + so,         (const char*)Ah + go);
            cp16(sb + 16384 + so, (const char*)Al + go);
        }
        #pragma unroll
        for (int i = 0; i < 4; i++) {
            int r = r8 + i * 32;
            size_t go = ((size_t)(col0 + r) * K + k0) * 2 + u8;
            uint32_t so = SW128S((uint32_t)(r * 128 + u8));
            cp16(sb + 32768 + so, (const char*)Bh + go);
        }
        CP_COMMIT();
    };

    load_stage(0, 0);

    for (int c = 0; c < nc; c++) {
        const int buf = c & 1;
        if (c + 1 < nc) {
            load_stage(c + 1, buf ^ 1);
            CP_WAIT(1);
        } else {
            CP_WAIT(0);
        }
        __syncthreads();

        const uint32_t sb = sb0 + buf * STG;
        #pragma unroll
        for (int ks = 0; ks < 4; ks++) {
            const uint32_t kb = ks * 32 + 16 * (lane >> 4);
            uint32_t ah[2][4], al[2][4], bh[4][4];
            #pragma unroll
            for (int i = 0; i < 2; i++) {
                uint32_t off = SW128S((uint32_t)((wm * 32 + i * 16 + (lane & 15)) * 128 + kb));
                ldm4u(ah[i], sb + off);
                ldm4u(al[i], sb + 16384 + off);
            }
            #pragma unroll
            for (int j2 = 0; j2 < 4; j2++) {
                uint32_t off = SW128S((uint32_t)((wn * 64 + j2 * 16 + (lane & 15)) * 128 + kb));
                ldm4u(bh[j2], sb + 32768 + off);
            }
            #pragma unroll
            for (int i = 0; i < 2; i++)
                #pragma unroll
                for (int j = 0; j < 8; j++) {
                    uint32_t b0 = bh[j >> 1][j & 1], b1 = bh[j >> 1][(j & 1) + 2];
                    mma16816(acc[i][j], ah[i], b0, b1);
                    mma16816(acc[i][j], al[i], b0, b1);
                }
        }
        __syncthreads();
    }

    // ---- epilogue ----
    const int which = qkv ? (col0 / Cn) : 0;   // uniform per CTA (384 = 3*128)
    #pragma unroll
    for (int i = 0; i < 2; i++) {
        #pragma unroll
        for (int j = 0; j < 8; j++) {
            int rb = row0 + wm * 32 + i * 16 + (lane >> 2);
            int cc = col0 + wn * 64 + j * 8 + (lane & 3) * 2;
            #pragma unroll
            for (int hh = 0; hh < 2; hh++) {
                int r = rb + 8 * hh;
                float vx = acc[i][j][2 * hh], vy = acc[i][j][2 * hh + 1];
                if (qkv) {
                    int cl = cc - which * Cn;
                    size_t off = (size_t)r * Cn + cl;
                    if (which == 0) {
                        split_store2(Ch, Cl, off, vx * 0.125f, vy * 0.125f);
                    } else if (which == 1) {
                        *(uint32_t*)(Kh + off) = pack_f16x2(vx, vy);
                    } else {
                        *(uint32_t*)(Vh + off) = pack_f16x2(vx, vy);
                    }
                } else {
                    if (bias) { vx += bias[cc]; vy += bias[cc + 1]; }
                    if (Cf) {
                        if (residual) {
                            float2 rr = *(const float2*)(residual + (size_t)r * N + cc);
                            vx += rr.x; vy += rr.y;
                        }
                        *(float2*)(Cf + (size_t)r * N + cc) = make_float2(vx, vy);
                    } else {
                        if (relu) { vx = fmaxf(vx, 0.f); vy = fmaxf(vy, 0.f); }
                        split_store2(Ch, Cl, (size_t)r * N + cc, vx, vy);
                    }
                }
            }
        }
    }
}

// ---------------- flash attention (fp16 planes in, zero conversions) -------
#define PF 136

__global__ __launch_bounds__(256)
void attn_flash(const __half* __restrict__ Qh, const __half* __restrict__ Ql,
                const __half* __restrict__ Kh, const __half* __restrict__ Vh,
                __half* __restrict__ Oh, __half* __restrict__ Ol)
{
    __shared__ __half smf[128 * PF];

    const int tid  = threadIdx.x;
    const int lane = tid & 31;
    const int w    = tid >> 5;
    const int qt = blockIdx.x;
    const int h  = blockIdx.y;
    const int b  = blockIdx.z;

    // ---- stage Q hi/lo (pre-scaled planes) ----
    {
        size_t qbase = ((size_t)(b * Tn + qt * 128)) * Cn + h * HDn;
        #pragma unroll
        for (int it = 0; it < 4; it++) {
            int f = tid + it * 256;          // 0..1023
            int row = f >> 3, c8 = (f & 7) * 8;
            *(uint4*)&smf[row * PF + c8]      = *(const uint4*)(Qh + qbase + (size_t)row * Cn + c8);
            *(uint4*)&smf[row * PF + 64 + c8] = *(const uint4*)(Ql + qbase + (size_t)row * Cn + c8);
        }
    }
    __syncthreads();

    uint32_t qh[4][4], ql[4][4];
    #pragma unroll
    for (int ks = 0; ks < 4; ks++) {
        const __half* p = &smf[(w * 16 + (lane & 15)) * PF + ks * 16 + 8 * (lane >> 4)];
        ldm_x4(qh[ks], p);
        ldm_x4(ql[ks], p + 64);
    }
    __syncthreads();

    float o[8][4];
    #pragma unroll
    for (int j = 0; j < 8; j++)
        #pragma unroll
        for (int q = 0; q < 4; q++) o[j][q] = 0.f;
    float m_old[2] = {-1e30f, -1e30f};
    float l_sum[2] = {0.f, 0.f};

    const int qrow0 = qt * 128 + w * 16 + (lane >> 2);
    const int n_st = 2 * qt + 2;

    for (int st = 0; st < n_st; st++) {
        // ---- stage K hi (rows 0-63) and V hi (rows 64-127) ----
        {
            size_t kb_ = ((size_t)(b * Tn + st * 64)) * Cn + h * HDn;
            #pragma unroll
            for (int it = 0; it < 2; it++) {
                int f = tid + it * 256;      // 0..511
                int row = f >> 3, c8 = (f & 7) * 8;
                *(uint4*)&smf[row * PF + c8] =
                    *(const uint4*)(Kh + kb_ + (size_t)row * Cn + c8);
                *(uint4*)&smf[(64 + row) * PF + c8] =
                    *(const uint4*)(Vh + kb_ + (size_t)row * Cn + c8);
            }
        }
        __syncthreads();

        // ---- S = Qh K^T + Ql K^T ----
        float s[8][4];
        #pragma unroll
        for (int j = 0; j < 8; j++)
            #pragma unroll
            for (int q = 0; q < 4; q++) s[j][q] = 0.f;

        #pragma unroll
        for (int ks = 0; ks < 4; ks++) {
            #pragma unroll
            for (int g = 0; g < 4; g++) {
                uint32_t kh4[4];
                const __half* p =
                    &smf[(g * 16 + (lane & 15)) * PF + ks * 16 + 8 * (lane >> 4)];
                ldm_x4(kh4, p);
                #pragma unroll
                for (int j = 0; j < 2; j++) {
                    int jj = g * 2 + j;
                    mma16816(s[jj], qh[ks], kh4[j], kh4[j + 2]);
                    mma16816(s[jj], ql[ks], kh4[j], kh4[j + 2]);
                }
            }
        }

        // ---- causal mask + online softmax ----
        float m_tile[2] = {-1e30f, -1e30f};
        #pragma unroll
        for (int j = 0; j < 8; j++) {
            #pragma unroll
            for (int q = 0; q < 4; q++) {
                int scol = st * 64 + j * 8 + 2 * (lane & 3) + (q & 1);
                int qrow = qrow0 + 8 * (q >> 1);
                if (scol > qrow) s[j][q] = -1e30f;
                m_tile[q >> 1] = fmaxf(m_tile[q >> 1], s[j][q]);
            }
        }
        #pragma unroll
        for (int r = 0; r < 2; r++) {
            m_tile[r] = fmaxf(m_tile[r], __shfl_xor_sync(0xffffffffu, m_tile[r], 1));
            m_tile[r] = fmaxf(m_tile[r], __shfl_xor_sync(0xffffffffu, m_tile[r], 2));
        }
        float m_new[2], fscale[2], rsum[2] = {0.f, 0.f};
        #pragma unroll
        for (int r = 0; r < 2; r++) {
            m_new[r] = fmaxf(m_old[r], m_tile[r]);
            fscale[r] = __expf(m_old[r] - m_new[r]);
        }
        #pragma unroll
        for (int j = 0; j < 8; j++) {
            #pragma unroll
            for (int q = 0; q < 4; q++) {
                float p = __expf(s[j][q] - m_new[q >> 1]);
                s[j][q] = p;
                rsum[q >> 1] += p;
            }
        }
        #pragma unroll
        for (int r = 0; r < 2; r++) {
            rsum[r] += __shfl_xor_sync(0xffffffffu, rsum[r], 1);
            rsum[r] += __shfl_xor_sync(0xffffffffu, rsum[r], 2);
            l_sum[r] = l_sum[r] * fscale[r] + rsum[r];
            m_old[r] = m_new[r];
        }
        #pragma unroll
        for (int j = 0; j < 8; j++) {
            o[j][0] *= fscale[0]; o[j][1] *= fscale[0];
            o[j][2] *= fscale[1]; o[j][3] *= fscale[1];
        }

        // ---- O += Ph V + Pl V ----
        #pragma unroll
        for (int ks = 0; ks < 4; ks++) {
            float p00 = s[2*ks][0],   p01 = s[2*ks][1],   p02 = s[2*ks][2],   p03 = s[2*ks][3];
            float p10 = s[2*ks+1][0], p11 = s[2*ks+1][1], p12 = s[2*ks+1][2], p13 = s[2*ks+1][3];
            uint32_t pah[4], pal[4];
            pah[0] = pack_f16x2(p00, p01);
            pah[1] = pack_f16x2(p02, p03);
            pah[2] = pack_f16x2(p10, p11);
            pah[3] = pack_f16x2(p12, p13);
            float r00 = p00 - __half2float(__float2half_rn(p00));
            float r01 = p01 - __half2float(__float2half_rn(p01));
            float r02 = p02 - __half2float(__float2half_rn(p02));
            float r03 = p03 - __half2float(__float2half_rn(p03));
            float r10 = p10 - __half2float(__float2half_rn(p10));
            float r11 = p11 - __half2float(__float2half_rn(p11));
            float r12 = p12 - __half2float(__float2half_rn(p12));
            float r13 = p13 - __half2float(__float2half_rn(p13));
            pal[0] = pack_f16x2(r00, r01);
            pal[1] = pack_f16x2(r02, r03);
            pal[2] = pack_f16x2(r10, r11);
            pal[3] = pack_f16x2(r12, r13);

            #pragma unroll
            for (int g = 0; g < 4; g++) {
                uint32_t vh4[4];
                const __half* p =
                    &smf[(64 + ks * 16 + (lane & 15)) * PF + g * 16 + 8 * (lane >> 4)];
                ldm_x4_trans(vh4, p);
                #pragma unroll
                for (int j = 0; j < 2; j++) {
                    int dd = g * 2 + j;
                    mma16816(o[dd], pah, vh4[j * 2], vh4[j * 2 + 1]);
                    mma16816(o[dd], pal, vh4[j * 2], vh4[j * 2 + 1]);
                }
            }
        }
        __syncthreads();
    }

    float inv0 = 1.0f / l_sum[0];
    float inv1 = 1.0f / l_sum[1];
    #pragma unroll
    for (int j = 0; j < 8; j++) {
        int col = h * HDn + j * 8 + 2 * (lane & 3);
        #pragma unroll
        for (int r = 0; r < 2; r++) {
            int row = b * Tn + qrow0 + 8 * r;
            float inv = r ? inv1 : inv0;
            split_store2(Oh, Ol, (size_t)row * Cn + col,
                         o[j][2 * r] * inv, o[j][2 * r + 1] * inv);
        }
    }
}

// ---------------- launch ---------------------------------------------------
extern "C" void kernel_launch(void* const* d_in, const int* in_sizes, int n_in,
                              void* d_out, int out_size)
{
    const float* x     = (const float*)d_in[0];
    const float* ln1_g = (const float*)d_in[1];
    const float* ln1_b = (const float*)d_in[2];
    const float* Wq    = (const float*)d_in[3];
    const float* Wk    = (const float*)d_in[4];
    const float* Wv    = (const float*)d_in[5];
    const float* Wo    = (const float*)d_in[6];
    const float* bo    = (const float*)d_in[7];
    const float* ln2_g = (const float*)d_in[8];
    const float* ln2_b = (const float*)d_in[9];
    const float* W1    = (const float*)d_in[10];
    const float* b1    = (const float*)d_in[11];
    const float* W2    = (const float*)d_in[12];
    const float* b2    = (const float*)d_in[13];
    float* out = (float*)d_out;

    cudaFuncSetAttribute(mma_gemm3, cudaFuncAttributeMaxDynamicSharedMemorySize, 2 * STG);

    void *p;
    cudaGetSymbolAddress(&p, g_x1h);   __half* x1h = (__half*)p;
    cudaGetSymbolAddress(&p, g_x1l);   __half* x1l = (__half*)p;
    cudaGetSymbolAddress(&p, g_qh);    __half* qh = (__half*)p;
    cudaGetSymbolAddress(&p, g_ql);    __half* ql = (__half*)p;
    cudaGetSymbolAddress(&p, g_kh);    __half* kh = (__half*)p;
    cudaGetSymbolAddress(&p, g_vh);    __half* vh = (__half*)p;
    cudaGetSymbolAddress(&p, g_ath);   __half* ath = (__half*)p;
    cudaGetSymbolAddress(&p, g_atl);   __half* atl = (__half*)p;
    cudaGetSymbolAddress(&p, g_hidh);  __half* hidh = (__half*)p;
    cudaGetSymbolAddress(&p, g_hidl);  __half* hidl = (__half*)p;
    cudaGetSymbolAddress(&p, g_wqkvh); __half* wqkvh = (__half*)p;
    cudaGetSymbolAddress(&p, g_woth);  __half* woth = (__half*)p;
    cudaGetSymbolAddress(&p, g_w1th);  __half* w1th = (__half*)p;
    cudaGetSymbolAddress(&p, g_w2th);  __half* w2th = (__half*)p;

    // weight prep (transpose + fp16 hi)
    pack_qkv_t<<<(QKVN * Cn + 255) / 256, 256>>>(Wq, Wk, Wv, wqkvh);
    pack_t<<<(Cn * Cn + 255) / 256, 256>>>(Wo, woth, Cn, Cn);
    pack_t<<<(Cn * FF + 255) / 256, 256>>>(W1, w1th, Cn, FF);
    pack_t<<<(FF * Cn + 255) / 256, 256>>>(W2, w2th, FF, Cn);

    // LN1 -> planes
    ln_kernel<<<BT / 8, 256>>>(x, ln1_g, ln1_b, x1h, x1l);
    // QKV: [BT,384] x [1152,384]^T -> fp16 planes (Q scaled hi/lo, K hi, V hi)
    mma_gemm3<<<dim3(QKVN / 128, BT / 128), 256, 2 * STG>>>(
        x1h, x1l, wqkvh, nullptr, qh, ql, kh, vh, nullptr, nullptr, 0, 1, QKVN, Cn);
    // causal flash attention -> planes
    attn_flash<<<dim3(2, Hn, Bn), 256>>>(qh, ql, kh, vh, ath, atl);
    // Wo + bias + residual(x) -> d_out (fp32)
    mma_gemm3<<<dim3(Cn / 128, BT / 128), 256, 2 * STG>>>(
        ath, atl, woth, out, nullptr, nullptr, nullptr, nullptr, bo, x, 0, 0, Cn, Cn);
    // LN2 -> planes
    ln_kernel<<<BT / 8, 256>>>(out, ln2_g, ln2_b, x1h, x1l);
    // FFN1: relu(x2 @ W1 + b1) -> planes
    mma_gemm3<<<dim3(FF / 128, BT / 128), 256, 2 * STG>>>(
        x1h, x1l, w1th, nullptr, hidh, hidl, nullptr, nullptr, b1, nullptr, 1, 0, FF, Cn);
    // FFN2: d_out += hid @ W2 + b2
    mma_gemm3<<<dim3(Cn / 128, BT / 128), 256, 2 * STG>>>(
        hidh, hidl, w2th, out, nullptr, nullptr, nullptr, nullptr, b2, out, 0, 0, Cn, FF);
}

// round 10
// speedup vs baseline: 6.6017x; 1.5257x over previous
#include <cuda_runtime.h>
#include <cuda_fp16.h>
#include <math.h>
#include <stdint.h>

#define Bn  128
#define Tn  256
#define Cn  384
#define Hn  6
#define HDn 64
#define BT  (Bn * Tn)
#define FF  (4 * Cn)
#define QKVN (3 * Cn)   // 1152

// ---------------- scratch (device globals; allocation-free) ----------------
__device__ __align__(16) __half g_x1h [(size_t)BT * Cn];
__device__ __align__(16) __half g_qh  [(size_t)BT * Cn];
__device__ __align__(16) __half g_ql  [(size_t)BT * Cn];
__device__ __align__(16) __half g_kh  [(size_t)BT * Cn];
__device__ __align__(16) __half g_vh  [(size_t)BT * Cn];
__device__ __align__(16) __half g_ath [(size_t)BT * Cn];
__device__ __align__(16) __half g_hidh[(size_t)BT * FF];
__device__ __align__(16) __half g_wqkvh[(size_t)QKVN * Cn];
__device__ __align__(16) __half g_woth [(size_t)Cn * Cn];
__device__ __align__(16) __half g_w1th [(size_t)FF * Cn];
__device__ __align__(16) __half g_w2th [(size_t)Cn * FF];

// ---------------- helpers ---------------------------------------------------
__device__ __forceinline__ float dot4(const float4 a, const float4 b) {
    return a.x * b.x + a.y * b.y + a.z * b.z + a.w * b.w;
}
__device__ __forceinline__ uint32_t pack_f16x2(float lo, float hi) {
    uint32_t d;
    asm("cvt.rn.f16x2.f32 %0, %1, %2;" : "=r"(d) : "f"(hi), "f"(lo));
    return d;
}
__device__ __forceinline__ void split_store2(__half* ph, __half* pl,
                                             size_t off, float x, float y) {
    float hx = __half2float(__float2half_rn(x));
    float hy = __half2float(__float2half_rn(y));
    *(uint32_t*)(ph + off) = pack_f16x2(x, y);
    *(uint32_t*)(pl + off) = pack_f16x2(x - hx, y - hy);
}
__device__ __forceinline__ uint32_t smem_u32(const void* p) {
    uint32_t a;
    asm("{ .reg .u64 t; cvta.to.shared.u64 t, %1; cvt.u32.u64 %0, t; }" : "=r"(a) : "l"(p));
    return a;
}
__device__ __forceinline__ void cp16(uint32_t dst, const void* src) {
    asm volatile("cp.async.cg.shared.global [%0], [%1], 16;" :: "r"(dst), "l"(src));
}
#define CP_COMMIT() asm volatile("cp.async.commit_group;" ::: "memory")
#define CP_WAIT(n)  asm volatile("cp.async.wait_group %0;" :: "n"(n) : "memory")

__device__ __forceinline__ void ldm4u(uint32_t r[4], uint32_t saddr) {
    asm volatile("ldmatrix.sync.aligned.m8n8.x4.shared.b16 {%0,%1,%2,%3}, [%4];\n"
                 : "=r"(r[0]), "=r"(r[1]), "=r"(r[2]), "=r"(r[3]) : "r"(saddr));
}
__device__ __forceinline__ void ldm_x4(uint32_t r[4], const __half* p) {
    ldm4u(r, smem_u32(p));
}
__device__ __forceinline__ void ldm_x4_trans(uint32_t r[4], const __half* p) {
    uint32_t a = smem_u32(p);
    asm volatile("ldmatrix.sync.aligned.m8n8.x4.trans.shared.b16 {%0,%1,%2,%3}, [%4];\n"
                 : "=r"(r[0]), "=r"(r[1]), "=r"(r[2]), "=r"(r[3]) : "r"(a));
}
__device__ __forceinline__ void mma16816(float d[4], const uint32_t a[4],
                                         uint32_t b0, uint32_t b1) {
    asm volatile("mma.sync.aligned.m16n8k16.row.col.f32.f16.f16.f32 "
        "{%0,%1,%2,%3}, {%4,%5,%6,%7}, {%8,%9}, {%0,%1,%2,%3};\n"
        : "+f"(d[0]), "+f"(d[1]), "+f"(d[2]), "+f"(d[3])
        : "r"(a[0]), "r"(a[1]), "r"(a[2]), "r"(a[3]), "r"(b0), "r"(b1));
}
#define SW128S(o) ((o) ^ (((o) >> 3) & 0x70))

// ---------------- LayerNorm -> fp16 hi plane --------------------------------
__global__ __launch_bounds__(256)
void ln_kernel(const float* __restrict__ x, const float* __restrict__ g,
               const float* __restrict__ b, __half* __restrict__ yh)
{
    int row  = blockIdx.x * 8 + (threadIdx.x >> 5);
    int lane = threadIdx.x & 31;
    const float4* xr = (const float4*)(x + (size_t)row * Cn);
    float4 a0 = xr[lane], a1 = xr[lane + 32], a2 = xr[lane + 64];

    float s  = a0.x + a0.y + a0.z + a0.w + a1.x + a1.y + a1.z + a1.w
             + a2.x + a2.y + a2.z + a2.w;
    float sq = dot4(a0, a0) + dot4(a1, a1) + dot4(a2, a2);
    #pragma unroll
    for (int off = 16; off; off >>= 1) {
        s  += __shfl_xor_sync(0xffffffffu, s,  off);
        sq += __shfl_xor_sync(0xffffffffu, sq, off);
    }
    const float inv = 1.0f / (float)Cn;
    float mu  = s * inv;
    float var = sq * inv - mu * mu;
    float r   = rsqrtf(var + 1e-5f);

    const float4* g4 = (const float4*)g;
    const float4* b4 = (const float4*)b;
    size_t rb = (size_t)row * Cn;
    #pragma unroll
    for (int seg = 0; seg < 3; seg++) {
        int li = lane + seg * 32;
        float4 a = seg == 0 ? a0 : (seg == 1 ? a1 : a2);
        float4 gv = g4[li], bv = b4[li];
        float ox = (a.x - mu) * r * gv.x + bv.x;
        float oy = (a.y - mu) * r * gv.y + bv.y;
        float oz = (a.z - mu) * r * gv.z + bv.z;
        float ow = (a.w - mu) * r * gv.w + bv.w;
        *(uint32_t*)(yh + rb + li * 4)     = pack_f16x2(ox, oy);
        *(uint32_t*)(yh + rb + li * 4 + 2) = pack_f16x2(oz, ow);
    }
}

// ---------------- weight prep: transpose to [N][K], fp16 hi -----------------
__global__ __launch_bounds__(256)
void pack_t(const float* __restrict__ in, __half* __restrict__ oh, int K, int N)
{
    int idx = blockIdx.x * 256 + threadIdx.x;
    if (idx >= N * K) return;
    int n = idx / K, k = idx % K;
    oh[idx] = __float2half_rn(in[(size_t)k * N + n]);
}

__global__ __launch_bounds__(256)
void pack_qkv_t(const float* __restrict__ Wq, const float* __restrict__ Wk,
                const float* __restrict__ Wv, __half* __restrict__ oh)
{
    int idx = blockIdx.x * 256 + threadIdx.x;
    if (idx >= QKVN * Cn) return;
    int n = idx / Cn, c = idx % Cn;
    int which = n / Cn;
    int rr = n % Cn;
    int h = rr / HDn, d = rr % HDn;
    const float* W = (which == 0) ? Wq : (which == 1) ? Wk : Wv;
    oh[idx] = __float2half_rn(W[((size_t)h * Cn + c) * HDn + d]);
}

// ---------------- mma.sync GEMM: 128x128 tile, KC=64, pure fp16, 3-stage ---
// A [M][K] fp16, B [N][K] fp16. Stage (32KB): A@0 (16K), B@16384 (16K).
// Output modes: fp32 (Cf, +bias/+residual), fp16 (Ch, +bias/+relu),
// QKV mode (Q scaled+split -> Ch/Ql, K->Kh, V->Vh).
#define KC   64
#define STG  32768

__global__ __launch_bounds__(256, 2)
void mma_gemm4(const __half* __restrict__ Ah, const __half* __restrict__ Bh,
               float* __restrict__ Cf, __half* __restrict__ Ch,
               __half* __restrict__ Ql, __half* __restrict__ Kh, __half* __restrict__ Vh,
               const float* __restrict__ bias, const float* __restrict__ residual,
               int relu, int qkv, int N, int K)
{
    extern __shared__ __align__(1024) char sm[];   // 3 * STG
    const uint32_t sb0 = smem_u32(sm);

    const int tid  = threadIdx.x;
    const int lane = tid & 31;
    const int w    = tid >> 5;
    const int wm   = w & 3;       // 4 M groups of 32 rows
    const int wn   = w >> 2;      // 2 N groups of 64 cols
    const int row0 = blockIdx.y * 128;
    const int col0 = blockIdx.x * 128;

    const int r8 = tid >> 3;             // 0..31
    const int u8 = (tid & 7) * 16;       // byte offset within 128B row

    float acc[2][8][4];
    #pragma unroll
    for (int i = 0; i < 2; i++)
        #pragma unroll
        for (int j = 0; j < 8; j++)
            #pragma unroll
            for (int q = 0; q < 4; q++) acc[i][j][q] = 0.f;

    const int nc = K / KC;

    auto load_stage = [&](int c, int buf) {
        const uint32_t sb = sb0 + buf * STG;
        const int k0 = c * KC;
        #pragma unroll
        for (int i = 0; i < 4; i++) {
            int r = r8 + i * 32;
            size_t go = ((size_t)(row0 + r) * K + k0) * 2 + u8;
            uint32_t so = SW128S((uint32_t)(r * 128 + u8));
            cp16(sb + so, (const char*)Ah + go);
        }
        #pragma unroll
        for (int i = 0; i < 4; i++) {
            int r = r8 + i * 32;
            size_t go = ((size_t)(col0 + r) * K + k0) * 2 + u8;
            uint32_t so = SW128S((uint32_t)(r * 128 + u8));
            cp16(sb + 16384 + so, (const char*)Bh + go);
        }
        CP_COMMIT();
    };

    load_stage(0, 0);
    if (nc > 1) load_stage(1, 1);

    for (int c = 0; c < nc; c++) {
        const int buf = c % 3;
        if (c + 2 < nc) {
            load_stage(c + 2, (c + 2) % 3);
            CP_WAIT(2);
        } else if (c + 1 < nc) {
            CP_WAIT(1);
        } else {
            CP_WAIT(0);
        }
        __syncthreads();

        const uint32_t sb = sb0 + buf * STG;
        #pragma unroll
        for (int ks = 0; ks < 4; ks++) {
            const uint32_t kb = ks * 32 + 16 * (lane >> 4);
            uint32_t ah[2][4], bh[4][4];
            #pragma unroll
            for (int i = 0; i < 2; i++) {
                uint32_t off = SW128S((uint32_t)((wm * 32 + i * 16 + (lane & 15)) * 128 + kb));
                ldm4u(ah[i], sb + off);
            }
            #pragma unroll
            for (int j2 = 0; j2 < 4; j2++) {
                uint32_t off = SW128S((uint32_t)((wn * 64 + j2 * 16 + (lane & 15)) * 128 + kb));
                ldm4u(bh[j2], sb + 16384 + off);
            }
            #pragma unroll
            for (int i = 0; i < 2; i++)
                #pragma unroll
                for (int j = 0; j < 8; j++) {
                    uint32_t b0 = bh[j >> 1][j & 1], b1 = bh[j >> 1][(j & 1) + 2];
                    mma16816(acc[i][j], ah[i], b0, b1);
                }
        }
        __syncthreads();
    }

    // ---- epilogue ----
    const int which = qkv ? (col0 / Cn) : 0;   // uniform per CTA (384 = 3*128)
    #pragma unroll
    for (int i = 0; i < 2; i++) {
        #pragma unroll
        for (int j = 0; j < 8; j++) {
            int rb = row0 + wm * 32 + i * 16 + (lane >> 2);
            int cc = col0 + wn * 64 + j * 8 + (lane & 3) * 2;
            #pragma unroll
            for (int hh = 0; hh < 2; hh++) {
                int r = rb + 8 * hh;
                float vx = acc[i][j][2 * hh], vy = acc[i][j][2 * hh + 1];
                if (qkv) {
                    int cl = cc - which * Cn;
                    size_t off = (size_t)r * Cn + cl;
                    if (which == 0) {
                        split_store2(Ch, Ql, off, vx * 0.125f, vy * 0.125f);
                    } else if (which == 1) {
                        *(uint32_t*)(Kh + off) = pack_f16x2(vx, vy);
                    } else {
                        *(uint32_t*)(Vh + off) = pack_f16x2(vx, vy);
                    }
                } else {
                    if (bias) { vx += bias[cc]; vy += bias[cc + 1]; }
                    if (Cf) {
                        if (residual) {
                            float2 rr = *(const float2*)(residual + (size_t)r * N + cc);
                            vx += rr.x; vy += rr.y;
                        }
                        *(float2*)(Cf + (size_t)r * N + cc) = make_float2(vx, vy);
                    } else {
                        if (relu) { vx = fmaxf(vx, 0.f); vy = fmaxf(vy, 0.f); }
                        *(uint32_t*)(Ch + (size_t)r * N + cc) = pack_f16x2(vx, vy);
                    }
                }
            }
        }
    }
}

// ---------------- flash attention (fp16 planes in, 2-term Q and P) ---------
#define PF 136

__global__ __launch_bounds__(256)
void attn_flash(const __half* __restrict__ Qh, const __half* __restrict__ Ql,
                const __half* __restrict__ Kh, const __half* __restrict__ Vh,
                __half* __restrict__ Oh)
{
    __shared__ __half smf[128 * PF];

    const int tid  = threadIdx.x;
    const int lane = tid & 31;
    const int w    = tid >> 5;
    const int qt = blockIdx.x;
    const int h  = blockIdx.y;
    const int b  = blockIdx.z;

    // ---- stage Q hi/lo (pre-scaled planes) ----
    {
        size_t qbase = ((size_t)(b * Tn + qt * 128)) * Cn + h * HDn;
        #pragma unroll
        for (int it = 0; it < 4; it++) {
            int f = tid + it * 256;          // 0..1023
            int row = f >> 3, c8 = (f & 7) * 8;
            *(uint4*)&smf[row * PF + c8]      = *(const uint4*)(Qh + qbase + (size_t)row * Cn + c8);
            *(uint4*)&smf[row * PF + 64 + c8] = *(const uint4*)(Ql + qbase + (size_t)row * Cn + c8);
        }
    }
    __syncthreads();

    uint32_t qh[4][4], ql[4][4];
    #pragma unroll
    for (int ks = 0; ks < 4; ks++) {
        const __half* p = &smf[(w * 16 + (lane & 15)) * PF + ks * 16 + 8 * (lane >> 4)];
        ldm_x4(qh[ks], p);
        ldm_x4(ql[ks], p + 64);
    }
    __syncthreads();

    float o[8][4];
    #pragma unroll
    for (int j = 0; j < 8; j++)
        #pragma unroll
        for (int q = 0; q < 4; q++) o[j][q] = 0.f;
    float m_old[2] = {-1e30f, -1e30f};
    float l_sum[2] = {0.f, 0.f};

    const int qrow0 = qt * 128 + w * 16 + (lane >> 2);
    const int n_st = 2 * qt + 2;

    for (int st = 0; st < n_st; st++) {
        // ---- stage K hi (rows 0-63) and V hi (rows 64-127) ----
        {
            size_t kb_ = ((size_t)(b * Tn + st * 64)) * Cn + h * HDn;
            #pragma unroll
            for (int it = 0; it < 2; it++) {
                int f = tid + it * 256;      // 0..511
                int row = f >> 3, c8 = (f & 7) * 8;
                *(uint4*)&smf[row * PF + c8] =
                    *(const uint4*)(Kh + kb_ + (size_t)row * Cn + c8);
                *(uint4*)&smf[(64 + row) * PF + c8] =
                    *(const uint4*)(Vh + kb_ + (size_t)row * Cn + c8);
            }
        }
        __syncthreads();

        // ---- S = Qh K^T + Ql K^T ----
        float s[8][4];
        #pragma unroll
        for (int j = 0; j < 8; j++)
            #pragma unroll
            for (int q = 0; q < 4; q++) s[j][q] = 0.f;

        #pragma unroll
        for (int ks = 0; ks < 4; ks++) {
            #pragma unroll
            for (int g = 0; g < 4; g++) {
                uint32_t kh4[4];
                const __half* p =
                    &smf[(g * 16 + (lane & 15)) * PF + ks * 16 + 8 * (lane >> 4)];
                ldm_x4(kh4, p);
                #pragma unroll
                for (int j = 0; j < 2; j++) {
                    int jj = g * 2 + j;
                    mma16816(s[jj], qh[ks], kh4[j], kh4[j + 2]);
                    mma16816(s[jj], ql[ks], kh4[j], kh4[j + 2]);
                }
            }
        }

        // ---- causal mask + online softmax ----
        float m_tile[2] = {-1e30f, -1e30f};
        #pragma unroll
        for (int j = 0; j < 8; j++) {
            #pragma unroll
            for (int q = 0; q < 4; q++) {
                int scol = st * 64 + j * 8 + 2 * (lane & 3) + (q & 1);
                int qrow = qrow0 + 8 * (q >> 1);
                if (scol > qrow) s[j][q] = -1e30f;
                m_tile[q >> 1] = fmaxf(m_tile[q >> 1], s[j][q]);
            }
        }
        #pragma unroll
        for (int r = 0; r < 2; r++) {
            m_tile[r] = fmaxf(m_tile[r], __shfl_xor_sync(0xffffffffu, m_tile[r], 1));
            m_tile[r] = fmaxf(m_tile[r], __shfl_xor_sync(0xffffffffu, m_tile[r], 2));
        }
        float m_new[2], fscale[2], rsum[2] = {0.f, 0.f};
        #pragma unroll
        for (int r = 0; r < 2; r++) {
            m_new[r] = fmaxf(m_old[r], m_tile[r]);
            fscale[r] = __expf(m_old[r] - m_new[r]);
        }
        #pragma unroll
        for (int j = 0; j < 8; j++) {
            #pragma unroll
            for (int q = 0; q < 4; q++) {
                float p = __expf(s[j][q] - m_new[q >> 1]);
                s[j][q] = p;
                rsum[q >> 1] += p;
            }
        }
        #pragma unroll
        for (int r = 0; r < 2; r++) {
            rsum[r] += __shfl_xor_sync(0xffffffffu, rsum[r], 1);
            rsum[r] += __shfl_xor_sync(0xffffffffu, rsum[r], 2);
            l_sum[r] = l_sum[r] * fscale[r] + rsum[r];
            m_old[r] = m_new[r];
        }
        #pragma unroll
        for (int j = 0; j < 8; j++) {
            o[j][0] *= fscale[0]; o[j][1] *= fscale[0];
            o[j][2] *= fscale[1]; o[j][3] *= fscale[1];
        }

        // ---- O += Ph V + Pl V ----
        #pragma unroll
        for (int ks = 0; ks < 4; ks++) {
            float p00 = s[2*ks][0],   p01 = s[2*ks][1],   p02 = s[2*ks][2],   p03 = s[2*ks][3];
            float p10 = s[2*ks+1][0], p11 = s[2*ks+1][1], p12 = s[2*ks+1][2], p13 = s[2*ks+1][3];
            uint32_t pah[4], pal[4];
            pah[0] = pack_f16x2(p00, p01);
            pah[1] = pack_f16x2(p02, p03);
            pah[2] = pack_f16x2(p10, p11);
            pah[3] = pack_f16x2(p12, p13);
            float r00 = p00 - __half2float(__float2half_rn(p00));
            float r01 = p01 - __half2float(__float2half_rn(p01));
            float r02 = p02 - __half2float(__float2half_rn(p02));
            float r03 = p03 - __half2float(__float2half_rn(p03));
            float r10 = p10 - __half2float(__float2half_rn(p10));
            float r11 = p11 - __half2float(__float2half_rn(p11));
            float r12 = p12 - __half2float(__float2half_rn(p12));
            float r13 = p13 - __half2float(__float2half_rn(p13));
            pal[0] = pack_f16x2(r00, r01);
            pal[1] = pack_f16x2(r02, r03);
            pal[2] = pack_f16x2(r10, r11);
            pal[3] = pack_f16x2(r12, r13);

            #pragma unroll
            for (int g = 0; g < 4; g++) {
                uint32_t vh4[4];
                const __half* p =
                    &smf[(64 + ks * 16 + (lane & 15)) * PF + g * 16 + 8 * (lane >> 4)];
                ldm_x4_trans(vh4, p);
                #pragma unroll
                for (int j = 0; j < 2; j++) {
                    int dd = g * 2 + j;
                    mma16816(o[dd], pah, vh4[j * 2], vh4[j * 2 + 1]);
                    mma16816(o[dd], pal, vh4[j * 2], vh4[j * 2 + 1]);
                }
            }
        }
        __syncthreads();
    }

    float inv0 = 1.0f / l_sum[0];
    float inv1 = 1.0f / l_sum[1];
    #pragma unroll
    for (int j = 0; j < 8; j++) {
        int col = h * HDn + j * 8 + 2 * (lane & 3);
        #pragma unroll
        for (int r = 0; r < 2; r++) {
            int row = b * Tn + qrow0 + 8 * r;
            float inv = r ? inv1 : inv0;
            *(uint32_t*)(Oh + (size_t)row * Cn + col) =
                pack_f16x2(o[j][2 * r] * inv, o[j][2 * r + 1] * inv);
        }
    }
}

// ---------------- launch ---------------------------------------------------
extern "C" void kernel_launch(void* const* d_in, const int* in_sizes, int n_in,
                              void* d_out, int out_size)
{
    const float* x     = (const float*)d_in[0];
    const float* ln1_g = (const float*)d_in[1];
    const float* ln1_b = (const float*)d_in[2];
    const float* Wq    = (const float*)d_in[3];
    const float* Wk    = (const float*)d_in[4];
    const float* Wv    = (const float*)d_in[5];
    const float* Wo    = (const float*)d_in[6];
    const float* bo    = (const float*)d_in[7];
    const float* ln2_g = (const float*)d_in[8];
    const float* ln2_b = (const float*)d_in[9];
    const float* W1    = (const float*)d_in[10];
    const float* b1    = (const float*)d_in[11];
    const float* W2    = (const float*)d_in[12];
    const float* b2    = (const float*)d_in[13];
    float* out = (float*)d_out;

    cudaFuncSetAttribute(mma_gemm4, cudaFuncAttributeMaxDynamicSharedMemorySize, 3 * STG);

    void *p;
    cudaGetSymbolAddress(&p, g_x1h);   __half* x1h = (__half*)p;
    cudaGetSymbolAddress(&p, g_qh);    __half* qh = (__half*)p;
    cudaGetSymbolAddress(&p, g_ql);    __half* ql = (__half*)p;
    cudaGetSymbolAddress(&p, g_kh);    __half* kh = (__half*)p;
    cudaGetSymbolAddress(&p, g_vh);    __half* vh = (__half*)p;
    cudaGetSymbolAddress(&p, g_ath);   __half* ath = (__half*)p;
    cudaGetSymbolAddress(&p, g_hidh);  __half* hidh = (__half*)p;
    cudaGetSymbolAddress(&p, g_wqkvh); __half* wqkvh = (__half*)p;
    cudaGetSymbolAddress(&p, g_woth);  __half* woth = (__half*)p;
    cudaGetSymbolAddress(&p, g_w1th);  __half* w1th = (__half*)p;
    cudaGetSymbolAddress(&p, g_w2th);  __half* w2th = (__half*)p;

    // weight prep (transpose + fp16 hi)
    pack_qkv_t<<<(QKVN * Cn + 255) / 256, 256>>>(Wq, Wk, Wv, wqkvh);
    pack_t<<<(Cn * Cn + 255) / 256, 256>>>(Wo, woth, Cn, Cn);
    pack_t<<<(Cn * FF + 255) / 256, 256>>>(W1, w1th, Cn, FF);
    pack_t<<<(FF * Cn + 255) / 256, 256>>>(W2, w2th, FF, Cn);

    // LN1 -> fp16
    ln_kernel<<<BT / 8, 256>>>(x, ln1_g, ln1_b, x1h);
    // QKV: [BT,384] x [1152,384]^T -> Q (scaled hi/lo), K hi, V hi
    mma_gemm4<<<dim3(QKVN / 128, BT / 128), 256, 3 * STG>>>(
        x1h, wqkvh, nullptr, qh, ql, kh, vh, nullptr, nullptr, 0, 1, QKVN, Cn);
    // causal flash attention -> fp16
    attn_flash<<<dim3(2, Hn, Bn), 256>>>(qh, ql, kh, vh, ath);
    // Wo + bias + residual(x) -> d_out (fp32)
    mma_gemm4<<<dim3(Cn / 128, BT / 128), 256, 3 * STG>>>(
        ath, woth, out, nullptr, nullptr, nullptr, nullptr, bo, x, 0, 0, Cn, Cn);
    // LN2 -> fp16
    ln_kernel<<<BT / 8, 256>>>(out, ln2_g, ln2_b, x1h);
    // FFN1: relu(x2 @ W1 + b1) -> fp16
    mma_gemm4<<<dim3(FF / 128, BT / 128), 256, 3 * STG>>>(
        x1h, w1th, nullptr, hidh, nullptr, nullptr, nullptr, b1, nullptr, 1, 0, FF, Cn);
    // FFN2: d_out += hid @ W2 + b2
    mma_gemm4<<<dim3(Cn / 128, BT / 128), 256, 3 * STG>>>(
        hidh, w2th, out, nullptr, nullptr, nullptr, nullptr, b2, out, 0, 0, Cn, FF);
}

// round 11
// speedup vs baseline: 7.1997x; 1.0906x over previous
#include <cuda_runtime.h>
#include <cuda_fp16.h>
#include <math.h>
#include <stdint.h>

#define Bn  128
#define Tn  256
#define Cn  384
#define Hn  6
#define HDn 64
#define BT  (Bn * Tn)
#define FF  (4 * Cn)
#define QKVN (3 * Cn)   // 1152

// ---------------- scratch (device globals; allocation-free) ----------------
__device__ __align__(16) __half g_x1h [(size_t)BT * Cn];
__device__ __align__(16) __half g_qh  [(size_t)BT * Cn];
__device__ __align__(16) __half g_ql  [(size_t)BT * Cn];
__device__ __align__(16) __half g_kh  [(size_t)BT * Cn];
__device__ __align__(16) __half g_vh  [(size_t)BT * Cn];
__device__ __align__(16) __half g_ath [(size_t)BT * Cn];
__device__ __align__(16) __half g_hidh[(size_t)BT * FF];
__device__ __align__(16) __half g_wqkvh[(size_t)QKVN * Cn];
__device__ __align__(16) __half g_woth [(size_t)Cn * Cn];
__device__ __align__(16) __half g_w1th [(size_t)FF * Cn];
__device__ __align__(16) __half g_w2th [(size_t)Cn * FF];

// ---------------- helpers ---------------------------------------------------
__device__ __forceinline__ float dot4(const float4 a, const float4 b) {
    return a.x * b.x + a.y * b.y + a.z * b.z + a.w * b.w;
}
__device__ __forceinline__ uint32_t pack_f16x2(float lo, float hi) {
    uint32_t d;
    asm("cvt.rn.f16x2.f32 %0, %1, %2;" : "=r"(d) : "f"(hi), "f"(lo));
    return d;
}
__device__ __forceinline__ void split_store2(__half* ph, __half* pl,
                                             size_t off, float x, float y) {
    float hx = __half2float(__float2half_rn(x));
    float hy = __half2float(__float2half_rn(y));
    *(uint32_t*)(ph + off) = pack_f16x2(x, y);
    *(uint32_t*)(pl + off) = pack_f16x2(x - hx, y - hy);
}
__device__ __forceinline__ uint32_t smem_u32(const void* p) {
    uint32_t a;
    asm("{ .reg .u64 t; cvta.to.shared.u64 t, %1; cvt.u32.u64 %0, t; }" : "=r"(a) : "l"(p));
    return a;
}
__device__ __forceinline__ void cp16(uint32_t dst, const void* src) {
    asm volatile("cp.async.cg.shared.global [%0], [%1], 16;" :: "r"(dst), "l"(src));
}
#define CP_COMMIT() asm volatile("cp.async.commit_group;" ::: "memory")
#define CP_WAIT(n)  asm volatile("cp.async.wait_group %0;" :: "n"(n) : "memory")

__device__ __forceinline__ void ldm4u(uint32_t r[4], uint32_t saddr) {
    asm volatile("ldmatrix.sync.aligned.m8n8.x4.shared.b16 {%0,%1,%2,%3}, [%4];\n"
                 : "=r"(r[0]), "=r"(r[1]), "=r"(r[2]), "=r"(r[3]) : "r"(saddr));
}
__device__ __forceinline__ void ldm_x4(uint32_t r[4], const __half* p) {
    ldm4u(r, smem_u32(p));
}
__device__ __forceinline__ void ldm_x4_trans(uint32_t r[4], const __half* p) {
    uint32_t a = smem_u32(p);
    asm volatile("ldmatrix.sync.aligned.m8n8.x4.trans.shared.b16 {%0,%1,%2,%3}, [%4];\n"
                 : "=r"(r[0]), "=r"(r[1]), "=r"(r[2]), "=r"(r[3]) : "r"(a));
}
__device__ __forceinline__ void mma16816(float d[4], const uint32_t a[4],
                                         uint32_t b0, uint32_t b1) {
    asm volatile("mma.sync.aligned.m16n8k16.row.col.f32.f16.f16.f32 "
        "{%0,%1,%2,%3}, {%4,%5,%6,%7}, {%8,%9}, {%0,%1,%2,%3};\n"
        : "+f"(d[0]), "+f"(d[1]), "+f"(d[2]), "+f"(d[3])
        : "r"(a[0]), "r"(a[1]), "r"(a[2]), "r"(a[3]), "r"(b0), "r"(b1));
}
#define SW128S(o) ((o) ^ (((o) >> 3) & 0x70))

// ---------------- LayerNorm -> fp16 hi plane --------------------------------
__global__ __launch_bounds__(256)
void ln_kernel(const float* __restrict__ x, const float* __restrict__ g,
               const float* __restrict__ b, __half* __restrict__ yh)
{
    int row  = blockIdx.x * 8 + (threadIdx.x >> 5);
    int lane = threadIdx.x & 31;
    const float4* xr = (const float4*)(x + (size_t)row * Cn);
    float4 a0 = xr[lane], a1 = xr[lane + 32], a2 = xr[lane + 64];

    float s  = a0.x + a0.y + a0.z + a0.w + a1.x + a1.y + a1.z + a1.w
             + a2.x + a2.y + a2.z + a2.w;
    float sq = dot4(a0, a0) + dot4(a1, a1) + dot4(a2, a2);
    #pragma unroll
    for (int off = 16; off; off >>= 1) {
        s  += __shfl_xor_sync(0xffffffffu, s,  off);
        sq += __shfl_xor_sync(0xffffffffu, sq, off);
    }
    const float inv = 1.0f / (float)Cn;
    float mu  = s * inv;
    float var = sq * inv - mu * mu;
    float r   = rsqrtf(var + 1e-5f);

    const float4* g4 = (const float4*)g;
    const float4* b4 = (const float4*)b;
    size_t rb = (size_t)row * Cn;
    #pragma unroll
    for (int seg = 0; seg < 3; seg++) {
        int li = lane + seg * 32;
        float4 a = seg == 0 ? a0 : (seg == 1 ? a1 : a2);
        float4 gv = g4[li], bv = b4[li];
        float ox = (a.x - mu) * r * gv.x + bv.x;
        float oy = (a.y - mu) * r * gv.y + bv.y;
        float oz = (a.z - mu) * r * gv.z + bv.z;
        float ow = (a.w - mu) * r * gv.w + bv.w;
        *(uint32_t*)(yh + rb + li * 4)     = pack_f16x2(ox, oy);
        *(uint32_t*)(yh + rb + li * 4 + 2) = pack_f16x2(oz, ow);
    }
}

// ---------------- weight prep: tiled transpose [K][N] -> [N][K], fp16 ------
__global__ __launch_bounds__(256)
void pack_t_tiled(const float* __restrict__ in, __half* __restrict__ oh,
                  int K, int N)
{
    __shared__ float tile[32][33];
    const int tx = threadIdx.x & 31;
    const int ty = threadIdx.x >> 5;          // 0..7
    const int k0 = blockIdx.x * 32;
    const int n0 = blockIdx.y * 32;
    #pragma unroll
    for (int i = 0; i < 32; i += 8)
        tile[ty + i][tx] = in[(size_t)(k0 + ty + i) * N + n0 + tx];
    __syncthreads();
    #pragma unroll
    for (int i = 0; i < 32; i += 8)
        oh[(size_t)(n0 + ty + i) * K + k0 + tx] = __float2half_rn(tile[tx][ty + i]);
}

// QKV weights [h][c][d] -> [which*384 + h*64 + d][c]
__global__ __launch_bounds__(256)
void pack_qkv_tiled(const float* __restrict__ Wq, const float* __restrict__ Wk,
                    const float* __restrict__ Wv, __half* __restrict__ oh)
{
    __shared__ float tile[32][33];
    const int tx = threadIdx.x & 31;
    const int ty = threadIdx.x >> 5;
    const int z = blockIdx.z;                 // 0..17 = which*6 + h
    const int which = z / Hn, h = z % Hn;
    const float* W = (which == 0) ? Wq : (which == 1) ? Wk : Wv;
    const int c0 = blockIdx.x * 32;           // 0..11
    const int d0 = blockIdx.y * 32;           // 0..1
    #pragma unroll
    for (int i = 0; i < 32; i += 8)
        tile[ty + i][tx] = W[((size_t)h * Cn + c0 + ty + i) * HDn + d0 + tx];
    __syncthreads();
    const int n0 = which * Cn + h * HDn + d0;
    #pragma unroll
    for (int i = 0; i < 32; i += 8)
        oh[(size_t)(n0 + ty + i) * Cn + c0 + tx] = __float2half_rn(tile[tx][ty + i]);
}

// ---------------- mma.sync GEMM: 128x128 tile, KC=64, pure fp16, 3-stage ---
#define KC   64
#define STG  32768

__global__ __launch_bounds__(256, 2)
void mma_gemm4(const __half* __restrict__ Ah, const __half* __restrict__ Bh,
               float* __restrict__ Cf, __half* __restrict__ Ch,
               __half* __restrict__ Ql, __half* __restrict__ Kh, __half* __restrict__ Vh,
               const float* __restrict__ bias, const float* __restrict__ residual,
               int relu, int qkv, int N, int K)
{
    extern __shared__ __align__(1024) char sm[];   // 3 * STG
    const uint32_t sb0 = smem_u32(sm);

    const int tid  = threadIdx.x;
    const int lane = tid & 31;
    const int w    = tid >> 5;
    const int wm   = w & 3;
    const int wn   = w >> 2;
    const int row0 = blockIdx.y * 128;
    const int col0 = blockIdx.x * 128;

    const int r8 = tid >> 3;
    const int u8 = (tid & 7) * 16;

    float acc[2][8][4];
    #pragma unroll
    for (int i = 0; i < 2; i++)
        #pragma unroll
        for (int j = 0; j < 8; j++)
            #pragma unroll
            for (int q = 0; q < 4; q++) acc[i][j][q] = 0.f;

    const int nc = K / KC;

    auto load_stage = [&](int c, int buf) {
        const uint32_t sb = sb0 + buf * STG;
        const int k0 = c * KC;
        #pragma unroll
        for (int i = 0; i < 4; i++) {
            int r = r8 + i * 32;
            size_t go = ((size_t)(row0 + r) * K + k0) * 2 + u8;
            uint32_t so = SW128S((uint32_t)(r * 128 + u8));
            cp16(sb + so, (const char*)Ah + go);
        }
        #pragma unroll
        for (int i = 0; i < 4; i++) {
            int r = r8 + i * 32;
            size_t go = ((size_t)(col0 + r) * K + k0) * 2 + u8;
            uint32_t so = SW128S((uint32_t)(r * 128 + u8));
            cp16(sb + 16384 + so, (const char*)Bh + go);
        }
        CP_COMMIT();
    };

    load_stage(0, 0);
    if (nc > 1) load_stage(1, 1);

    for (int c = 0; c < nc; c++) {
        const int buf = c % 3;
        if (c + 2 < nc) {
            load_stage(c + 2, (c + 2) % 3);
            CP_WAIT(2);
        } else if (c + 1 < nc) {
            CP_WAIT(1);
        } else {
            CP_WAIT(0);
        }
        __syncthreads();

        const uint32_t sb = sb0 + buf * STG;
        #pragma unroll
        for (int ks = 0; ks < 4; ks++) {
            const uint32_t kb = ks * 32 + 16 * (lane >> 4);
            uint32_t ah[2][4], bh[4][4];
            #pragma unroll
            for (int i = 0; i < 2; i++) {
                uint32_t off = SW128S((uint32_t)((wm * 32 + i * 16 + (lane & 15)) * 128 + kb));
                ldm4u(ah[i], sb + off);
            }
            #pragma unroll
            for (int j2 = 0; j2 < 4; j2++) {
                uint32_t off = SW128S((uint32_t)((wn * 64 + j2 * 16 + (lane & 15)) * 128 + kb));
                ldm4u(bh[j2], sb + 16384 + off);
            }
            #pragma unroll
            for (int i = 0; i < 2; i++)
                #pragma unroll
                for (int j = 0; j < 8; j++) {
                    uint32_t b0 = bh[j >> 1][j & 1], b1 = bh[j >> 1][(j & 1) + 2];
                    mma16816(acc[i][j], ah[i], b0, b1);
                }
        }
        __syncthreads();
    }

    // ---- epilogue ----
    const int which = qkv ? (col0 / Cn) : 0;   // uniform per CTA (384 = 3*128)
    #pragma unroll
    for (int i = 0; i < 2; i++) {
        #pragma unroll
        for (int j = 0; j < 8; j++) {
            int rb = row0 + wm * 32 + i * 16 + (lane >> 2);
            int cc = col0 + wn * 64 + j * 8 + (lane & 3) * 2;
            #pragma unroll
            for (int hh = 0; hh < 2; hh++) {
                int r = rb + 8 * hh;
                float vx = acc[i][j][2 * hh], vy = acc[i][j][2 * hh + 1];
                if (qkv) {
                    int cl = cc - which * Cn;
                    size_t off = (size_t)r * Cn + cl;
                    if (which == 0) {
                        split_store2(Ch, Ql, off, vx * 0.125f, vy * 0.125f);
                    } else if (which == 1) {
                        *(uint32_t*)(Kh + off) = pack_f16x2(vx, vy);
                    } else {
                        *(uint32_t*)(Vh + off) = pack_f16x2(vx, vy);
                    }
                } else {
                    if (bias) { vx += bias[cc]; vy += bias[cc + 1]; }
                    if (Cf) {
                        if (residual) {
                            float2 rr = *(const float2*)(residual + (size_t)r * N + cc);
                            vx += rr.x; vy += rr.y;
                        }
                        *(float2*)(Cf + (size_t)r * N + cc) = make_float2(vx, vy);
                    } else {
                        if (relu) { vx = fmaxf(vx, 0.f); vy = fmaxf(vy, 0.f); }
                        *(uint32_t*)(Ch + (size_t)r * N + cc) = pack_f16x2(vx, vy);
                    }
                }
            }
        }
    }
}

// ---------------- flash attention (2-term S, 1-term PV) --------------------
#define PF 136

__global__ __launch_bounds__(256)
void attn_flash(const __half* __restrict__ Qh, const __half* __restrict__ Ql,
                const __half* __restrict__ Kh, const __half* __restrict__ Vh,
                __half* __restrict__ Oh)
{
    __shared__ __half smf[128 * PF];

    const int tid  = threadIdx.x;
    const int lane = tid & 31;
    const int w    = tid >> 5;
    const int qt = blockIdx.x;
    const int h  = blockIdx.y;
    const int b  = blockIdx.z;

    // ---- stage Q hi/lo (pre-scaled planes) ----
    {
        size_t qbase = ((size_t)(b * Tn + qt * 128)) * Cn + h * HDn;
        #pragma unroll
        for (int it = 0; it < 4; it++) {
            int f = tid + it * 256;
            int row = f >> 3, c8 = (f & 7) * 8;
            *(uint4*)&smf[row * PF + c8]      = *(const uint4*)(Qh + qbase + (size_t)row * Cn + c8);
            *(uint4*)&smf[row * PF + 64 + c8] = *(const uint4*)(Ql + qbase + (size_t)row * Cn + c8);
        }
    }
    __syncthreads();

    uint32_t qh[4][4], ql[4][4];
    #pragma unroll
    for (int ks = 0; ks < 4; ks++) {
        const __half* p = &smf[(w * 16 + (lane & 15)) * PF + ks * 16 + 8 * (lane >> 4)];
        ldm_x4(qh[ks], p);
        ldm_x4(ql[ks], p + 64);
    }
    __syncthreads();

    float o[8][4];
    #pragma unroll
    for (int j = 0; j < 8; j++)
        #pragma unroll
        for (int q = 0; q < 4; q++) o[j][q] = 0.f;
    float m_old[2] = {-1e30f, -1e30f};
    float l_sum[2] = {0.f, 0.f};

    const int qrow0 = qt * 128 + w * 16 + (lane >> 2);
    const int n_st = 2 * qt + 2;

    for (int st = 0; st < n_st; st++) {
        // ---- stage K hi (rows 0-63) and V hi (rows 64-127) ----
        {
            size_t kb_ = ((size_t)(b * Tn + st * 64)) * Cn + h * HDn;
            #pragma unroll
            for (int it = 0; it < 2; it++) {
                int f = tid + it * 256;
                int row = f >> 3, c8 = (f & 7) * 8;
                *(uint4*)&smf[row * PF + c8] =
                    *(const uint4*)(Kh + kb_ + (size_t)row * Cn + c8);
                *(uint4*)&smf[(64 + row) * PF + c8] =
                    *(const uint4*)(Vh + kb_ + (size_t)row * Cn + c8);
            }
        }
        __syncthreads();

        // ---- S = Qh K^T + Ql K^T ----
        float s[8][4];
        #pragma unroll
        for (int j = 0; j < 8; j++)
            #pragma unroll
            for (int q = 0; q < 4; q++) s[j][q] = 0.f;

        #pragma unroll
        for (int ks = 0; ks < 4; ks++) {
            #pragma unroll
            for (int g = 0; g < 4; g++) {
                uint32_t kh4[4];
                const __half* p =
                    &smf[(g * 16 + (lane & 15)) * PF + ks * 16 + 8 * (lane >> 4)];
                ldm_x4(kh4, p);
                #pragma unroll
                for (int j = 0; j < 2; j++) {
                    int jj = g * 2 + j;
                    mma16816(s[jj], qh[ks], kh4[j], kh4[j + 2]);
                    mma16816(s[jj], ql[ks], kh4[j], kh4[j + 2]);
                }
            }
        }

        // ---- causal mask + online softmax ----
        float m_tile[2] = {-1e30f, -1e30f};
        #pragma unroll
        for (int j = 0; j < 8; j++) {
            #pragma unroll
            for (int q = 0; q < 4; q++) {
                int scol = st * 64 + j * 8 + 2 * (lane & 3) + (q & 1);
                int qrow = qrow0 + 8 * (q >> 1);
                if (scol > qrow) s[j][q] = -1e30f;
                m_tile[q >> 1] = fmaxf(m_tile[q >> 1], s[j][q]);
            }
        }
        #pragma unroll
        for (int r = 0; r < 2; r++) {
            m_tile[r] = fmaxf(m_tile[r], __shfl_xor_sync(0xffffffffu, m_tile[r], 1));
            m_tile[r] = fmaxf(m_tile[r], __shfl_xor_sync(0xffffffffu, m_tile[r], 2));
        }
        float m_new[2], fscale[2], rsum[2] = {0.f, 0.f};
        #pragma unroll
        for (int r = 0; r < 2; r++) {
            m_new[r] = fmaxf(m_old[r], m_tile[r]);
            fscale[r] = __expf(m_old[r] - m_new[r]);
        }
        #pragma unroll
        for (int j = 0; j < 8; j++) {
            #pragma unroll
            for (int q = 0; q < 4; q++) {
                float p = __expf(s[j][q] - m_new[q >> 1]);
                s[j][q] = p;
                rsum[q >> 1] += p;
            }
        }
        #pragma unroll
        for (int r = 0; r < 2; r++) {
            rsum[r] += __shfl_xor_sync(0xffffffffu, rsum[r], 1);
            rsum[r] += __shfl_xor_sync(0xffffffffu, rsum[r], 2);
            l_sum[r] = l_sum[r] * fscale[r] + rsum[r];
            m_old[r] = m_new[r];
        }
        #pragma unroll
        for (int j = 0; j < 8; j++) {
            o[j][0] *= fscale[0]; o[j][1] *= fscale[0];
            o[j][2] *= fscale[1]; o[j][3] *= fscale[1];
        }

        // ---- O += Ph V (1-term) ----
        #pragma unroll
        for (int ks = 0; ks < 4; ks++) {
            uint32_t pah[4];
            pah[0] = pack_f16x2(s[2*ks][0],   s[2*ks][1]);
            pah[1] = pack_f16x2(s[2*ks][2],   s[2*ks][3]);
            pah[2] = pack_f16x2(s[2*ks+1][0], s[2*ks+1][1]);
            pah[3] = pack_f16x2(s[2*ks+1][2], s[2*ks+1][3]);

            #pragma unroll
            for (int g = 0; g < 4; g++) {
                uint32_t vh4[4];
                const __half* p =
                    &smf[(64 + ks * 16 + (lane & 15)) * PF + g * 16 + 8 * (lane >> 4)];
                ldm_x4_trans(vh4, p);
                #pragma unroll
                for (int j = 0; j < 2; j++) {
                    int dd = g * 2 + j;
                    mma16816(o[dd], pah, vh4[j * 2], vh4[j * 2 + 1]);
                }
            }
        }
        __syncthreads();
    }

    float inv0 = 1.0f / l_sum[0];
    float inv1 = 1.0f / l_sum[1];
    #pragma unroll
    for (int j = 0; j < 8; j++) {
        int col = h * HDn + j * 8 + 2 * (lane & 3);
        #pragma unroll
        for (int r = 0; r < 2; r++) {
            int row = b * Tn + qrow0 + 8 * r;
            float inv = r ? inv1 : inv0;
            *(uint32_t*)(Oh + (size_t)row * Cn + col) =
                pack_f16x2(o[j][2 * r] * inv, o[j][2 * r + 1] * inv);
        }
    }
}

// ---------------- launch ---------------------------------------------------
extern "C" void kernel_launch(void* const* d_in, const int* in_sizes, int n_in,
                              void* d_out, int out_size)
{
    const float* x     = (const float*)d_in[0];
    const float* ln1_g = (const float*)d_in[1];
    const float* ln1_b = (const float*)d_in[2];
    const float* Wq    = (const float*)d_in[3];
    const float* Wk    = (const float*)d_in[4];
    const float* Wv    = (const float*)d_in[5];
    const float* Wo    = (const float*)d_in[6];
    const float* bo    = (const float*)d_in[7];
    const float* ln2_g = (const float*)d_in[8];
    const float* ln2_b = (const float*)d_in[9];
    const float* W1    = (const float*)d_in[10];
    const float* b1    = (const float*)d_in[11];
    const float* W2    = (const float*)d_in[12];
    const float* b2    = (const float*)d_in[13];
    float* out = (float*)d_out;

    cudaFuncSetAttribute(mma_gemm4, cudaFuncAttributeMaxDynamicSharedMemorySize, 3 * STG);

    void *p;
    cudaGetSymbolAddress(&p, g_x1h);   __half* x1h = (__half*)p;
    cudaGetSymbolAddress(&p, g_qh);    __half* qh = (__half*)p;
    cudaGetSymbolAddress(&p, g_ql);    __half* ql = (__half*)p;
    cudaGetSymbolAddress(&p, g_kh);    __half* kh = (__half*)p;
    cudaGetSymbolAddress(&p, g_vh);    __half* vh = (__half*)p;
    cudaGetSymbolAddress(&p, g_ath);   __half* ath = (__half*)p;
    cudaGetSymbolAddress(&p, g_hidh);  __half* hidh = (__half*)p;
    cudaGetSymbolAddress(&p, g_wqkvh); __half* wqkvh = (__half*)p;
    cudaGetSymbolAddress(&p, g_woth);  __half* woth = (__half*)p;
    cudaGetSymbolAddress(&p, g_w1th);  __half* w1th = (__half*)p;
    cudaGetSymbolAddress(&p, g_w2th);  __half* w2th = (__half*)p;

    // weight prep (tiled transpose + fp16)
    pack_qkv_tiled<<<dim3(Cn / 32, HDn / 32, 3 * Hn), 256>>>(Wq, Wk, Wv, wqkvh);
    pack_t_tiled<<<dim3(Cn / 32, Cn / 32), 256>>>(Wo, woth, Cn, Cn);
    pack_t_tiled<<<dim3(Cn / 32, FF / 32), 256>>>(W1, w1th, Cn, FF);
    pack_t_tiled<<<dim3(FF / 32, Cn / 32), 256>>>(W2, w2th, FF, Cn);

    // LN1 -> fp16
    ln_kernel<<<BT / 8, 256>>>(x, ln1_g, ln1_b, x1h);
    // QKV: [BT,384] x [1152,384]^T -> Q (scaled hi/lo), K hi, V hi
    mma_gemm4<<<dim3(QKVN / 128, BT / 128), 256, 3 * STG>>>(
        x1h, wqkvh, nullptr, qh, ql, kh, vh, nullptr, nullptr, 0, 1, QKVN, Cn);
    // causal flash attention -> fp16
    attn_flash<<<dim3(2, Hn, Bn), 256>>>(qh, ql, kh, vh, ath);
    // Wo + bias + residual(x) -> d_out (fp32)
    mma_gemm4<<<dim3(Cn / 128, BT / 128), 256, 3 * STG>>>(
        ath, woth, out, nullptr, nullptr, nullptr, nullptr, bo, x, 0, 0, Cn, Cn);
    // LN2 -> fp16
    ln_kernel<<<BT / 8, 256>>>(out, ln2_g, ln2_b, x1h);
    // FFN1: relu(x2 @ W1 + b1) -> fp16
    mma_gemm4<<<dim3(FF / 128, BT / 128), 256, 3 * STG>>>(
        x1h, w1th, nullptr, hidh, nullptr, nullptr, nullptr, b1, nullptr, 1, 0, FF, Cn);
    // FFN2: d_out += hid @ W2 + b2
    mma_gemm4<<<dim3(Cn / 128, BT / 128), 256, 3 * STG>>>(
        hidh, w2th, out, nullptr, nullptr, nullptr, nullptr, b2, out, 0, 0, Cn, FF);
}